// round 2
// baseline (speedup 1.0000x reference)
#include <cuda_runtime.h>
#include <math.h>

#define Bn  4
#define Sn  4096
#define Dn  1024
#define TPn 16
#define TEn 64
#define DKn 128

// ---------------- scratch (no allocations allowed) ----------------
__device__ float g_Q [Bn*Sn*DKn];
__device__ float g_Kd[Bn*Sn*DKn];
__device__ float g_Vd[Bn*Sn*DKn];
__device__ float g_QT[Bn*Sn*DKn];
__device__ float g_T [Bn*DKn*DKn];
__device__ float g_m [Bn*Sn];
__device__ float g_l [Bn*Sn];

// ---------------- kernel 1: T_scaled per batch ----------------
__global__ void prep_T_kernel(const float* __restrict__ tp,
                              const float* __restrict__ Wt,
                              const float* __restrict__ bt) {
    __shared__ float sTP[TPn*TEn];
    __shared__ float sWt[TEn*DKn];
    __shared__ float sE [TPn*DKn];
    __shared__ float red[256];
    int b = blockIdx.x, tid = threadIdx.x;
    for (int i = tid; i < TPn*TEn; i += 256) sTP[i] = tp[b*TPn*TEn + i];
    for (int i = tid; i < TEn*DKn; i += 256) sWt[i] = Wt[i];
    __syncthreads();
    for (int i = tid; i < TPn*DKn; i += 256) {
        int t = i >> 7, d = i & 127;
        float acc = bt[d];
        #pragma unroll 8
        for (int e = 0; e < TEn; e++) acc += sTP[t*TEn + e] * sWt[e*DKn + d];
        sE[i] = acc;
    }
    __syncthreads();
    float ss = 0.f;
    for (int i = tid; i < TPn*DKn; i += 256) ss += sE[i]*sE[i];
    red[tid] = ss; __syncthreads();
    for (int off = 128; off > 0; off >>= 1) {
        if (tid < off) red[tid] += red[tid+off];
        __syncthreads();
    }
    float tn = sqrtf((float)Sn * red[0]);
    float sc = (float)Sn / (tn + 1e-8f);
    for (int i = tid; i < DKn*DKn; i += 256) {
        int d = i >> 7, e2 = i & 127;
        float acc = 0.f;
        #pragma unroll
        for (int t = 0; t < TPn; t++) acc += sE[t*DKn + d] * sE[t*DKn + e2];
        g_T[b*DKn*DKn + i] = acc * sc;
    }
}

// ---------------- kernel 2: generic GEMM, N fixed = 128 ----------------
// C[M,128] = A[M,Kd] @ W[Kd,128] (+ bias). blockIdx.z batches via strides.
__global__ void gemm_n128(const float* __restrict__ A, const float* __restrict__ W,
                          const float* __restrict__ bias, float* __restrict__ C,
                          int M, int Kd, long long Ab, long long Wb, long long Cb) {
    A += (long long)blockIdx.z * Ab;
    W += (long long)blockIdx.z * Wb;
    C += (long long)blockIdx.z * Cb;
    __shared__ float sA[16*65];
    __shared__ float sW[16*128];
    int tid = threadIdx.x;
    int tr = tid >> 4, tc = tid & 15;      // 16x16 thread grid, 4x8 microtile
    int row0 = blockIdx.x << 6;
    float acc[4][8];
    #pragma unroll
    for (int i = 0; i < 4; i++)
        #pragma unroll
        for (int j = 0; j < 8; j++) acc[i][j] = 0.f;

    int kl = tid & 15, rb2 = tid >> 4;
    for (int k0 = 0; k0 < Kd; k0 += 16) {
        #pragma unroll
        for (int it = 0; it < 4; it++) {
            int rl = rb2 + (it << 4);
            sA[kl*65 + rl] = A[(long long)(row0 + rl)*Kd + (k0 + kl)];
        }
        #pragma unroll
        for (int i2 = tid; i2 < 2048; i2 += 256)
            sW[i2] = W[(long long)(k0 + (i2 >> 7))*DKn + (i2 & 127)];
        __syncthreads();
        #pragma unroll
        for (int k = 0; k < 16; k++) {
            float a[4];
            #pragma unroll
            for (int i = 0; i < 4; i++) a[i] = sA[k*65 + 4*tr + i];
            float4 w0 = *(const float4*)(sW + k*128 + 8*tc);
            float4 w1 = *(const float4*)(sW + k*128 + 8*tc + 4);
            float w[8] = {w0.x,w0.y,w0.z,w0.w,w1.x,w1.y,w1.z,w1.w};
            #pragma unroll
            for (int i = 0; i < 4; i++)
                #pragma unroll
                for (int j = 0; j < 8; j++) acc[i][j] += a[i]*w[j];
        }
        __syncthreads();
    }
    float bvv[8];
    if (bias) {
        float4 b0 = *(const float4*)(bias + 8*tc);
        float4 b1 = *(const float4*)(bias + 8*tc + 4);
        bvv[0]=b0.x; bvv[1]=b0.y; bvv[2]=b0.z; bvv[3]=b0.w;
        bvv[4]=b1.x; bvv[5]=b1.y; bvv[6]=b1.z; bvv[7]=b1.w;
    } else {
        #pragma unroll
        for (int j = 0; j < 8; j++) bvv[j] = 0.f;
    }
    #pragma unroll
    for (int i = 0; i < 4; i++) {
        long long row = row0 + 4*tr + i;
        float4 o0 = make_float4(acc[i][0]+bvv[0], acc[i][1]+bvv[1], acc[i][2]+bvv[2], acc[i][3]+bvv[3]);
        float4 o1 = make_float4(acc[i][4]+bvv[4], acc[i][5]+bvv[5], acc[i][6]+bvv[6], acc[i][7]+bvv[7]);
        *(float4*)(C + row*DKn + 8*tc)     = o0;
        *(float4*)(C + row*DKn + 8*tc + 4) = o1;
    }
}

// ---------------- kernel 3: flash attention + raw score dump ----------------
// grid (S/64, B), 256 threads. smem: sQ/sK k-major swizzled (pitch 68),
// sV row-major, sP probability tile.
#define PITCH 68
#define ATTN_SMEM ((128*PITCH + 128*PITCH + 64*128 + 64*PITCH) * 4)

__global__ void attn_kernel(float* __restrict__ d_out) {
    extern __shared__ float smem[];
    float* sQ = smem;                    // [128][68] k-major, swizzled cols
    float* sK = sQ + 128*PITCH;          // [128][68]
    float* sV = sK + 128*PITCH;          // [64][128] row-major
    float* sP = sV + 64*128;             // [64][68]

    int b  = blockIdx.y, rb = blockIdx.x;
    int tid = threadIdx.x;
    int tr = tid >> 4, tc = tid & 15;    // scores: 4 rows x 4 cols; out: 4 rows x 8 cols
    float* out  = d_out;
    float* attn = d_out + (long long)Bn*Sn*DKn;

    // ---- load QT block (64 rows x 128 dk), transpose to k-major with swizzle ----
    {
        const float* src = g_QT + ((long long)b*Sn + rb*64)*DKn;
        int m = tid & 31, r0 = tid >> 5;
        int k4 = 4*m, h = (m >> 1) & 7;   // h == ((k4+i)>>3)&7 for i in 0..3
        #pragma unroll
        for (int it = 0; it < 8; it++) {
            int r = r0 + it*8;
            float4 v = *(const float4*)(src + (long long)r*DKn + k4);
            int cs = (r & 3) | ((((r >> 2) ^ h) & 15) << 2);
            sQ[(k4+0)*PITCH + cs] = v.x;
            sQ[(k4+1)*PITCH + cs] = v.y;
            sQ[(k4+2)*PITCH + cs] = v.z;
            sQ[(k4+3)*PITCH + cs] = v.w;
        }
    }

    float m_r[4], l_r[4], acc[4][8];
    #pragma unroll
    for (int i = 0; i < 4; i++) {
        m_r[i] = -1e30f; l_r[i] = 0.f;
        #pragma unroll
        for (int j = 0; j < 8; j++) acc[i][j] = 0.f;
    }
    __syncthreads();

    const float scale = 0.08838834764831845f;  // 1/sqrt(128)

    for (int jt = 0; jt < Sn/64; jt++) {
        __syncthreads();   // previous tile's sK/sV/sP consumers done
        // ---- load K tile (transposed+swizzled) and V tile (row-major) ----
        {
            const float* srcK = g_Kd + ((long long)b*Sn + jt*64)*DKn;
            int m = tid & 31, r0 = tid >> 5;
            int k4 = 4*m, h = (m >> 1) & 7;
            #pragma unroll
            for (int it = 0; it < 8; it++) {
                int c = r0 + it*8;
                float4 v = *(const float4*)(srcK + (long long)c*DKn + k4);
                int cs = (c & 3) | ((((c >> 2) ^ h) & 15) << 2);
                sK[(k4+0)*PITCH + cs] = v.x;
                sK[(k4+1)*PITCH + cs] = v.y;
                sK[(k4+2)*PITCH + cs] = v.z;
                sK[(k4+3)*PITCH + cs] = v.w;
            }
            const float4* srcV = (const float4*)(g_Vd + ((long long)b*Sn + jt*64)*DKn);
            #pragma unroll
            for (int i2 = tid; i2 < 64*128/4; i2 += 256)
                ((float4*)sV)[i2] = srcV[i2];
        }
        __syncthreads();

        // ---- scores: 4x4 per thread over full K=128 ----
        float sc[4][4];
        #pragma unroll
        for (int i = 0; i < 4; i++)
            #pragma unroll
            for (int j = 0; j < 4; j++) sc[i][j] = 0.f;
        #pragma unroll 16
        for (int k = 0; k < DKn; k++) {
            int g = (k >> 3) & 7;
            float4 a4 = *(const float4*)(sQ + k*PITCH + (((tr ^ g) & 15) << 2));
            float4 b4 = *(const float4*)(sK + k*PITCH + (((tc ^ g) & 15) << 2));
            float a[4] = {a4.x,a4.y,a4.z,a4.w};
            float bb[4] = {b4.x,b4.y,b4.z,b4.w};
            #pragma unroll
            for (int i = 0; i < 4; i++)
                #pragma unroll
                for (int j = 0; j < 4; j++) sc[i][j] += a[i]*bb[j];
        }
        #pragma unroll
        for (int i = 0; i < 4; i++)
            #pragma unroll
            for (int j = 0; j < 4; j++) sc[i][j] *= scale;

        // ---- dump raw (scaled) scores to gmem attn region ----
        {
            long long base = (long long)b*Sn*Sn + (long long)(rb*64)*Sn + (long long)jt*64;
            #pragma unroll
            for (int i = 0; i < 4; i++) {
                long long row = 4*tr + i;
                *(float4*)(attn + base + row*Sn + 4*tc) =
                    make_float4(sc[i][0], sc[i][1], sc[i][2], sc[i][3]);
            }
        }

        // ---- online softmax update ----
        #pragma unroll
        for (int i = 0; i < 4; i++) {
            float rm = fmaxf(fmaxf(sc[i][0], sc[i][1]), fmaxf(sc[i][2], sc[i][3]));
            rm = fmaxf(rm, __shfl_xor_sync(0xffffffffu, rm, 1));
            rm = fmaxf(rm, __shfl_xor_sync(0xffffffffu, rm, 2));
            rm = fmaxf(rm, __shfl_xor_sync(0xffffffffu, rm, 4));
            rm = fmaxf(rm, __shfl_xor_sync(0xffffffffu, rm, 8));
            float mn   = fmaxf(m_r[i], rm);
            float resc = __expf(m_r[i] - mn);
            m_r[i] = mn;
            float rs = 0.f;
            #pragma unroll
            for (int j = 0; j < 4; j++) { sc[i][j] = __expf(sc[i][j] - mn); rs += sc[i][j]; }
            rs += __shfl_xor_sync(0xffffffffu, rs, 1);
            rs += __shfl_xor_sync(0xffffffffu, rs, 2);
            rs += __shfl_xor_sync(0xffffffffu, rs, 4);
            rs += __shfl_xor_sync(0xffffffffu, rs, 8);
            l_r[i] = l_r[i]*resc + rs;
            #pragma unroll
            for (int j = 0; j < 8; j++) acc[i][j] *= resc;
            *(float4*)(sP + (4*tr + i)*PITCH + 4*tc) =
                make_float4(sc[i][0], sc[i][1], sc[i][2], sc[i][3]);
        }
        __syncthreads();

        // ---- PV accumulation ----
        #pragma unroll 2
        for (int c4 = 0; c4 < 64; c4 += 4) {
            float p[4][4];
            #pragma unroll
            for (int i = 0; i < 4; i++) {
                float4 pv = *(const float4*)(sP + (4*tr + i)*PITCH + c4);
                p[i][0]=pv.x; p[i][1]=pv.y; p[i][2]=pv.z; p[i][3]=pv.w;
            }
            #pragma unroll
            for (int cc = 0; cc < 4; cc++) {
                float4 v0 = *(const float4*)(sV + (c4+cc)*128 + 8*tc);
                float4 v1 = *(const float4*)(sV + (c4+cc)*128 + 8*tc + 4);
                float v[8] = {v0.x,v0.y,v0.z,v0.w,v1.x,v1.y,v1.z,v1.w};
                #pragma unroll
                for (int i = 0; i < 4; i++) {
                    float pp = p[i][cc];
                    #pragma unroll
                    for (int j = 0; j < 8; j++) acc[i][j] += pp * v[j];
                }
            }
        }
    }

    // ---- epilogue: out = acc / l ; store m,l for normalize pass ----
    #pragma unroll
    for (int i = 0; i < 4; i++) {
        float inv = 1.0f / l_r[i];
        int row = rb*64 + 4*tr + i;
        float4 o0 = make_float4(acc[i][0]*inv, acc[i][1]*inv, acc[i][2]*inv, acc[i][3]*inv);
        float4 o1 = make_float4(acc[i][4]*inv, acc[i][5]*inv, acc[i][6]*inv, acc[i][7]*inv);
        long long obase = ((long long)b*Sn + row)*DKn;
        *(float4*)(out + obase + 8*tc)     = o0;
        *(float4*)(out + obase + 8*tc + 4) = o1;
        if (tc == 0) { g_m[b*Sn + row] = m_r[i]; g_l[b*Sn + row] = l_r[i]; }
    }
}

// ---------------- kernel 4: in-place softmax normalize of attn ----------------
__global__ void softmax_norm_kernel(float* __restrict__ attn) {
    long long total4 = (long long)Bn*Sn*Sn / 4;
    long long stride = (long long)gridDim.x * blockDim.x;
    for (long long idx = (long long)blockIdx.x*blockDim.x + threadIdx.x;
         idx < total4; idx += stride) {
        long long e = idx << 2;
        int row = (int)(e >> 12);          // S = 4096 cols per row; row in [0, B*S)
        float mm  = g_m[row];
        float inv = 1.0f / g_l[row];
        float4 v = ((float4*)attn)[idx];
        v.x = __expf(v.x - mm) * inv;
        v.y = __expf(v.y - mm) * inv;
        v.z = __expf(v.z - mm) * inv;
        v.w = __expf(v.w - mm) * inv;
        ((float4*)attn)[idx] = v;
    }
}

// ---------------- launcher ----------------
extern "C" void kernel_launch(void* const* d_in, const int* in_sizes, int n_in,
                              void* d_out, int out_size) {
    const float* x  = (const float*)d_in[0];
    const float* tp = (const float*)d_in[1];
    const float* Wq = (const float*)d_in[2];
    const float* bq = (const float*)d_in[3];
    const float* Wk = (const float*)d_in[4];
    const float* bk = (const float*)d_in[5];
    const float* Wv = (const float*)d_in[6];
    const float* bv = (const float*)d_in[7];
    const float* Wt = (const float*)d_in[8];
    const float* bt = (const float*)d_in[9];
    float* out = (float*)d_out;

    float *pQ, *pK, *pV, *pQT, *pT;
    cudaGetSymbolAddress((void**)&pQ,  g_Q);
    cudaGetSymbolAddress((void**)&pK,  g_Kd);
    cudaGetSymbolAddress((void**)&pV,  g_Vd);
    cudaGetSymbolAddress((void**)&pQT, g_QT);
    cudaGetSymbolAddress((void**)&pT,  g_T);

    cudaFuncSetAttribute(attn_kernel, cudaFuncAttributeMaxDynamicSharedMemorySize, ATTN_SMEM);

    // 1) T_scaled
    prep_T_kernel<<<Bn, 256>>>(tp, Wt, bt);
    // 2) Q, K, V projections (M = B*S, Kd = D)
    gemm_n128<<<dim3((Bn*Sn)/64, 1, 1), 256>>>(x, Wq, bq, pQ, Bn*Sn, Dn, 0, 0, 0);
    gemm_n128<<<dim3((Bn*Sn)/64, 1, 1), 256>>>(x, Wk, bk, pK, Bn*Sn, Dn, 0, 0, 0);
    gemm_n128<<<dim3((Bn*Sn)/64, 1, 1), 256>>>(x, Wv, bv, pV, Bn*Sn, Dn, 0, 0, 0);
    // 3) QT = Q @ T_scaled (per batch)
    gemm_n128<<<dim3(Sn/64, 1, Bn), 256>>>(pQ, pT, nullptr, pQT, Sn, DKn,
                                           (long long)Sn*DKn, (long long)DKn*DKn,
                                           (long long)Sn*DKn);
    // 4) flash attention + raw score dump + out
    attn_kernel<<<dim3(Sn/64, Bn), 256, ATTN_SMEM>>>(out);
    // 5) normalize attn in place
    softmax_norm_kernel<<<4096, 256>>>(out + (long long)Bn*Sn*DKn);
}

// round 4
// speedup vs baseline: 1.7125x; 1.7125x over previous
#include <cuda_runtime.h>
#include <cuda_bf16.h>
#include <math.h>
#include <stdint.h>

#define Bn 4
#define Sn 4096
#define Dn 1024
#define TPn 16
#define TEn 64
#define DKn 128
#define NTILE 128
#define SPLIT_SZ (NTILE*32768ULL)
#define SCALE 0.08838834764831845f

// ---------------- scratch ----------------
__device__ float g_Q[Bn*Sn*DKn];
__device__ float g_T[Bn*DKn*DKn];
__device__ float g_m[Bn*Sn];
__device__ float g_l[Bn*Sn];
__device__ __align__(16) unsigned char g_Ks [3*SPLIT_SZ];   // K 3-split blobs
__device__ __align__(16) unsigned char g_QTs[3*SPLIT_SZ];   // QT 3-split blobs
__device__ __align__(16) unsigned char g_Vt [2*SPLIT_SZ];   // V^T 2-split blobs

// ---------------- helpers ----------------
__device__ __forceinline__ uint32_t smem_u32(const void* p){
    uint32_t a;
    asm("{ .reg .u64 t; cvta.to.shared.u64 t, %1; cvt.u32.u64 %0, t; }" : "=r"(a) : "l"(p));
    return a;
}
__device__ __forceinline__ uint32_t swz16(uint32_t r, uint32_t g){
    return ((g & 8u) | ((g ^ r) & 7u)) << 4;   // byte offset of 16B group
}
__device__ __forceinline__ void cp16(uint32_t dst, const void* src){
    asm volatile("cp.async.cg.shared.global [%0], [%1], 16;" :: "r"(dst), "l"(src) : "memory");
}
#define CP_COMMIT() asm volatile("cp.async.commit_group;" ::: "memory")
#define CP_WAIT(n)  asm volatile("cp.async.wait_group %0;" :: "n"(n) : "memory")
#define STS16(addr, v) asm volatile("st.shared.v4.b32 [%0], {%1,%2,%3,%4};" \
    :: "r"(addr), "r"((v).x), "r"((v).y), "r"((v).z), "r"((v).w) : "memory")

__device__ __forceinline__ void ldm_x4(uint32_t* r, uint32_t addr){
    asm volatile("ldmatrix.sync.aligned.m8n8.x4.shared.b16 {%0,%1,%2,%3}, [%4];"
        : "=r"(r[0]), "=r"(r[1]), "=r"(r[2]), "=r"(r[3]) : "r"(addr));
}
__device__ __forceinline__ void ldm_x2(uint32_t* r, uint32_t addr){
    asm volatile("ldmatrix.sync.aligned.m8n8.x2.shared.b16 {%0,%1}, [%2];"
        : "=r"(r[0]), "=r"(r[1]) : "r"(addr));
}
__device__ __forceinline__ void mma16816(float* d, const uint32_t* a, const uint32_t* b){
    asm volatile("mma.sync.aligned.m16n8k16.row.col.f32.bf16.bf16.f32 "
        "{%0,%1,%2,%3}, {%4,%5,%6,%7}, {%8,%9}, {%0,%1,%2,%3};"
        : "+f"(d[0]), "+f"(d[1]), "+f"(d[2]), "+f"(d[3])
        : "r"(a[0]), "r"(a[1]), "r"(a[2]), "r"(a[3]), "r"(b[0]), "r"(b[1]));
}

__device__ __forceinline__ uint32_t pk(unsigned short a, unsigned short b){
    return (uint32_t)a | ((uint32_t)b << 16);
}
__device__ __forceinline__ void split3x8(const float* v, uint4& uh, uint4& um, uint4& ul){
    unsigned short h[8], m[8], l[8];
    #pragma unroll
    for (int j = 0; j < 8; j++){
        __nv_bfloat16 bh = __float2bfloat16(v[j]);
        float r = v[j] - __bfloat162float(bh);
        __nv_bfloat16 bm = __float2bfloat16(r);
        r -= __bfloat162float(bm);
        __nv_bfloat16 bl = __float2bfloat16(r);
        h[j] = __bfloat16_as_ushort(bh); m[j] = __bfloat16_as_ushort(bm); l[j] = __bfloat16_as_ushort(bl);
    }
    uh = make_uint4(pk(h[0],h[1]), pk(h[2],h[3]), pk(h[4],h[5]), pk(h[6],h[7]));
    um = make_uint4(pk(m[0],m[1]), pk(m[2],m[3]), pk(m[4],m[5]), pk(m[6],m[7]));
    ul = make_uint4(pk(l[0],l[1]), pk(l[2],l[3]), pk(l[4],l[5]), pk(l[6],l[7]));
}
__device__ __forceinline__ void split2x8(const float* v, uint4& uh, uint4& ul){
    unsigned short h[8], l[8];
    #pragma unroll
    for (int j = 0; j < 8; j++){
        __nv_bfloat16 bh = __float2bfloat16(v[j]);
        __nv_bfloat16 bl = __float2bfloat16(v[j] - __bfloat162float(bh));
        h[j] = __bfloat16_as_ushort(bh); l[j] = __bfloat16_as_ushort(bl);
    }
    uh = make_uint4(pk(h[0],h[1]), pk(h[2],h[3]), pk(h[4],h[5]), pk(h[6],h[7]));
    ul = make_uint4(pk(l[0],l[1]), pk(l[2],l[3]), pk(l[4],l[5]), pk(l[6],l[7]));
}

// ---------------- kernel 1: T_scaled per batch ----------------
__global__ void prep_T_kernel(const float* __restrict__ tp,
                              const float* __restrict__ Wt,
                              const float* __restrict__ bt) {
    __shared__ float sTP[TPn*TEn];
    __shared__ float sWt[TEn*DKn];
    __shared__ float sE [TPn*DKn];
    __shared__ float red[256];
    int b = blockIdx.x, tid = threadIdx.x;
    for (int i = tid; i < TPn*TEn; i += 256) sTP[i] = tp[b*TPn*TEn + i];
    for (int i = tid; i < TEn*DKn; i += 256) sWt[i] = Wt[i];
    __syncthreads();
    for (int i = tid; i < TPn*DKn; i += 256) {
        int t = i >> 7, d = i & 127;
        float acc = bt[d];
        #pragma unroll 8
        for (int e = 0; e < TEn; e++) acc += sTP[t*TEn + e] * sWt[e*DKn + d];
        sE[i] = acc;
    }
    __syncthreads();
    float ss = 0.f;
    for (int i = tid; i < TPn*DKn; i += 256) ss += sE[i]*sE[i];
    red[tid] = ss; __syncthreads();
    for (int off = 128; off > 0; off >>= 1) {
        if (tid < off) red[tid] += red[tid+off];
        __syncthreads();
    }
    float tn = sqrtf((float)Sn * red[0]);
    float sc = (float)Sn / (tn + 1e-8f);
    for (int i = tid; i < DKn*DKn; i += 256) {
        int d = i >> 7, e2 = i & 127;
        float acc = 0.f;
        #pragma unroll
        for (int t = 0; t < TPn; t++) acc += sE[t*DKn + d] * sE[t*DKn + e2];
        g_T[b*DKn*DKn + i] = acc * sc;
    }
}

// ---------------- kernel 2: 128x128 SIMT GEMM, templated epilogue ----------------
// MODE 0: fp32 C. MODE 1: 3-split bf16 blobs (rows=tokens, cols=dk). MODE 2: 2-split V^T blobs.
template<int MODE>
__global__ void __launch_bounds__(256,1)
gemm128(const float* __restrict__ A, const float* __restrict__ W,
        const float* __restrict__ bias, float* __restrict__ Cf,
        unsigned char* __restrict__ Cb, int Kd,
        long long Ab, long long Wb, int rowz, float oscale) {
    A += (long long)blockIdx.z * Ab;
    W += (long long)blockIdx.z * Wb;
    __shared__ float sA[16*132];
    __shared__ float sW[16*128];
    int tid = threadIdx.x;
    int tr = tid >> 4, tc = tid & 15;
    long long row0 = (long long)blockIdx.x * 128;
    float acc[8][8];
    #pragma unroll
    for (int i = 0; i < 8; i++)
        #pragma unroll
        for (int j = 0; j < 8; j++) acc[i][j] = 0.f;

    for (int k0 = 0; k0 < Kd; k0 += 16) {
        #pragma unroll
        for (int t = 0; t < 2; t++) {
            int idx = tid + t*256;
            int r = idx >> 2, kq = (idx & 3) << 2;
            float4 v = *(const float4*)(A + (row0 + r)*Kd + k0 + kq);
            sA[(kq+0)*132 + r] = v.x;
            sA[(kq+1)*132 + r] = v.y;
            sA[(kq+2)*132 + r] = v.z;
            sA[(kq+3)*132 + r] = v.w;
        }
        #pragma unroll
        for (int t = 0; t < 2; t++) {
            int idx = tid + t*256;
            int kr = idx >> 5, c4 = (idx & 31) << 2;
            *(float4*)(sW + kr*128 + c4) = *(const float4*)(W + (long long)(k0+kr)*DKn + c4);
        }
        __syncthreads();
        #pragma unroll
        for (int k = 0; k < 16; k++) {
            float a[8], wv[8];
            *(float4*)(a)    = *(const float4*)(sA + k*132 + 8*tr);
            *(float4*)(a+4)  = *(const float4*)(sA + k*132 + 8*tr + 4);
            *(float4*)(wv)   = *(const float4*)(sW + k*128 + 8*tc);
            *(float4*)(wv+4) = *(const float4*)(sW + k*128 + 8*tc + 4);
            #pragma unroll
            for (int i = 0; i < 8; i++)
                #pragma unroll
                for (int j = 0; j < 8; j++) acc[i][j] += a[i]*wv[j];
        }
        __syncthreads();
    }
    float bv[8];
    if (bias) {
        *(float4*)(bv)   = *(const float4*)(bias + 8*tc);
        *(float4*)(bv+4) = *(const float4*)(bias + 8*tc + 4);
    } else {
        #pragma unroll
        for (int j = 0; j < 8; j++) bv[j] = 0.f;
    }

    if (MODE == 0) {
        #pragma unroll
        for (int i = 0; i < 8; i++) {
            long long gr = row0 + 8*tr + i;
            float o[8];
            #pragma unroll
            for (int j = 0; j < 8; j++) o[j] = acc[i][j] + bv[j];
            *(float4*)(Cf + gr*DKn + 8*tc)     = *(float4*)(o);
            *(float4*)(Cf + gr*DKn + 8*tc + 4) = *(float4*)(o+4);
        }
    } else if (MODE == 1) {
        #pragma unroll
        for (int i = 0; i < 8; i++) {
            long long gr = (long long)blockIdx.z * rowz + row0 + 8*tr + i;
            uint32_t rr = (uint32_t)(gr & 127);
            size_t base = (size_t)(gr >> 7)*32768 + (size_t)rr*256 + swz16(rr, (uint32_t)tc);
            float v[8];
            #pragma unroll
            for (int j = 0; j < 8; j++) v[j] = (acc[i][j] + bv[j]) * oscale;
            uint4 uh, um, ul;
            split3x8(v, uh, um, ul);
            *(uint4*)(Cb + base)              = uh;
            *(uint4*)(Cb + SPLIT_SZ + base)   = um;
            *(uint4*)(Cb + 2*SPLIT_SZ + base) = ul;
        }
    } else {
        long long gt0 = row0 + 8*tr;                 // 8 consecutive tokens
        size_t tbase = (size_t)(gt0 >> 7)*32768;
        uint32_t tg = (uint32_t)((gt0 >> 3) & 15);   // token 16B-group within tile
        #pragma unroll
        for (int j = 0; j < 8; j++) {
            uint32_t d = 8*tc + j;
            float v[8];
            #pragma unroll
            for (int i = 0; i < 8; i++) v[i] = acc[i][j] + bv[j];
            uint4 uh, ul;
            split2x8(v, uh, ul);
            size_t off = tbase + (size_t)d*256 + swz16(d, tg);
            *(uint4*)(Cb + off)            = uh;
            *(uint4*)(Cb + SPLIT_SZ + off) = ul;
        }
    }
}

// ---------------- pass 1: scores via mma.sync, raw dump + m/l ----------------
// grid (32, 4), 256 thr. smem: QT 3x32KB + K double-buffer 2x(3x16KB) + stats
#define P1_SMEM (196608 + 2048)
__global__ void __launch_bounds__(256,1) attn_pass1(float* __restrict__ d_out) {
    extern __shared__ unsigned char sm[];
    uint32_t sb = smem_u32(sm);
    uint32_t qt_s = sb, k_s = sb + 98304;
    float* sMax = (float*)(sm + 196608);
    float* sSum = sMax + 256;

    int tid = threadIdx.x, w = tid >> 5, l = tid & 31;
    int b = blockIdx.y, rb = blockIdx.x;
    float* attn = d_out + (size_t)Bn*Sn*DKn;
    int wm = w >> 1, wn = w & 1;

    // prologue: QT (96KB) + K tile0 half0 (48KB) as one cp group
    size_t qtile = (size_t)(b*32 + rb)*32768;
    #pragma unroll
    for (int sp = 0; sp < 3; sp++) {
        const unsigned char* src = g_QTs + (size_t)sp*SPLIT_SZ + qtile;
        for (int i = tid; i < 2048; i += 256) cp16(qt_s + sp*32768 + i*16, src + (size_t)i*16);
    }
    {
        size_t kt = (size_t)(b*32)*32768;
        #pragma unroll
        for (int sp = 0; sp < 3; sp++) {
            const unsigned char* src = g_Ks + (size_t)sp*SPLIT_SZ + kt;
            for (int i = tid; i < 1024; i += 256) cp16(k_s + sp*16384 + i*16, src + (size_t)i*16);
        }
    }
    CP_COMMIT();

    float mreg[4], lreg[4];
    int rowid[4];
    #pragma unroll
    for (int ri = 0; ri < 4; ri++) {
        mreg[ri] = -1e30f; lreg[ri] = 0.f;
        rowid[ri] = 32*wm + 16*(ri >> 1) + (l >> 2) + 8*(ri & 1);
    }

    const int pa[6] = {0,0,1,1,0,2};
    const int pb[6] = {0,1,0,1,2,0};

    for (int jj = 0; jj < 64; jj++) {
        __syncthreads();                       // prev mma done with alt K buffer
        if (jj + 1 < 64) {
            int jt = (jj+1) >> 1, hf = (jj+1) & 1;
            size_t kt = (size_t)(b*32 + jt)*32768 + (size_t)hf*16384;
            uint32_t dst = k_s + (uint32_t)(((jj+1) & 1) * 49152);
            #pragma unroll
            for (int sp = 0; sp < 3; sp++) {
                const unsigned char* src = g_Ks + (size_t)sp*SPLIT_SZ + kt;
                for (int i = tid; i < 1024; i += 256) cp16(dst + sp*16384 + i*16, src + (size_t)i*16);
            }
            CP_COMMIT();
            CP_WAIT(1);
        } else {
            CP_WAIT(0);
        }
        __syncthreads();

        uint32_t kbase = k_s + (uint32_t)((jj & 1) * 49152);
        float acc[2][4][4];
        #pragma unroll
        for (int mt = 0; mt < 2; mt++)
            #pragma unroll
            for (int nt = 0; nt < 4; nt++)
                #pragma unroll
                for (int c = 0; c < 4; c++) acc[mt][nt][c] = 0.f;

        #pragma unroll
        for (int pr = 0; pr < 6; pr++) {
            uint32_t abase = qt_s + (uint32_t)(pa[pr] * 32768);
            uint32_t bbase = kbase + (uint32_t)(pb[pr] * 16384);
            #pragma unroll
            for (int kc = 0; kc < 8; kc++) {
                uint32_t afr[2][4], bfr[4][2];
                #pragma unroll
                for (int mt = 0; mt < 2; mt++) {
                    uint32_t r = 32*wm + 16*mt + (l & 7) + ((l >> 3) & 1)*8;
                    uint32_t g = kc*2 + (l >> 4);
                    ldm_x4(afr[mt], abase + r*256 + swz16(r, g));
                }
                #pragma unroll
                for (int nt = 0; nt < 4; nt++) {
                    uint32_t n = 32*wn + 8*nt + (l & 7);
                    uint32_t g = kc*2 + ((l >> 3) & 1);
                    ldm_x2(bfr[nt], bbase + n*256 + swz16(n, g));
                }
                #pragma unroll
                for (int mt = 0; mt < 2; mt++)
                    #pragma unroll
                    for (int nt = 0; nt < 4; nt++)
                        mma16816(acc[mt][nt], afr[mt], bfr[nt]);
            }
        }

        // dump raw scaled scores
        size_t colbase = (size_t)jj*64 + 32*wn + 2*(l & 3);
        #pragma unroll
        for (int ri = 0; ri < 4; ri++) {
            int mt = ri >> 1, dl = ri & 1;
            float* dst = attn + ((size_t)b*Sn + rb*128 + rowid[ri])*Sn + colbase;
            #pragma unroll
            for (int nt = 0; nt < 4; nt++)
                *(float2*)(dst + 8*nt) = make_float2(acc[mt][nt][2*dl], acc[mt][nt][2*dl+1]);
        }

        // online softmax stats
        float mn_s[4];
        #pragma unroll
        for (int ri = 0; ri < 4; ri++) {
            int mt = ri >> 1, dl = ri & 1;
            float tm = -1e30f;
            #pragma unroll
            for (int nt = 0; nt < 4; nt++)
                tm = fmaxf(tm, fmaxf(acc[mt][nt][2*dl], acc[mt][nt][2*dl+1]));
            tm = fmaxf(tm, __shfl_xor_sync(0xffffffffu, tm, 1));
            tm = fmaxf(tm, __shfl_xor_sync(0xffffffffu, tm, 2));
            if ((l & 3) == 0) sMax[rowid[ri]*2 + wn] = tm;
        }
        __syncthreads();
        #pragma unroll
        for (int ri = 0; ri < 4; ri++) {
            int mt = ri >> 1, dl = ri & 1;
            float mn = fmaxf(mreg[ri], fmaxf(sMax[rowid[ri]*2], sMax[rowid[ri]*2 + 1]));
            mn_s[ri] = mn;
            float rs = 0.f;
            #pragma unroll
            for (int nt = 0; nt < 4; nt++)
                rs += __expf(acc[mt][nt][2*dl] - mn) + __expf(acc[mt][nt][2*dl+1] - mn);
            rs += __shfl_xor_sync(0xffffffffu, rs, 1);
            rs += __shfl_xor_sync(0xffffffffu, rs, 2);
            if ((l & 3) == 0) sSum[rowid[ri]*2 + wn] = rs;
        }
        __syncthreads();
        #pragma unroll
        for (int ri = 0; ri < 4; ri++) {
            float tot = sSum[rowid[ri]*2] + sSum[rowid[ri]*2 + 1];
            lreg[ri] = lreg[ri]*__expf(mreg[ri] - mn_s[ri]) + tot;
            mreg[ri] = mn_s[ri];
        }
    }

    if (wn == 0 && (l & 3) == 0) {
        #pragma unroll
        for (int ri = 0; ri < 4; ri++) {
            size_t rg = (size_t)b*Sn + rb*128 + rowid[ri];
            g_m[rg] = mreg[ri];
            g_l[rg] = lreg[ri];
        }
    }
}

// ---------------- pass 2: p = exp(s-m)/l in place + out = p @ V ----------------
// smem: P 2x32KB + V double-buffer 2x(2x32KB)
#define P2_SMEM 196608
__global__ void __launch_bounds__(256,1) attn_pass2(float* __restrict__ d_out) {
    extern __shared__ unsigned char sm[];
    uint32_t sb = smem_u32(sm);
    uint32_t p_s = sb, v_s = sb + 65536;

    int tid = threadIdx.x, w = tid >> 5, l = tid & 31;
    int b = blockIdx.y, rb = blockIdx.x;
    float* attn = d_out + (size_t)Bn*Sn*DKn;
    int wm = w & 1, wn = w >> 1;

    // per-thread row constants for exp phase: row = 16*pass + (tid>>4)
    float mml[8], lli[8];
    int rlow = tid >> 4;
    #pragma unroll
    for (int pass = 0; pass < 8; pass++) {
        size_t rg = (size_t)b*Sn + rb*128 + 16*pass + rlow;
        mml[pass] = g_m[rg];
        lli[pass] = 1.0f / g_l[rg];
    }

    // prologue: V(0)
    {
        size_t vt = (size_t)(b*32)*32768;
        #pragma unroll
        for (int sp = 0; sp < 2; sp++) {
            const unsigned char* src = g_Vt + (size_t)sp*SPLIT_SZ + vt;
            for (int i = tid; i < 2048; i += 256) cp16(v_s + sp*32768 + i*16, src + (size_t)i*16);
        }
        CP_COMMIT();
    }

    float out[4][4][4];
    #pragma unroll
    for (int mt = 0; mt < 4; mt++)
        #pragma unroll
        for (int nt = 0; nt < 4; nt++)
            #pragma unroll
            for (int c = 0; c < 4; c++) out[mt][nt][c] = 0.f;

    const int pa2[3] = {0,0,1};
    const int pb2[3] = {0,1,0};

    for (int j = 0; j < 32; j++) {
        __syncthreads();                  // prev mma done: P writable, V alt writable

        // exp phase: read raw scores, write final p, stage 2-split into P smem
        #pragma unroll
        for (int pass = 0; pass < 8; pass++) {
            int i = pass*2048 + tid*8;
            int row = i >> 7, col = i & 127;
            float* src = attn + ((size_t)b*Sn + rb*128 + row)*Sn + (size_t)j*128 + col;
            float p8[8];
            *(float4*)(p8)   = *(const float4*)(src);
            *(float4*)(p8+4) = *(const float4*)(src + 4);
            #pragma unroll
            for (int x = 0; x < 8; x++) p8[x] = __expf(p8[x] - mml[pass]) * lli[pass];
            *(float4*)(src)     = *(float4*)(p8);
            *(float4*)(src + 4) = *(float4*)(p8+4);
            uint4 uh, ul;
            split2x8(p8, uh, ul);
            uint32_t a = p_s + (uint32_t)row*256 + swz16((uint32_t)row, (uint32_t)(col >> 3));
            STS16(a, uh);
            STS16(a + 32768, ul);
        }

        if (j + 1 < 32) {
            size_t vt = (size_t)(b*32 + j + 1)*32768;
            uint32_t dst = v_s + (uint32_t)(((j+1) & 1) * 65536);
            #pragma unroll
            for (int sp = 0; sp < 2; sp++) {
                const unsigned char* src = g_Vt + (size_t)sp*SPLIT_SZ + vt;
                for (int i = tid; i < 2048; i += 256) cp16(dst + sp*32768 + i*16, src + (size_t)i*16);
            }
            CP_COMMIT();
            CP_WAIT(1);
        } else {
            CP_WAIT(0);
        }
        __syncthreads();

        uint32_t vb = v_s + (uint32_t)((j & 1) * 65536);
        #pragma unroll
        for (int pr = 0; pr < 3; pr++) {
            uint32_t abase = p_s + (uint32_t)(pa2[pr] * 32768);
            uint32_t bbase = vb  + (uint32_t)(pb2[pr] * 32768);
            #pragma unroll
            for (int kc = 0; kc < 8; kc++) {
                uint32_t afr[4][4], bfr[4][2];
                #pragma unroll
                for (int mt = 0; mt < 4; mt++) {
                    uint32_t r = 64*wm + 16*mt + (l & 7) + ((l >> 3) & 1)*8;
                    uint32_t g = kc*2 + (l >> 4);
                    ldm_x4(afr[mt], abase + r*256 + swz16(r, g));
                }
                #pragma unroll
                for (int nt = 0; nt < 4; nt++) {
                    uint32_t n = 32*wn + 8*nt + (l & 7);
                    uint32_t g = kc*2 + ((l >> 3) & 1);
                    ldm_x2(bfr[nt], bbase + n*256 + swz16(n, g));
                }
                #pragma unroll
                for (int mt = 0; mt < 4; mt++)
                    #pragma unroll
                    for (int nt = 0; nt < 4; nt++)
                        mma16816(out[mt][nt], afr[mt], bfr[nt]);
            }
        }
    }

    // epilogue: write out
    #pragma unroll
    for (int mt = 0; mt < 4; mt++)
        #pragma unroll
        for (int dl = 0; dl < 2; dl++) {
            int row = 64*wm + 16*mt + (l >> 2) + 8*dl;
            float* o = d_out + ((size_t)b*Sn + rb*128 + row)*DKn + 32*wn + 2*(l & 3);
            #pragma unroll
            for (int nt = 0; nt < 4; nt++)
                *(float2*)(o + 8*nt) = make_float2(out[mt][nt][2*dl], out[mt][nt][2*dl+1]);
        }
}

// ---------------- launcher ----------------
extern "C" void kernel_launch(void* const* d_in, const int* in_sizes, int n_in,
                              void* d_out, int out_size) {
    const float* x  = (const float*)d_in[0];
    const float* tp = (const float*)d_in[1];
    const float* Wq = (const float*)d_in[2];
    const float* bq = (const float*)d_in[3];
    const float* Wk = (const float*)d_in[4];
    const float* bk = (const float*)d_in[5];
    const float* Wv = (const float*)d_in[6];
    const float* bv = (const float*)d_in[7];
    const float* Wt = (const float*)d_in[8];
    const float* bt = (const float*)d_in[9];
    float* out = (float*)d_out;

    float *pQ, *pT;
    unsigned char *pKs, *pQTs, *pVt;
    cudaGetSymbolAddress((void**)&pQ,   g_Q);
    cudaGetSymbolAddress((void**)&pT,   g_T);
    cudaGetSymbolAddress((void**)&pKs,  g_Ks);
    cudaGetSymbolAddress((void**)&pQTs, g_QTs);
    cudaGetSymbolAddress((void**)&pVt,  g_Vt);

    cudaFuncSetAttribute(attn_pass1, cudaFuncAttributeMaxDynamicSharedMemorySize, P1_SMEM);
    cudaFuncSetAttribute(attn_pass2, cudaFuncAttributeMaxDynamicSharedMemorySize, P2_SMEM);

    prep_T_kernel<<<Bn, 256>>>(tp, Wt, bt);
    // Q fp32, K 3-split blobs, V^T 2-split blobs
    gemm128<0><<<dim3(128,1,1), 256>>>(x, Wq, bq, pQ, nullptr, Dn, 0, 0, Sn, 1.0f);
    gemm128<1><<<dim3(128,1,1), 256>>>(x, Wk, bk, nullptr, pKs, Dn, 0, 0, Sn, 1.0f);
    gemm128<2><<<dim3(128,1,1), 256>>>(x, Wv, bv, nullptr, pVt, Dn, 0, 0, Sn, 1.0f);
    // QT = (Q @ T_scaled) * 1/sqrt(dk), 3-split blobs
    gemm128<1><<<dim3(32,1,Bn), 256>>>(pQ, pT, nullptr, nullptr, pQTs, DKn,
                                       (long long)Sn*DKn, (long long)DKn*DKn, Sn, SCALE);
    attn_pass1<<<dim3(32, Bn), 256, P1_SMEM>>>(out);
    attn_pass2<<<dim3(32, Bn), 256, P2_SMEM>>>(out);
}

// round 5
// speedup vs baseline: 2.1235x; 1.2400x over previous
#include <cuda_runtime.h>
#include <cuda_bf16.h>
#include <math.h>
#include <stdint.h>

#define Bn 4
#define Sn 4096
#define Dn 1024
#define TPn 16
#define TEn 64
#define DKn 128
#define NTILE 128
#define SPLIT_SZ (NTILE*32768ULL)       // 256B-row blob images (K/Q/QT/Vt)
#define XS_SPLIT (NTILE*16*16384ULL)    // x split images: 2048 blobs of 16KB
#define WS_SPLIT (3*16*16384ULL)        // W^T split images: 3 mats x 16 chunks
#define TS_SPLIT (Bn*32768ULL)
#define SCALE 0.08838834764831845f

// ---------------- scratch ----------------
__device__ float g_m[Bn*Sn];
__device__ float g_l[Bn*Sn];
__device__ __align__(16) unsigned char g_xs [3*XS_SPLIT];
__device__ __align__(16) unsigned char g_Ws [3*WS_SPLIT];
__device__ __align__(16) unsigned char g_Ts [3*TS_SPLIT];
__device__ __align__(16) unsigned char g_Qs [3*SPLIT_SZ];
__device__ __align__(16) unsigned char g_Ks [3*SPLIT_SZ];
__device__ __align__(16) unsigned char g_QTs[3*SPLIT_SZ];
__device__ __align__(16) unsigned char g_Vt [2*SPLIT_SZ];

// ---------------- helpers ----------------
__device__ __forceinline__ uint32_t smem_u32(const void* p){
    uint32_t a;
    asm("{ .reg .u64 t; cvta.to.shared.u64 t, %1; cvt.u32.u64 %0, t; }" : "=r"(a) : "l"(p));
    return a;
}
__device__ __forceinline__ uint32_t swz16(uint32_t r, uint32_t g){
    return ((g & 8u) | ((g ^ r) & 7u)) << 4;       // 256B rows, 16 groups
}
__device__ __forceinline__ uint32_t swz8(uint32_t r, uint32_t g){
    return ((g ^ r) & 7u) << 4;                    // 128B rows, 8 groups
}
__device__ __forceinline__ void cp16(uint32_t dst, const void* src){
    asm volatile("cp.async.cg.shared.global [%0], [%1], 16;" :: "r"(dst), "l"(src) : "memory");
}
#define CP_COMMIT() asm volatile("cp.async.commit_group;" ::: "memory")
#define CP_WAIT(n)  asm volatile("cp.async.wait_group %0;" :: "n"(n) : "memory")
#define STS16(addr, v) asm volatile("st.shared.v4.b32 [%0], {%1,%2,%3,%4};" \
    :: "r"(addr), "r"((v).x), "r"((v).y), "r"((v).z), "r"((v).w) : "memory")

__device__ __forceinline__ void ldm_x4(uint32_t* r, uint32_t addr){
    asm volatile("ldmatrix.sync.aligned.m8n8.x4.shared.b16 {%0,%1,%2,%3}, [%4];"
        : "=r"(r[0]), "=r"(r[1]), "=r"(r[2]), "=r"(r[3]) : "r"(addr));
}
__device__ __forceinline__ void ldm_x2(uint32_t* r, uint32_t addr){
    asm volatile("ldmatrix.sync.aligned.m8n8.x2.shared.b16 {%0,%1}, [%2];"
        : "=r"(r[0]), "=r"(r[1]) : "r"(addr));
}
__device__ __forceinline__ void mma16816(float* d, const uint32_t* a, const uint32_t* b){
    asm volatile("mma.sync.aligned.m16n8k16.row.col.f32.bf16.bf16.f32 "
        "{%0,%1,%2,%3}, {%4,%5,%6,%7}, {%8,%9}, {%0,%1,%2,%3};"
        : "+f"(d[0]), "+f"(d[1]), "+f"(d[2]), "+f"(d[3])
        : "r"(a[0]), "r"(a[1]), "r"(a[2]), "r"(a[3]), "r"(b[0]), "r"(b[1]));
}
__device__ __forceinline__ uint32_t pk(unsigned short a, unsigned short b){
    return (uint32_t)a | ((uint32_t)b << 16);
}
__device__ __forceinline__ void split3x8(const float* v, uint4& uh, uint4& um, uint4& ul){
    unsigned short h[8], m[8], l[8];
    #pragma unroll
    for (int j = 0; j < 8; j++){
        __nv_bfloat16 bh = __float2bfloat16(v[j]);
        float r = v[j] - __bfloat162float(bh);
        __nv_bfloat16 bm = __float2bfloat16(r);
        r -= __bfloat162float(bm);
        __nv_bfloat16 bl = __float2bfloat16(r);
        h[j] = __bfloat16_as_ushort(bh); m[j] = __bfloat16_as_ushort(bm); l[j] = __bfloat16_as_ushort(bl);
    }
    uh = make_uint4(pk(h[0],h[1]), pk(h[2],h[3]), pk(h[4],h[5]), pk(h[6],h[7]));
    um = make_uint4(pk(m[0],m[1]), pk(m[2],m[3]), pk(m[4],m[5]), pk(m[6],m[7]));
    ul = make_uint4(pk(l[0],l[1]), pk(l[2],l[3]), pk(l[4],l[5]), pk(l[6],l[7]));
}
__device__ __forceinline__ void split2x8(const float* v, uint4& uh, uint4& ul){
    unsigned short h[8], l[8];
    #pragma unroll
    for (int j = 0; j < 8; j++){
        __nv_bfloat16 bh = __float2bfloat16(v[j]);
        __nv_bfloat16 bl = __float2bfloat16(v[j] - __bfloat162float(bh));
        h[j] = __bfloat16_as_ushort(bh); l[j] = __bfloat16_as_ushort(bl);
    }
    uh = make_uint4(pk(h[0],h[1]), pk(h[2],h[3]), pk(h[4],h[5]), pk(h[6],h[7]));
    ul = make_uint4(pk(l[0],l[1]), pk(l[2],l[3]), pk(l[4],l[5]), pk(l[6],l[7]));
}

// ---------------- kernel 1: T_scaled (x SCALE) -> 3-split blobs ----------------
__global__ void prep_T_kernel(const float* __restrict__ tp,
                              const float* __restrict__ Wt,
                              const float* __restrict__ bt) {
    __shared__ float sTP[TPn*TEn];
    __shared__ float sWt[TEn*DKn];
    __shared__ float sE [TPn*DKn];
    __shared__ float red[256];
    int b = blockIdx.x, tid = threadIdx.x;
    for (int i = tid; i < TPn*TEn; i += 256) sTP[i] = tp[b*TPn*TEn + i];
    for (int i = tid; i < TEn*DKn; i += 256) sWt[i] = Wt[i];
    __syncthreads();
    for (int i = tid; i < TPn*DKn; i += 256) {
        int t = i >> 7, d = i & 127;
        float acc = bt[d];
        #pragma unroll 8
        for (int e = 0; e < TEn; e++) acc += sTP[t*TEn + e] * sWt[e*DKn + d];
        sE[i] = acc;
    }
    __syncthreads();
    float ss = 0.f;
    for (int i = tid; i < TPn*DKn; i += 256) ss += sE[i]*sE[i];
    red[tid] = ss; __syncthreads();
    for (int off = 128; off > 0; off >>= 1) {
        if (tid < off) red[tid] += red[tid+off];
        __syncthreads();
    }
    float tn = sqrtf((float)Sn * red[0]);
    float sc = (float)Sn / (tn + 1e-8f) * SCALE;
    for (int i = tid; i < DKn*DKn; i += 256) {
        int d = i >> 7, e2 = i & 127;
        float acc = 0.f;
        #pragma unroll
        for (int t = 0; t < TPn; t++) acc += sE[t*DKn + d] * sE[t*DKn + e2];
        float v = acc * sc;
        // T symmetric: blob[n=e][k=d] value = T[d][n] = T[n][d] -> store at (d,e2)
        __nv_bfloat16 bh = __float2bfloat16(v);
        float r1 = v - __bfloat162float(bh);
        __nv_bfloat16 bm = __float2bfloat16(r1);
        __nv_bfloat16 bl = __float2bfloat16(r1 - __bfloat162float(bm));
        size_t base = (size_t)b*32768 + (size_t)d*256 + swz16((uint32_t)d, (uint32_t)(e2 >> 3)) + (size_t)(e2 & 7)*2;
        *(__nv_bfloat16*)(g_Ts + base)              = bh;
        *(__nv_bfloat16*)(g_Ts + TS_SPLIT + base)   = bm;
        *(__nv_bfloat16*)(g_Ts + 2*TS_SPLIT + base) = bl;
    }
}

// ---------------- kernel 2: split x -> 3-split blobs ----------------
__global__ void split_x_kernel(const float* __restrict__ x) {
    int gidx = blockIdx.x*256 + threadIdx.x;       // 2,097,152 groups of 8
    int rt = gidx >> 7, gk = gidx & 127;
    int kc = gk >> 3, g = gk & 7;
    const float* src = x + (size_t)rt*Dn + kc*64 + g*8;
    float v[8];
    *(float4*)(v)   = *(const float4*)(src);
    *(float4*)(v+4) = *(const float4*)(src + 4);
    uint4 uh, um, ul;
    split3x8(v, uh, um, ul);
    int tile = rt >> 7, r = rt & 127;
    size_t off = (size_t)(tile*16 + kc)*16384 + (size_t)r*128 + swz8((uint32_t)r, (uint32_t)g);
    *(uint4*)(g_xs + off)              = uh;
    *(uint4*)(g_xs + XS_SPLIT + off)   = um;
    *(uint4*)(g_xs + 2*XS_SPLIT + off) = ul;
}

// ---------------- kernel 3: split W^T -> 3-split blobs ----------------
__global__ void split_W_kernel(const float* __restrict__ Wq,
                               const float* __restrict__ Wk,
                               const float* __restrict__ Wv) {
    __shared__ float sW[64*128];
    int kc = blockIdx.x, mat = blockIdx.y, tid = threadIdx.x;
    const float* W = (mat == 0) ? Wq : ((mat == 1) ? Wk : Wv);
    for (int i = tid; i < 2048; i += 256)
        ((float4*)sW)[i] = ((const float4*)(W + (size_t)kc*64*128))[i];
    __syncthreads();
    for (int it = 0; it < 4; it++) {
        int gi = tid + it*256;
        int d = gi >> 3, g = gi & 7;
        float v[8];
        #pragma unroll
        for (int j = 0; j < 8; j++) v[j] = sW[(g*8 + j)*128 + d];
        uint4 uh, um, ul;
        split3x8(v, uh, um, ul);
        size_t off = (size_t)(mat*16 + kc)*16384 + (size_t)d*128 + swz8((uint32_t)d, (uint32_t)g);
        *(uint4*)(g_Ws + off)              = uh;
        *(uint4*)(g_Ws + WS_SPLIT + off)   = um;
        *(uint4*)(g_Ws + 2*WS_SPLIT + off) = ul;
    }
}

// ---------------- kernel 4: TC projection GEMM (K=1024, 16 chunks of 64) ----------------
// out[128 x 128] per CTA. MODE 1: rows=tokens, 3-split blob + bias[col].
// MODE 2: rows=dk, 2-split blob + bias[row] (V^T).
#define PROJ_SMEM 196608
template<int NPROD, int MODE>
__global__ void __launch_bounds__(256,1)
proj_tc(const unsigned char* __restrict__ Ab, size_t Asplit, int aStride,
        const unsigned char* __restrict__ Bb, size_t Bsplit, int bStride,
        const float* __restrict__ bias, unsigned char* __restrict__ Out,
        size_t OutSplit) {
    extern __shared__ unsigned char sm[];
    uint32_t sb = smem_u32(sm);
    int tid = threadIdx.x, w = tid >> 5, l = tid & 31;
    int tile = blockIdx.x;
    int aB0 = tile * aStride, bB0 = tile * bStride;
    const int NSP = (NPROD == 6) ? 3 : 2;
    const int pa[6] = {0,0,1,1,0,2};
    const int pb[6] = {0,1,0,1,2,0};

    float acc[16][4];
    #pragma unroll
    for (int nt = 0; nt < 16; nt++)
        #pragma unroll
        for (int c = 0; c < 4; c++) acc[nt][c] = 0.f;

    uint32_t stg[2] = {sb, sb + 98304};
    // prologue: chunk 0 -> stage 0
    #pragma unroll
    for (int sp = 0; sp < NSP; sp++) {
        const unsigned char* sa = Ab + (size_t)sp*Asplit + (size_t)(aB0 + 0)*16384;
        const unsigned char* sv = Bb + (size_t)sp*Bsplit + (size_t)(bB0 + 0)*16384;
        for (int i = tid; i < 1024; i += 256) {
            cp16(stg[0] + sp*16384 + i*16, sa + (size_t)i*16);
            cp16(stg[0] + 49152 + sp*16384 + i*16, sv + (size_t)i*16);
        }
    }
    CP_COMMIT();

    for (int kc = 0; kc < 16; kc++) {
        __syncthreads();
        if (kc + 1 < 16) {
            uint32_t dst = stg[(kc+1) & 1];
            #pragma unroll
            for (int sp = 0; sp < NSP; sp++) {
                const unsigned char* sa = Ab + (size_t)sp*Asplit + (size_t)(aB0 + kc + 1)*16384;
                const unsigned char* sv = Bb + (size_t)sp*Bsplit + (size_t)(bB0 + kc + 1)*16384;
                for (int i = tid; i < 1024; i += 256) {
                    cp16(dst + sp*16384 + i*16, sa + (size_t)i*16);
                    cp16(dst + 49152 + sp*16384 + i*16, sv + (size_t)i*16);
                }
            }
            CP_COMMIT();
            CP_WAIT(1);
        } else {
            CP_WAIT(0);
        }
        __syncthreads();

        uint32_t a0 = stg[kc & 1], b0 = stg[kc & 1] + 49152;
        #pragma unroll
        for (int pr = 0; pr < NPROD; pr++) {
            uint32_t abase = a0 + (uint32_t)pa[pr]*16384;
            uint32_t bbase = b0 + (uint32_t)pb[pr]*16384;
            #pragma unroll
            for (int ks = 0; ks < 4; ks++) {
                uint32_t afr[4], bfr[32];
                {
                    uint32_t r = 16*w + (l & 7) + 8*((l >> 3) & 1);
                    uint32_t g = ks*2 + (l >> 4);
                    ldm_x4(afr, abase + r*128 + swz8(r, g));
                }
                #pragma unroll
                for (int p = 0; p < 8; p++) {
                    uint32_t n = 16*p + 8*((l >> 4) & 1) + (l & 7);
                    uint32_t g = ks*2 + ((l >> 3) & 1);
                    ldm_x4(bfr + 4*p, bbase + n*128 + swz8(n, g));
                }
                #pragma unroll
                for (int nt = 0; nt < 16; nt++)
                    mma16816(acc[nt], afr, &bfr[2*nt]);
            }
        }
    }

    // epilogue: stage fp32 through smem, then split-write blobs
    __syncthreads();
    float* sOut = (float*)sm;
    #pragma unroll
    for (int nt = 0; nt < 16; nt++) {
        int colb = 8*nt + 2*(l & 3);
        int r0 = 16*w + (l >> 2);
        sOut[r0*132 + colb]       = acc[nt][0];
        sOut[r0*132 + colb + 1]   = acc[nt][1];
        sOut[(r0+8)*132 + colb]   = acc[nt][2];
        sOut[(r0+8)*132 + colb+1] = acc[nt][3];
    }
    __syncthreads();
    int tr = tid >> 4, tc = tid & 15;
    if (MODE == 1) {
        float bv[8];
        *(float4*)(bv)   = *(const float4*)(bias + 8*tc);
        *(float4*)(bv+4) = *(const float4*)(bias + 8*tc + 4);
        #pragma unroll
        for (int i = 0; i < 8; i++) {
            int row = 8*tr + i;
            float v[8];
            #pragma unroll
            for (int j = 0; j < 8; j++) v[j] = sOut[row*132 + 8*tc + j] + bv[j];
            uint4 uh, um, ul;
            split3x8(v, uh, um, ul);
            size_t base = (size_t)tile*32768 + (size_t)row*256 + swz16((uint32_t)row, (uint32_t)tc);
            *(uint4*)(Out + base)              = uh;
            *(uint4*)(Out + OutSplit + base)   = um;
            *(uint4*)(Out + 2*OutSplit + base) = ul;
        }
    } else {
        #pragma unroll
        for (int i = 0; i < 8; i++) {
            int d = 8*tr + i;
            float bd = bias[d];
            float v[8];
            #pragma unroll
            for (int j = 0; j < 8; j++) v[j] = sOut[d*132 + 8*tc + j] + bd;
            uint4 uh, ul;
            split2x8(v, uh, ul);
            size_t base = (size_t)tile*32768 + (size_t)d*256 + swz16((uint32_t)d, (uint32_t)tc);
            *(uint4*)(Out + base)            = uh;
            *(uint4*)(Out + OutSplit + base) = ul;
        }
    }
}

// ---------------- kernel 5: QT = Qs @ Ts (K=128, 6 products) ----------------
#define QT_SMEM 196608
__global__ void __launch_bounds__(256,1) qt_tc() {
    extern __shared__ unsigned char sm[];
    uint32_t sb = smem_u32(sm);
    int tid = threadIdx.x, w = tid >> 5, l = tid & 31;
    int b = blockIdx.y, rb = blockIdx.x, tile = b*32 + rb;
    const int pa[6] = {0,0,1,1,0,2};
    const int pb[6] = {0,1,0,1,2,0};

    #pragma unroll
    for (int sp = 0; sp < 3; sp++) {
        const unsigned char* sa = g_Qs + (size_t)sp*SPLIT_SZ + (size_t)tile*32768;
        const unsigned char* st = g_Ts + (size_t)sp*TS_SPLIT + (size_t)b*32768;
        for (int i = tid; i < 2048; i += 256) {
            cp16(sb + sp*32768 + i*16, sa + (size_t)i*16);
            cp16(sb + 98304 + sp*32768 + i*16, st + (size_t)i*16);
        }
    }
    CP_COMMIT();
    CP_WAIT(0);
    __syncthreads();

    float acc[16][4];
    #pragma unroll
    for (int nt = 0; nt < 16; nt++)
        #pragma unroll
        for (int c = 0; c < 4; c++) acc[nt][c] = 0.f;

    #pragma unroll
    for (int pr = 0; pr < 6; pr++) {
        uint32_t abase = sb + (uint32_t)pa[pr]*32768;
        uint32_t bbase = sb + 98304 + (uint32_t)pb[pr]*32768;
        #pragma unroll
        for (int ks = 0; ks < 8; ks++) {
            uint32_t afr[4], bfr[32];
            {
                uint32_t r = 16*w + (l & 7) + 8*((l >> 3) & 1);
                uint32_t g = ks*2 + (l >> 4);
                ldm_x4(afr, abase + r*256 + swz16(r, g));
            }
            #pragma unroll
            for (int p = 0; p < 8; p++) {
                uint32_t n = 16*p + 8*((l >> 4) & 1) + (l & 7);
                uint32_t g = ks*2 + ((l >> 3) & 1);
                ldm_x4(bfr + 4*p, bbase + n*256 + swz16(n, g));
            }
            #pragma unroll
            for (int nt = 0; nt < 16; nt++)
                mma16816(acc[nt], afr, &bfr[2*nt]);
        }
    }

    __syncthreads();
    float* sOut = (float*)sm;
    #pragma unroll
    for (int nt = 0; nt < 16; nt++) {
        int colb = 8*nt + 2*(l & 3);
        int r0 = 16*w + (l >> 2);
        sOut[r0*132 + colb]       = acc[nt][0];
        sOut[r0*132 + colb + 1]   = acc[nt][1];
        sOut[(r0+8)*132 + colb]   = acc[nt][2];
        sOut[(r0+8)*132 + colb+1] = acc[nt][3];
    }
    __syncthreads();
    int tr = tid >> 4, tc = tid & 15;
    #pragma unroll
    for (int i = 0; i < 8; i++) {
        int row = 8*tr + i;
        float v[8];
        #pragma unroll
        for (int j = 0; j < 8; j++) v[j] = sOut[row*132 + 8*tc + j];
        uint4 uh, um, ul;
        split3x8(v, uh, um, ul);
        size_t base = (size_t)tile*32768 + (size_t)row*256 + swz16((uint32_t)row, (uint32_t)tc);
        *(uint4*)(g_QTs + base)              = uh;
        *(uint4*)(g_QTs + SPLIT_SZ + base)   = um;
        *(uint4*)(g_QTs + 2*SPLIT_SZ + base) = ul;
    }
}

// ---------------- pass 1: scores, raw dump, warp-private m/l ----------------
#define P1_SMEM 196608
__global__ void __launch_bounds__(256,1) attn_pass1(float* __restrict__ d_out) {
    extern __shared__ unsigned char sm[];
    uint32_t sb = smem_u32(sm);
    uint32_t qt_s = sb, k_s = sb + 98304;

    int tid = threadIdx.x, w = tid >> 5, l = tid & 31;
    int b = blockIdx.y, rb = blockIdx.x;
    float* attn = d_out + (size_t)Bn*Sn*DKn;
    size_t rowbase = (size_t)b*Sn + (size_t)rb*128;

    size_t qtile = (size_t)(b*32 + rb)*32768;
    #pragma unroll
    for (int sp = 0; sp < 3; sp++) {
        const unsigned char* src = g_QTs + (size_t)sp*SPLIT_SZ + qtile;
        for (int i = tid; i < 2048; i += 256) cp16(qt_s + sp*32768 + i*16, src + (size_t)i*16);
    }
    {
        size_t kt = (size_t)(b*32)*32768;
        #pragma unroll
        for (int sp = 0; sp < 3; sp++) {
            const unsigned char* src = g_Ks + (size_t)sp*SPLIT_SZ + kt;
            for (int i = tid; i < 1024; i += 256) cp16(k_s + sp*16384 + i*16, src + (size_t)i*16);
        }
    }
    CP_COMMIT();

    const int pa[6] = {0,0,1,1,0,2};
    const int pb[6] = {0,1,0,1,2,0};
    int r0 = 16*w + (l >> 2);
    float m0 = -1e30f, l0 = 0.f, m1 = -1e30f, l1 = 0.f;

    for (int jj = 0; jj < 64; jj++) {
        __syncthreads();
        if (jj + 1 < 64) {
            int jt = (jj+1) >> 1, hf = (jj+1) & 1;
            size_t kt = (size_t)(b*32 + jt)*32768 + (size_t)hf*16384;
            uint32_t dst = k_s + (uint32_t)(((jj+1) & 1) * 49152);
            #pragma unroll
            for (int sp = 0; sp < 3; sp++) {
                const unsigned char* src = g_Ks + (size_t)sp*SPLIT_SZ + kt;
                for (int i = tid; i < 1024; i += 256) cp16(dst + sp*16384 + i*16, src + (size_t)i*16);
            }
            CP_COMMIT();
            CP_WAIT(1);
        } else {
            CP_WAIT(0);
        }
        __syncthreads();

        uint32_t kbase = k_s + (uint32_t)((jj & 1) * 49152);
        float acc[8][4];
        #pragma unroll
        for (int nt = 0; nt < 8; nt++)
            #pragma unroll
            for (int c = 0; c < 4; c++) acc[nt][c] = 0.f;

        #pragma unroll
        for (int pr = 0; pr < 6; pr++) {
            uint32_t abase = qt_s + (uint32_t)pa[pr]*32768;
            uint32_t bbase = kbase + (uint32_t)pb[pr]*16384;
            #pragma unroll
            for (int kc = 0; kc < 8; kc++) {
                uint32_t afr[4], bfr[16];
                {
                    uint32_t r = 16*w + (l & 7) + 8*((l >> 3) & 1);
                    uint32_t g = kc*2 + (l >> 4);
                    ldm_x4(afr, abase + r*256 + swz16(r, g));
                }
                #pragma unroll
                for (int p = 0; p < 4; p++) {
                    uint32_t n = 16*p + 8*((l >> 4) & 1) + (l & 7);
                    uint32_t g = kc*2 + ((l >> 3) & 1);
                    ldm_x4(bfr + 4*p, bbase + n*256 + swz16(n, g));
                }
                #pragma unroll
                for (int nt = 0; nt < 8; nt++)
                    mma16816(acc[nt], afr, &bfr[2*nt]);
            }
        }

        // warp-private softmax stats (quad shuffles)
        float tm0 = -1e30f, tm1 = -1e30f;
        #pragma unroll
        for (int nt = 0; nt < 8; nt++) {
            tm0 = fmaxf(tm0, fmaxf(acc[nt][0], acc[nt][1]));
            tm1 = fmaxf(tm1, fmaxf(acc[nt][2], acc[nt][3]));
        }
        tm0 = fmaxf(tm0, __shfl_xor_sync(0xffffffffu, tm0, 1));
        tm0 = fmaxf(tm0, __shfl_xor_sync(0xffffffffu, tm0, 2));
        tm1 = fmaxf(tm1, __shfl_xor_sync(0xffffffffu, tm1, 1));
        tm1 = fmaxf(tm1, __shfl_xor_sync(0xffffffffu, tm1, 2));
        float mn0 = fmaxf(m0, tm0), mn1 = fmaxf(m1, tm1);
        float rs0 = 0.f, rs1 = 0.f;
        #pragma unroll
        for (int nt = 0; nt < 8; nt++) {
            rs0 += __expf(acc[nt][0] - mn0) + __expf(acc[nt][1] - mn0);
            rs1 += __expf(acc[nt][2] - mn1) + __expf(acc[nt][3] - mn1);
        }
        rs0 += __shfl_xor_sync(0xffffffffu, rs0, 1);
        rs0 += __shfl_xor_sync(0xffffffffu, rs0, 2);
        rs1 += __shfl_xor_sync(0xffffffffu, rs1, 1);
        rs1 += __shfl_xor_sync(0xffffffffu, rs1, 2);
        l0 = l0*__expf(m0 - mn0) + rs0; m0 = mn0;
        l1 = l1*__expf(m1 - mn1) + rs1; m1 = mn1;

        // dump raw scaled scores
        float* dst0 = attn + (rowbase + r0)*Sn + (size_t)jj*64 + 2*(l & 3);
        float* dst1 = attn + (rowbase + r0 + 8)*Sn + (size_t)jj*64 + 2*(l & 3);
        #pragma unroll
        for (int nt = 0; nt < 8; nt++) {
            *(float2*)(dst0 + 8*nt) = make_float2(acc[nt][0], acc[nt][1]);
            *(float2*)(dst1 + 8*nt) = make_float2(acc[nt][2], acc[nt][3]);
        }
    }

    if ((l & 3) == 0) {
        g_m[rowbase + r0]     = m0;
        g_l[rowbase + r0]     = l0;
        g_m[rowbase + r0 + 8] = m1;
        g_l[rowbase + r0 + 8] = l1;
    }
}

// ---------------- pass 2: p = exp(s-m)/l in place + out = p @ V ----------------
#define P2_SMEM 196608
__global__ void __launch_bounds__(256,1) attn_pass2(float* __restrict__ d_out) {
    extern __shared__ unsigned char sm[];
    uint32_t sb = smem_u32(sm);
    uint32_t p_s = sb, v_s = sb + 65536;

    int tid = threadIdx.x, w = tid >> 5, l = tid & 31;
    int b = blockIdx.y, rb = blockIdx.x;
    float* attn = d_out + (size_t)Bn*Sn*DKn;
    int wm = w & 1, wn = w >> 1;

    float mml[8], lli[8];
    int rlow = tid >> 4;
    #pragma unroll
    for (int pass = 0; pass < 8; pass++) {
        size_t rg = (size_t)b*Sn + rb*128 + 16*pass + rlow;
        mml[pass] = g_m[rg];
        lli[pass] = 1.0f / g_l[rg];
    }

    {
        size_t vt = (size_t)(b*32)*32768;
        #pragma unroll
        for (int sp = 0; sp < 2; sp++) {
            const unsigned char* src = g_Vt + (size_t)sp*SPLIT_SZ + vt;
            for (int i = tid; i < 2048; i += 256) cp16(v_s + sp*32768 + i*16, src + (size_t)i*16);
        }
        CP_COMMIT();
    }

    float out[4][4][4];
    #pragma unroll
    for (int mt = 0; mt < 4; mt++)
        #pragma unroll
        for (int nt = 0; nt < 4; nt++)
            #pragma unroll
            for (int c = 0; c < 4; c++) out[mt][nt][c] = 0.f;

    const int pa2[3] = {0,0,1};
    const int pb2[3] = {0,1,0};

    for (int j = 0; j < 32; j++) {
        __syncthreads();

        #pragma unroll
        for (int pass = 0; pass < 8; pass++) {
            int i = pass*2048 + tid*8;
            int row = i >> 7, col = i & 127;
            float* src = attn + ((size_t)b*Sn + rb*128 + row)*Sn + (size_t)j*128 + col;
            float p8[8];
            *(float4*)(p8)   = *(const float4*)(src);
            *(float4*)(p8+4) = *(const float4*)(src + 4);
            #pragma unroll
            for (int x = 0; x < 8; x++) p8[x] = __expf(p8[x] - mml[pass]) * lli[pass];
            *(float4*)(src)     = *(float4*)(p8);
            *(float4*)(src + 4) = *(float4*)(p8+4);
            uint4 uh, ul;
            split2x8(p8, uh, ul);
            uint32_t a = p_s + (uint32_t)row*256 + swz16((uint32_t)row, (uint32_t)(col >> 3));
            STS16(a, uh);
            STS16(a + 32768, ul);
        }

        if (j + 1 < 32) {
            size_t vt = (size_t)(b*32 + j + 1)*32768;
            uint32_t dst = v_s + (uint32_t)(((j+1) & 1) * 65536);
            #pragma unroll
            for (int sp = 0; sp < 2; sp++) {
                const unsigned char* src = g_Vt + (size_t)sp*SPLIT_SZ + vt;
                for (int i = tid; i < 2048; i += 256) cp16(dst + sp*32768 + i*16, src + (size_t)i*16);
            }
            CP_COMMIT();
            CP_WAIT(1);
        } else {
            CP_WAIT(0);
        }
        __syncthreads();

        uint32_t vb = v_s + (uint32_t)((j & 1) * 65536);
        #pragma unroll
        for (int pr = 0; pr < 3; pr++) {
            uint32_t abase = p_s + (uint32_t)(pa2[pr] * 32768);
            uint32_t bbase = vb  + (uint32_t)(pb2[pr] * 32768);
            #pragma unroll
            for (int kc = 0; kc < 8; kc++) {
                uint32_t afr[4][4], bfr[4][2];
                #pragma unroll
                for (int mt = 0; mt < 4; mt++) {
                    uint32_t r = 64*wm + 16*mt + (l & 7) + ((l >> 3) & 1)*8;
                    uint32_t g = kc*2 + (l >> 4);
                    ldm_x4(afr[mt], abase + r*256 + swz16(r, g));
                }
                #pragma unroll
                for (int nt = 0; nt < 4; nt++) {
                    uint32_t n = 32*wn + 8*nt + (l & 7);
                    uint32_t g = kc*2 + ((l >> 3) & 1);
                    ldm_x2(bfr[nt], bbase + n*256 + swz16(n, g));
                }
                #pragma unroll
                for (int mt = 0; mt < 4; mt++)
                    #pragma unroll
                    for (int nt = 0; nt < 4; nt++)
                        mma16816(out[mt][nt], afr[mt], bfr[nt]);
            }
        }
    }

    #pragma unroll
    for (int mt = 0; mt < 4; mt++)
        #pragma unroll
        for (int dl = 0; dl < 2; dl++) {
            int row = 64*wm + 16*mt + (l >> 2) + 8*dl;
            float* o = d_out + ((size_t)b*Sn + rb*128 + row)*DKn + 32*wn + 2*(l & 3);
            #pragma unroll
            for (int nt = 0; nt < 4; nt++)
                *(float2*)(o + 8*nt) = make_float2(out[mt][nt][2*dl], out[mt][nt][2*dl+1]);
        }
}

// ---------------- launcher ----------------
extern "C" void kernel_launch(void* const* d_in, const int* in_sizes, int n_in,
                              void* d_out, int out_size) {
    const float* x  = (const float*)d_in[0];
    const float* tp = (const float*)d_in[1];
    const float* Wq = (const float*)d_in[2];
    const float* bq = (const float*)d_in[3];
    const float* Wk = (const float*)d_in[4];
    const float* bk = (const float*)d_in[5];
    const float* Wv = (const float*)d_in[6];
    const float* bv = (const float*)d_in[7];
    const float* Wt = (const float*)d_in[8];
    const float* bt = (const float*)d_in[9];
    float* out = (float*)d_out;

    unsigned char *pxs, *pWs, *pQs, *pKs, *pQTs, *pVt;
    cudaGetSymbolAddress((void**)&pxs,  g_xs);
    cudaGetSymbolAddress((void**)&pWs,  g_Ws);
    cudaGetSymbolAddress((void**)&pQs,  g_Qs);
    cudaGetSymbolAddress((void**)&pKs,  g_Ks);
    cudaGetSymbolAddress((void**)&pQTs, g_QTs);
    cudaGetSymbolAddress((void**)&pVt,  g_Vt);

    cudaFuncSetAttribute((const void*)proj_tc<6,1>, cudaFuncAttributeMaxDynamicSharedMemorySize, PROJ_SMEM);
    cudaFuncSetAttribute((const void*)proj_tc<3,2>, cudaFuncAttributeMaxDynamicSharedMemorySize, PROJ_SMEM);
    cudaFuncSetAttribute((const void*)qt_tc,        cudaFuncAttributeMaxDynamicSharedMemorySize, QT_SMEM);
    cudaFuncSetAttribute((const void*)attn_pass1,   cudaFuncAttributeMaxDynamicSharedMemorySize, P1_SMEM);
    cudaFuncSetAttribute((const void*)attn_pass2,   cudaFuncAttributeMaxDynamicSharedMemorySize, P2_SMEM);

    prep_T_kernel<<<Bn, 256>>>(tp, Wt, bt);
    split_x_kernel<<<8192, 256>>>(x);
    split_W_kernel<<<dim3(16, 3), 256>>>(Wq, Wk, Wv);

    // Q: A = x blobs (per tile), B = Wq^T blobs (fixed)
    proj_tc<6,1><<<128, 256, PROJ_SMEM>>>(pxs, XS_SPLIT, 16,
                                          pWs, WS_SPLIT, 0, bq, pQs, SPLIT_SZ);
    // K
    proj_tc<6,1><<<128, 256, PROJ_SMEM>>>(pxs, XS_SPLIT, 16,
                                          pWs + 16*16384, WS_SPLIT, 0, bk, pKs, SPLIT_SZ);
    // V^T: A = Wv^T (fixed), B = x blobs (per tile)
    proj_tc<3,2><<<128, 256, PROJ_SMEM>>>(pWs + 32*16384, WS_SPLIT, 0,
                                          pxs, XS_SPLIT, 16, bv, pVt, SPLIT_SZ);
    // QT = Qs @ Ts (scale folded into T)
    qt_tc<<<dim3(32, Bn), 256, QT_SMEM>>>();

    attn_pass1<<<dim3(32, Bn), 256, P1_SMEM>>>(out);
    attn_pass2<<<dim3(32, Bn), 256, P2_SMEM>>>(out);
}

// round 6
// speedup vs baseline: 2.7224x; 1.2821x over previous
#include <cuda_runtime.h>
#include <cuda_fp16.h>
#include <math.h>
#include <stdint.h>

#define Bn 4
#define Sn 4096
#define Dn 1024
#define TPn 16
#define TEn 64
#define DKn 128
#define NTILE 128
#define SPLIT_SZ (NTILE*32768ULL)       // 256B-row blob images (Q/K/QT/Vt)
#define XS_SPLIT (NTILE*16*16384ULL)    // x split images: 2048 blobs of 16KB
#define WS_SPLIT (3*16*16384ULL)        // W^T split images: 3 mats x 16 chunks
#define TS_SPLIT (Bn*32768ULL)
#define SCALE 0.08838834764831845f

// ---------------- scratch (2-way fp16 splits) ----------------
__device__ float g_m[Bn*Sn];
__device__ float g_l[Bn*Sn];
__device__ __align__(16) unsigned char g_xs [2*XS_SPLIT];
__device__ __align__(16) unsigned char g_Ws [2*WS_SPLIT];
__device__ __align__(16) unsigned char g_Ts [2*TS_SPLIT];
__device__ __align__(16) unsigned char g_Qs [2*SPLIT_SZ];
__device__ __align__(16) unsigned char g_Ks [2*SPLIT_SZ];
__device__ __align__(16) unsigned char g_QTs[2*SPLIT_SZ];
__device__ __align__(16) unsigned char g_Vt [2*SPLIT_SZ];

// ---------------- helpers ----------------
__device__ __forceinline__ uint32_t smem_u32(const void* p){
    uint32_t a;
    asm("{ .reg .u64 t; cvta.to.shared.u64 t, %1; cvt.u32.u64 %0, t; }" : "=r"(a) : "l"(p));
    return a;
}
__device__ __forceinline__ uint32_t swz16(uint32_t r, uint32_t g){
    return ((g & 8u) | ((g ^ r) & 7u)) << 4;       // 256B rows, 16 groups
}
__device__ __forceinline__ uint32_t swz8(uint32_t r, uint32_t g){
    return ((g ^ r) & 7u) << 4;                    // 128B rows, 8 groups
}
__device__ __forceinline__ void cp16(uint32_t dst, const void* src){
    asm volatile("cp.async.cg.shared.global [%0], [%1], 16;" :: "r"(dst), "l"(src) : "memory");
}
#define CP_COMMIT() asm volatile("cp.async.commit_group;" ::: "memory")
#define CP_WAIT(n)  asm volatile("cp.async.wait_group %0;" :: "n"(n) : "memory")
#define STS16(addr, v) asm volatile("st.shared.v4.b32 [%0], {%1,%2,%3,%4};" \
    :: "r"(addr), "r"((v).x), "r"((v).y), "r"((v).z), "r"((v).w) : "memory")

__device__ __forceinline__ void ldm_x4(uint32_t* r, uint32_t addr){
    asm volatile("ldmatrix.sync.aligned.m8n8.x4.shared.b16 {%0,%1,%2,%3}, [%4];"
        : "=r"(r[0]), "=r"(r[1]), "=r"(r[2]), "=r"(r[3]) : "r"(addr));
}
__device__ __forceinline__ void ldm_x2(uint32_t* r, uint32_t addr){
    asm volatile("ldmatrix.sync.aligned.m8n8.x2.shared.b16 {%0,%1}, [%2];"
        : "=r"(r[0]), "=r"(r[1]) : "r"(addr));
}
__device__ __forceinline__ void mma16816(float* d, const uint32_t* a, const uint32_t* b){
    asm volatile("mma.sync.aligned.m16n8k16.row.col.f32.f16.f16.f32 "
        "{%0,%1,%2,%3}, {%4,%5,%6,%7}, {%8,%9}, {%0,%1,%2,%3};"
        : "+f"(d[0]), "+f"(d[1]), "+f"(d[2]), "+f"(d[3])
        : "r"(a[0]), "r"(a[1]), "r"(a[2]), "r"(a[3]), "r"(b[0]), "r"(b[1]));
}
__device__ __forceinline__ uint32_t pk(unsigned short a, unsigned short b){
    return (uint32_t)a | ((uint32_t)b << 16);
}
// 2-way fp16 split of 8 floats
__device__ __forceinline__ void split2h8(const float* v, uint4& uh, uint4& ul){
    unsigned short h[8], l[8];
    #pragma unroll
    for (int j = 0; j < 8; j++){
        __half hh = __float2half_rn(v[j]);
        __half hl = __float2half_rn(v[j] - __half2float(hh));
        h[j] = __half_as_ushort(hh); l[j] = __half_as_ushort(hl);
    }
    uh = make_uint4(pk(h[0],h[1]), pk(h[2],h[3]), pk(h[4],h[5]), pk(h[6],h[7]));
    ul = make_uint4(pk(l[0],l[1]), pk(l[2],l[3]), pk(l[4],l[5]), pk(l[6],l[7]));
}

// ---------------- kernel 1: T_scaled (x SCALE) -> 2-split fp16 blobs ----------------
__global__ void prep_T_kernel(const float* __restrict__ tp,
                              const float* __restrict__ Wt,
                              const float* __restrict__ bt) {
    __shared__ float sTP[TPn*TEn];
    __shared__ float sWt[TEn*DKn];
    __shared__ float sE [TPn*DKn];
    __shared__ float red[256];
    int b = blockIdx.x, tid = threadIdx.x;
    for (int i = tid; i < TPn*TEn; i += 256) sTP[i] = tp[b*TPn*TEn + i];
    for (int i = tid; i < TEn*DKn; i += 256) sWt[i] = Wt[i];
    __syncthreads();
    for (int i = tid; i < TPn*DKn; i += 256) {
        int t = i >> 7, d = i & 127;
        float acc = bt[d];
        #pragma unroll 8
        for (int e = 0; e < TEn; e++) acc += sTP[t*TEn + e] * sWt[e*DKn + d];
        sE[i] = acc;
    }
    __syncthreads();
    float ss = 0.f;
    for (int i = tid; i < TPn*DKn; i += 256) ss += sE[i]*sE[i];
    red[tid] = ss; __syncthreads();
    for (int off = 128; off > 0; off >>= 1) {
        if (tid < off) red[tid] += red[tid+off];
        __syncthreads();
    }
    float tn = sqrtf((float)Sn * red[0]);
    float sc = (float)Sn / (tn + 1e-8f) * SCALE;
    for (int i = tid; i < DKn*DKn; i += 256) {
        int d = i >> 7, e2 = i & 127;
        float acc = 0.f;
        #pragma unroll
        for (int t = 0; t < TPn; t++) acc += sE[t*DKn + d] * sE[t*DKn + e2];
        float v = acc * sc;
        __half hh = __float2half_rn(v);
        __half hl = __float2half_rn(v - __half2float(hh));
        size_t base = (size_t)b*32768 + (size_t)d*256 + swz16((uint32_t)d, (uint32_t)(e2 >> 3)) + (size_t)(e2 & 7)*2;
        *(__half*)(g_Ts + base)            = hh;
        *(__half*)(g_Ts + TS_SPLIT + base) = hl;
    }
}

// ---------------- kernel 2: split x -> 2-split fp16 blobs ----------------
__global__ void split_x_kernel(const float* __restrict__ x) {
    int gidx = blockIdx.x*256 + threadIdx.x;
    int rt = gidx >> 7, gk = gidx & 127;
    int kc = gk >> 3, g = gk & 7;
    const float* src = x + (size_t)rt*Dn + kc*64 + g*8;
    float v[8];
    *(float4*)(v)   = *(const float4*)(src);
    *(float4*)(v+4) = *(const float4*)(src + 4);
    uint4 uh, ul;
    split2h8(v, uh, ul);
    int tile = rt >> 7, r = rt & 127;
    size_t off = (size_t)(tile*16 + kc)*16384 + (size_t)r*128 + swz8((uint32_t)r, (uint32_t)g);
    *(uint4*)(g_xs + off)            = uh;
    *(uint4*)(g_xs + XS_SPLIT + off) = ul;
}

// ---------------- kernel 3: split W^T -> 2-split fp16 blobs ----------------
__global__ void split_W_kernel(const float* __restrict__ Wq,
                               const float* __restrict__ Wk,
                               const float* __restrict__ Wv) {
    __shared__ float sW[64*128];
    int kc = blockIdx.x, mat = blockIdx.y, tid = threadIdx.x;
    const float* W = (mat == 0) ? Wq : ((mat == 1) ? Wk : Wv);
    for (int i = tid; i < 2048; i += 256)
        ((float4*)sW)[i] = ((const float4*)(W + (size_t)kc*64*128))[i];
    __syncthreads();
    for (int it = 0; it < 4; it++) {
        int gi = tid + it*256;
        int d = gi >> 3, g = gi & 7;
        float v[8];
        #pragma unroll
        for (int j = 0; j < 8; j++) v[j] = sW[(g*8 + j)*128 + d];
        uint4 uh, ul;
        split2h8(v, uh, ul);
        size_t off = (size_t)(mat*16 + kc)*16384 + (size_t)d*128 + swz8((uint32_t)d, (uint32_t)g);
        *(uint4*)(g_Ws + off)            = uh;
        *(uint4*)(g_Ws + WS_SPLIT + off) = ul;
    }
}

// ---------------- kernel 4: TC projection GEMM (K=1024, 16 chunks of 64) ----------------
// MODE 1: rows=tokens, 2-split blob + bias[col]. MODE 2: rows=dk, 2-split V^T + bias[row].
#define PROJ_SMEM (2*65536)
template<int MODE>
__global__ void __launch_bounds__(256,1)
proj_tc(const unsigned char* __restrict__ Ab, size_t Asplit, int aStride,
        const unsigned char* __restrict__ Bb, size_t Bsplit, int bStride,
        const float* __restrict__ bias, unsigned char* __restrict__ Out,
        size_t OutSplit) {
    extern __shared__ unsigned char sm[];
    uint32_t sb = smem_u32(sm);
    int tid = threadIdx.x, w = tid >> 5, l = tid & 31;
    int tile = blockIdx.x;
    int aB0 = tile * aStride, bB0 = tile * bStride;
    const int pa[3] = {0,0,1};
    const int pb[3] = {0,1,0};

    float acc[16][4];
    #pragma unroll
    for (int nt = 0; nt < 16; nt++)
        #pragma unroll
        for (int c = 0; c < 4; c++) acc[nt][c] = 0.f;

    uint32_t stg[2] = {sb, sb + 65536};
    #pragma unroll
    for (int sp = 0; sp < 2; sp++) {
        const unsigned char* sa = Ab + (size_t)sp*Asplit + (size_t)(aB0 + 0)*16384;
        const unsigned char* sv = Bb + (size_t)sp*Bsplit + (size_t)(bB0 + 0)*16384;
        for (int i = tid; i < 1024; i += 256) {
            cp16(stg[0] + sp*16384 + i*16, sa + (size_t)i*16);
            cp16(stg[0] + 32768 + sp*16384 + i*16, sv + (size_t)i*16);
        }
    }
    CP_COMMIT();

    for (int kc = 0; kc < 16; kc++) {
        __syncthreads();
        if (kc + 1 < 16) {
            uint32_t dst = stg[(kc+1) & 1];
            #pragma unroll
            for (int sp = 0; sp < 2; sp++) {
                const unsigned char* sa = Ab + (size_t)sp*Asplit + (size_t)(aB0 + kc + 1)*16384;
                const unsigned char* sv = Bb + (size_t)sp*Bsplit + (size_t)(bB0 + kc + 1)*16384;
                for (int i = tid; i < 1024; i += 256) {
                    cp16(dst + sp*16384 + i*16, sa + (size_t)i*16);
                    cp16(dst + 32768 + sp*16384 + i*16, sv + (size_t)i*16);
                }
            }
            CP_COMMIT();
            CP_WAIT(1);
        } else {
            CP_WAIT(0);
        }
        __syncthreads();

        uint32_t a0 = stg[kc & 1], b0 = stg[kc & 1] + 32768;
        #pragma unroll
        for (int pr = 0; pr < 3; pr++) {
            uint32_t abase = a0 + (uint32_t)pa[pr]*16384;
            uint32_t bbase = b0 + (uint32_t)pb[pr]*16384;
            #pragma unroll
            for (int ks = 0; ks < 4; ks++) {
                uint32_t afr[4], bfr[32];
                {
                    uint32_t r = 16*w + (l & 7) + 8*((l >> 3) & 1);
                    uint32_t g = ks*2 + (l >> 4);
                    ldm_x4(afr, abase + r*128 + swz8(r, g));
                }
                #pragma unroll
                for (int p = 0; p < 8; p++) {
                    uint32_t n = 16*p + 8*((l >> 4) & 1) + (l & 7);
                    uint32_t g = ks*2 + ((l >> 3) & 1);
                    ldm_x4(bfr + 4*p, bbase + n*128 + swz8(n, g));
                }
                #pragma unroll
                for (int nt = 0; nt < 16; nt++)
                    mma16816(acc[nt], afr, &bfr[2*nt]);
            }
        }
    }

    __syncthreads();
    float* sOut = (float*)sm;
    #pragma unroll
    for (int nt = 0; nt < 16; nt++) {
        int colb = 8*nt + 2*(l & 3);
        int r0 = 16*w + (l >> 2);
        sOut[r0*132 + colb]       = acc[nt][0];
        sOut[r0*132 + colb + 1]   = acc[nt][1];
        sOut[(r0+8)*132 + colb]   = acc[nt][2];
        sOut[(r0+8)*132 + colb+1] = acc[nt][3];
    }
    __syncthreads();
    int tr = tid >> 4, tc = tid & 15;
    if (MODE == 1) {
        float bv[8];
        *(float4*)(bv)   = *(const float4*)(bias + 8*tc);
        *(float4*)(bv+4) = *(const float4*)(bias + 8*tc + 4);
        #pragma unroll
        for (int i = 0; i < 8; i++) {
            int row = 8*tr + i;
            float v[8];
            #pragma unroll
            for (int j = 0; j < 8; j++) v[j] = sOut[row*132 + 8*tc + j] + bv[j];
            uint4 uh, ul;
            split2h8(v, uh, ul);
            size_t base = (size_t)tile*32768 + (size_t)row*256 + swz16((uint32_t)row, (uint32_t)tc);
            *(uint4*)(Out + base)            = uh;
            *(uint4*)(Out + OutSplit + base) = ul;
        }
    } else {
        #pragma unroll
        for (int i = 0; i < 8; i++) {
            int d = 8*tr + i;
            float bd = bias[d];
            float v[8];
            #pragma unroll
            for (int j = 0; j < 8; j++) v[j] = sOut[d*132 + 8*tc + j] + bd;
            uint4 uh, ul;
            split2h8(v, uh, ul);
            size_t base = (size_t)tile*32768 + (size_t)d*256 + swz16((uint32_t)d, (uint32_t)tc);
            *(uint4*)(Out + base)            = uh;
            *(uint4*)(Out + OutSplit + base) = ul;
        }
    }
}

// ---------------- kernel 5: QT = Qs @ Ts (K=128, 3 products) ----------------
#define QT_SMEM (2*65536)
__global__ void __launch_bounds__(256,1) qt_tc() {
    extern __shared__ unsigned char sm[];
    uint32_t sb = smem_u32(sm);
    int tid = threadIdx.x, w = tid >> 5, l = tid & 31;
    int b = blockIdx.y, rb = blockIdx.x, tile = b*32 + rb;
    const int pa[3] = {0,0,1};
    const int pb[3] = {0,1,0};

    #pragma unroll
    for (int sp = 0; sp < 2; sp++) {
        const unsigned char* sa = g_Qs + (size_t)sp*SPLIT_SZ + (size_t)tile*32768;
        const unsigned char* st = g_Ts + (size_t)sp*TS_SPLIT + (size_t)b*32768;
        for (int i = tid; i < 2048; i += 256) {
            cp16(sb + sp*32768 + i*16, sa + (size_t)i*16);
            cp16(sb + 65536 + sp*32768 + i*16, st + (size_t)i*16);
        }
    }
    CP_COMMIT();
    CP_WAIT(0);
    __syncthreads();

    float acc[16][4];
    #pragma unroll
    for (int nt = 0; nt < 16; nt++)
        #pragma unroll
        for (int c = 0; c < 4; c++) acc[nt][c] = 0.f;

    #pragma unroll
    for (int pr = 0; pr < 3; pr++) {
        uint32_t abase = sb + (uint32_t)pa[pr]*32768;
        uint32_t bbase = sb + 65536 + (uint32_t)pb[pr]*32768;
        #pragma unroll
        for (int ks = 0; ks < 8; ks++) {
            uint32_t afr[4], bfr[32];
            {
                uint32_t r = 16*w + (l & 7) + 8*((l >> 3) & 1);
                uint32_t g = ks*2 + (l >> 4);
                ldm_x4(afr, abase + r*256 + swz16(r, g));
            }
            #pragma unroll
            for (int p = 0; p < 8; p++) {
                uint32_t n = 16*p + 8*((l >> 4) & 1) + (l & 7);
                uint32_t g = ks*2 + ((l >> 3) & 1);
                ldm_x4(bfr + 4*p, bbase + n*256 + swz16(n, g));
            }
            #pragma unroll
            for (int nt = 0; nt < 16; nt++)
                mma16816(acc[nt], afr, &bfr[2*nt]);
        }
    }

    __syncthreads();
    float* sOut = (float*)sm;
    #pragma unroll
    for (int nt = 0; nt < 16; nt++) {
        int colb = 8*nt + 2*(l & 3);
        int r0 = 16*w + (l >> 2);
        sOut[r0*132 + colb]       = acc[nt][0];
        sOut[r0*132 + colb + 1]   = acc[nt][1];
        sOut[(r0+8)*132 + colb]   = acc[nt][2];
        sOut[(r0+8)*132 + colb+1] = acc[nt][3];
    }
    __syncthreads();
    int tr = tid >> 4, tc = tid & 15;
    #pragma unroll
    for (int i = 0; i < 8; i++) {
        int row = 8*tr + i;
        float v[8];
        #pragma unroll
        for (int j = 0; j < 8; j++) v[j] = sOut[row*132 + 8*tc + j];
        uint4 uh, ul;
        split2h8(v, uh, ul);
        size_t base = (size_t)tile*32768 + (size_t)row*256 + swz16((uint32_t)row, (uint32_t)tc);
        *(uint4*)(g_QTs + base)            = uh;
        *(uint4*)(g_QTs + SPLIT_SZ + base) = ul;
    }
}

// ---------------- pass 1: scores, raw dump, warp-private m/l ----------------
#define P1_SMEM (65536 + 2*32768)
__global__ void __launch_bounds__(256,1) attn_pass1(float* __restrict__ d_out) {
    extern __shared__ unsigned char sm[];
    uint32_t sb = smem_u32(sm);
    uint32_t qt_s = sb, k_s = sb + 65536;

    int tid = threadIdx.x, w = tid >> 5, l = tid & 31;
    int b = blockIdx.y, rb = blockIdx.x;
    float* attn = d_out + (size_t)Bn*Sn*DKn;
    size_t rowbase = (size_t)b*Sn + (size_t)rb*128;

    size_t qtile = (size_t)(b*32 + rb)*32768;
    #pragma unroll
    for (int sp = 0; sp < 2; sp++) {
        const unsigned char* src = g_QTs + (size_t)sp*SPLIT_SZ + qtile;
        for (int i = tid; i < 2048; i += 256) cp16(qt_s + sp*32768 + i*16, src + (size_t)i*16);
    }
    {
        size_t kt = (size_t)(b*32)*32768;
        #pragma unroll
        for (int sp = 0; sp < 2; sp++) {
            const unsigned char* src = g_Ks + (size_t)sp*SPLIT_SZ + kt;
            for (int i = tid; i < 1024; i += 256) cp16(k_s + sp*16384 + i*16, src + (size_t)i*16);
        }
    }
    CP_COMMIT();

    const int pa[3] = {0,0,1};
    const int pb[3] = {0,1,0};
    int r0 = 16*w + (l >> 2);
    float m0 = -1e30f, l0 = 0.f, m1 = -1e30f, l1 = 0.f;

    for (int jj = 0; jj < 64; jj++) {
        __syncthreads();
        if (jj + 1 < 64) {
            int jt = (jj+1) >> 1, hf = (jj+1) & 1;
            size_t kt = (size_t)(b*32 + jt)*32768 + (size_t)hf*16384;
            uint32_t dst = k_s + (uint32_t)(((jj+1) & 1) * 32768);
            #pragma unroll
            for (int sp = 0; sp < 2; sp++) {
                const unsigned char* src = g_Ks + (size_t)sp*SPLIT_SZ + kt;
                for (int i = tid; i < 1024; i += 256) cp16(dst + sp*16384 + i*16, src + (size_t)i*16);
            }
            CP_COMMIT();
            CP_WAIT(1);
        } else {
            CP_WAIT(0);
        }
        __syncthreads();

        uint32_t kbase = k_s + (uint32_t)((jj & 1) * 32768);
        float acc[8][4];
        #pragma unroll
        for (int nt = 0; nt < 8; nt++)
            #pragma unroll
            for (int c = 0; c < 4; c++) acc[nt][c] = 0.f;

        #pragma unroll
        for (int pr = 0; pr < 3; pr++) {
            uint32_t abase = qt_s + (uint32_t)pa[pr]*32768;
            uint32_t bbase = kbase + (uint32_t)pb[pr]*16384;
            #pragma unroll
            for (int kc = 0; kc < 8; kc++) {
                uint32_t afr[4], bfr[16];
                {
                    uint32_t r = 16*w + (l & 7) + 8*((l >> 3) & 1);
                    uint32_t g = kc*2 + (l >> 4);
                    ldm_x4(afr, abase + r*256 + swz16(r, g));
                }
                #pragma unroll
                for (int p = 0; p < 4; p++) {
                    uint32_t n = 16*p + 8*((l >> 4) & 1) + (l & 7);
                    uint32_t g = kc*2 + ((l >> 3) & 1);
                    ldm_x4(bfr + 4*p, bbase + n*256 + swz16(n, g));
                }
                #pragma unroll
                for (int nt = 0; nt < 8; nt++)
                    mma16816(acc[nt], afr, &bfr[2*nt]);
            }
        }

        float tm0 = -1e30f, tm1 = -1e30f;
        #pragma unroll
        for (int nt = 0; nt < 8; nt++) {
            tm0 = fmaxf(tm0, fmaxf(acc[nt][0], acc[nt][1]));
            tm1 = fmaxf(tm1, fmaxf(acc[nt][2], acc[nt][3]));
        }
        tm0 = fmaxf(tm0, __shfl_xor_sync(0xffffffffu, tm0, 1));
        tm0 = fmaxf(tm0, __shfl_xor_sync(0xffffffffu, tm0, 2));
        tm1 = fmaxf(tm1, __shfl_xor_sync(0xffffffffu, tm1, 1));
        tm1 = fmaxf(tm1, __shfl_xor_sync(0xffffffffu, tm1, 2));
        float mn0 = fmaxf(m0, tm0), mn1 = fmaxf(m1, tm1);
        float rs0 = 0.f, rs1 = 0.f;
        #pragma unroll
        for (int nt = 0; nt < 8; nt++) {
            rs0 += __expf(acc[nt][0] - mn0) + __expf(acc[nt][1] - mn0);
            rs1 += __expf(acc[nt][2] - mn1) + __expf(acc[nt][3] - mn1);
        }
        rs0 += __shfl_xor_sync(0xffffffffu, rs0, 1);
        rs0 += __shfl_xor_sync(0xffffffffu, rs0, 2);
        rs1 += __shfl_xor_sync(0xffffffffu, rs1, 1);
        rs1 += __shfl_xor_sync(0xffffffffu, rs1, 2);
        l0 = l0*__expf(m0 - mn0) + rs0; m0 = mn0;
        l1 = l1*__expf(m1 - mn1) + rs1; m1 = mn1;

        float* dst0 = attn + (rowbase + r0)*Sn + (size_t)jj*64 + 2*(l & 3);
        float* dst1 = attn + (rowbase + r0 + 8)*Sn + (size_t)jj*64 + 2*(l & 3);
        #pragma unroll
        for (int nt = 0; nt < 8; nt++) {
            *(float2*)(dst0 + 8*nt) = make_float2(acc[nt][0], acc[nt][1]);
            *(float2*)(dst1 + 8*nt) = make_float2(acc[nt][2], acc[nt][3]);
        }
    }

    if ((l & 3) == 0) {
        g_m[rowbase + r0]     = m0;
        g_l[rowbase + r0]     = l0;
        g_m[rowbase + r0 + 8] = m1;
        g_l[rowbase + r0 + 8] = l1;
    }
}

// ---------------- pass 2: p = exp(s-m)/l in place + out = p @ V ----------------
#define P2_SMEM (65536 + 2*65536)
__global__ void __launch_bounds__(256,1) attn_pass2(float* __restrict__ d_out) {
    extern __shared__ unsigned char sm[];
    uint32_t sb = smem_u32(sm);
    uint32_t p_s = sb, v_s = sb + 65536;

    int tid = threadIdx.x, w = tid >> 5, l = tid & 31;
    int b = blockIdx.y, rb = blockIdx.x;
    float* attn = d_out + (size_t)Bn*Sn*DKn;
    int wm = w & 1, wn = w >> 1;

    float mml[8], lli[8];
    int rlow = tid >> 4;
    #pragma unroll
    for (int pass = 0; pass < 8; pass++) {
        size_t rg = (size_t)b*Sn + rb*128 + 16*pass + rlow;
        mml[pass] = g_m[rg];
        lli[pass] = 1.0f / g_l[rg];
    }

    {
        size_t vt = (size_t)(b*32)*32768;
        #pragma unroll
        for (int sp = 0; sp < 2; sp++) {
            const unsigned char* src = g_Vt + (size_t)sp*SPLIT_SZ + vt;
            for (int i = tid; i < 2048; i += 256) cp16(v_s + sp*32768 + i*16, src + (size_t)i*16);
        }
        CP_COMMIT();
    }

    float out[4][4][4];
    #pragma unroll
    for (int mt = 0; mt < 4; mt++)
        #pragma unroll
        for (int nt = 0; nt < 4; nt++)
            #pragma unroll
            for (int c = 0; c < 4; c++) out[mt][nt][c] = 0.f;

    const int pa2[3] = {0,0,1};
    const int pb2[3] = {0,1,0};

    for (int j = 0; j < 32; j++) {
        __syncthreads();

        #pragma unroll
        for (int pass = 0; pass < 8; pass++) {
            int i = pass*2048 + tid*8;
            int row = i >> 7, col = i & 127;
            float* src = attn + ((size_t)b*Sn + rb*128 + row)*Sn + (size_t)j*128 + col;
            float p8[8];
            *(float4*)(p8)   = *(const float4*)(src);
            *(float4*)(p8+4) = *(const float4*)(src + 4);
            #pragma unroll
            for (int x = 0; x < 8; x++) p8[x] = __expf(p8[x] - mml[pass]) * lli[pass];
            *(float4*)(src)     = *(float4*)(p8);
            *(float4*)(src + 4) = *(float4*)(p8+4);
            uint4 uh, ul;
            split2h8(p8, uh, ul);
            uint32_t a = p_s + (uint32_t)row*256 + swz16((uint32_t)row, (uint32_t)(col >> 3));
            STS16(a, uh);
            STS16(a + 32768, ul);
        }

        if (j + 1 < 32) {
            size_t vt = (size_t)(b*32 + j + 1)*32768;
            uint32_t dst = v_s + (uint32_t)(((j+1) & 1) * 65536);
            #pragma unroll
            for (int sp = 0; sp < 2; sp++) {
                const unsigned char* src = g_Vt + (size_t)sp*SPLIT_SZ + vt;
                for (int i = tid; i < 2048; i += 256) cp16(dst + sp*32768 + i*16, src + (size_t)i*16);
            }
            CP_COMMIT();
            CP_WAIT(1);
        } else {
            CP_WAIT(0);
        }
        __syncthreads();

        uint32_t vb = v_s + (uint32_t)((j & 1) * 65536);
        #pragma unroll
        for (int pr = 0; pr < 3; pr++) {
            uint32_t abase = p_s + (uint32_t)(pa2[pr] * 32768);
            uint32_t bbase = vb  + (uint32_t)(pb2[pr] * 32768);
            #pragma unroll
            for (int kc = 0; kc < 8; kc++) {
                uint32_t afr[4][4], bfr[4][2];
                #pragma unroll
                for (int mt = 0; mt < 4; mt++) {
                    uint32_t r = 64*wm + 16*mt + (l & 7) + ((l >> 3) & 1)*8;
                    uint32_t g = kc*2 + (l >> 4);
                    ldm_x4(afr[mt], abase + r*256 + swz16(r, g));
                }
                #pragma unroll
                for (int nt = 0; nt < 4; nt++) {
                    uint32_t n = 32*wn + 8*nt + (l & 7);
                    uint32_t g = kc*2 + ((l >> 3) & 1);
                    ldm_x2(bfr[nt], bbase + n*256 + swz16(n, g));
                }
                #pragma unroll
                for (int mt = 0; mt < 4; mt++)
                    #pragma unroll
                    for (int nt = 0; nt < 4; nt++)
                        mma16816(out[mt][nt], afr[mt], bfr[nt]);
            }
        }
    }

    #pragma unroll
    for (int mt = 0; mt < 4; mt++)
        #pragma unroll
        for (int dl = 0; dl < 2; dl++) {
            int row = 64*wm + 16*mt + (l >> 2) + 8*dl;
            float* o = d_out + ((size_t)b*Sn + rb*128 + row)*DKn + 32*wn + 2*(l & 3);
            #pragma unroll
            for (int nt = 0; nt < 4; nt++)
                *(float2*)(o + 8*nt) = make_float2(out[mt][nt][2*dl], out[mt][nt][2*dl+1]);
        }
}

// ---------------- launcher ----------------
extern "C" void kernel_launch(void* const* d_in, const int* in_sizes, int n_in,
                              void* d_out, int out_size) {
    const float* x  = (const float*)d_in[0];
    const float* tp = (const float*)d_in[1];
    const float* Wq = (const float*)d_in[2];
    const float* bq = (const float*)d_in[3];
    const float* Wk = (const float*)d_in[4];
    const float* bk = (const float*)d_in[5];
    const float* Wv = (const float*)d_in[6];
    const float* bv = (const float*)d_in[7];
    const float* Wt = (const float*)d_in[8];
    const float* bt = (const float*)d_in[9];
    float* out = (float*)d_out;

    unsigned char *pxs, *pWs, *pQs, *pKs, *pVt;
    cudaGetSymbolAddress((void**)&pxs,  g_xs);
    cudaGetSymbolAddress((void**)&pWs,  g_Ws);
    cudaGetSymbolAddress((void**)&pQs,  g_Qs);
    cudaGetSymbolAddress((void**)&pKs,  g_Ks);
    cudaGetSymbolAddress((void**)&pVt,  g_Vt);

    cudaFuncSetAttribute((const void*)proj_tc<1>, cudaFuncAttributeMaxDynamicSharedMemorySize, PROJ_SMEM);
    cudaFuncSetAttribute((const void*)proj_tc<2>, cudaFuncAttributeMaxDynamicSharedMemorySize, PROJ_SMEM);
    cudaFuncSetAttribute((const void*)qt_tc,      cudaFuncAttributeMaxDynamicSharedMemorySize, QT_SMEM);
    cudaFuncSetAttribute((const void*)attn_pass1, cudaFuncAttributeMaxDynamicSharedMemorySize, P1_SMEM);
    cudaFuncSetAttribute((const void*)attn_pass2, cudaFuncAttributeMaxDynamicSharedMemorySize, P2_SMEM);

    prep_T_kernel<<<Bn, 256>>>(tp, Wt, bt);
    split_x_kernel<<<8192, 256>>>(x);
    split_W_kernel<<<dim3(16, 3), 256>>>(Wq, Wk, Wv);

    proj_tc<1><<<128, 256, PROJ_SMEM>>>(pxs, XS_SPLIT, 16,
                                        pWs, WS_SPLIT, 0, bq, pQs, SPLIT_SZ);
    proj_tc<1><<<128, 256, PROJ_SMEM>>>(pxs, XS_SPLIT, 16,
                                        pWs + 16*16384, WS_SPLIT, 0, bk, pKs, SPLIT_SZ);
    proj_tc<2><<<128, 256, PROJ_SMEM>>>(pWs + 32*16384, WS_SPLIT, 0,
                                        pxs, XS_SPLIT, 16, bv, pVt, SPLIT_SZ);
    qt_tc<<<dim3(32, Bn), 256, QT_SMEM>>>();

    attn_pass1<<<dim3(32, Bn), 256, P1_SMEM>>>(out);
    attn_pass2<<<dim3(32, Bn), 256, P2_SMEM>>>(out);
}

// round 7
// speedup vs baseline: 3.1800x; 1.1681x over previous
#include <cuda_runtime.h>
#include <cuda_fp16.h>
#include <math.h>
#include <stdint.h>

#define Bn 4
#define Sn 4096
#define Dn 1024
#define TPn 16
#define TEn 64
#define DKn 128
#define NTILE 128
#define SPLIT_SZ (NTILE*32768ULL)
#define XS_SPLIT (NTILE*16*16384ULL)
#define WS_SPLIT (3*16*16384ULL)
#define TS_SPLIT (Bn*32768ULL)
#define SCALE 0.08838834764831845f

// ---------------- scratch (2-way fp16 splits) ----------------
__device__ float g_m[Bn*Sn];
__device__ float g_l[Bn*Sn];
__device__ __align__(16) unsigned char g_xs [2*XS_SPLIT];
__device__ __align__(16) unsigned char g_Ws [2*WS_SPLIT];
__device__ __align__(16) unsigned char g_Ts [2*TS_SPLIT];
__device__ __align__(16) unsigned char g_Qs [2*SPLIT_SZ];
__device__ __align__(16) unsigned char g_Ks [2*SPLIT_SZ];
__device__ __align__(16) unsigned char g_QTs[2*SPLIT_SZ];
__device__ __align__(16) unsigned char g_Vt [2*SPLIT_SZ];

// ---------------- helpers ----------------
__device__ __forceinline__ uint32_t smem_u32(const void* p){
    uint32_t a;
    asm("{ .reg .u64 t; cvta.to.shared.u64 t, %1; cvt.u32.u64 %0, t; }" : "=r"(a) : "l"(p));
    return a;
}
__device__ __forceinline__ uint32_t swz16(uint32_t r, uint32_t g){
    return ((g & 8u) | ((g ^ r) & 7u)) << 4;
}
__device__ __forceinline__ uint32_t swz8(uint32_t r, uint32_t g){
    return ((g ^ r) & 7u) << 4;
}
__device__ __forceinline__ void cp16(uint32_t dst, const void* src){
    asm volatile("cp.async.cg.shared.global [%0], [%1], 16;" :: "r"(dst), "l"(src) : "memory");
}
#define CP_COMMIT() asm volatile("cp.async.commit_group;" ::: "memory")
#define CP_WAIT(n)  asm volatile("cp.async.wait_group %0;" :: "n"(n) : "memory")
#define STS16(addr, v) asm volatile("st.shared.v4.b32 [%0], {%1,%2,%3,%4};" \
    :: "r"(addr), "r"((v).x), "r"((v).y), "r"((v).z), "r"((v).w) : "memory")

__device__ __forceinline__ void ldm_x4(uint32_t* r, uint32_t addr){
    asm volatile("ldmatrix.sync.aligned.m8n8.x4.shared.b16 {%0,%1,%2,%3}, [%4];"
        : "=r"(r[0]), "=r"(r[1]), "=r"(r[2]), "=r"(r[3]) : "r"(addr));
}
__device__ __forceinline__ void mma16816(float* d, const uint32_t* a, const uint32_t* b){
    asm volatile("mma.sync.aligned.m16n8k16.row.col.f32.f16.f16.f32 "
        "{%0,%1,%2,%3}, {%4,%5,%6,%7}, {%8,%9}, {%0,%1,%2,%3};"
        : "+f"(d[0]), "+f"(d[1]), "+f"(d[2]), "+f"(d[3])
        : "r"(a[0]), "r"(a[1]), "r"(a[2]), "r"(a[3]), "r"(b[0]), "r"(b[1]));
}
__device__ __forceinline__ uint32_t pk(unsigned short a, unsigned short b){
    return (uint32_t)a | ((uint32_t)b << 16);
}
__device__ __forceinline__ void split2h8(const float* v, uint4& uh, uint4& ul){
    unsigned short h[8], l[8];
    #pragma unroll
    for (int j = 0; j < 8; j++){
        __half hh = __float2half_rn(v[j]);
        __half hl = __float2half_rn(v[j] - __half2float(hh));
        h[j] = __half_as_ushort(hh); l[j] = __half_as_ushort(hl);
    }
    uh = make_uint4(pk(h[0],h[1]), pk(h[2],h[3]), pk(h[4],h[5]), pk(h[6],h[7]));
    ul = make_uint4(pk(l[0],l[1]), pk(l[2],l[3]), pk(l[4],l[5]), pk(l[6],l[7]));
}

// ---------------- kernel 1: T_scaled (x SCALE) -> 2-split fp16 blobs ----------------
__global__ void prep_T_kernel(const float* __restrict__ tp,
                              const float* __restrict__ Wt,
                              const float* __restrict__ bt) {
    __shared__ float sTP[TPn*TEn];
    __shared__ float sWt[TEn*DKn];
    __shared__ float sE [TPn*DKn];
    __shared__ float red[256];
    int b = blockIdx.x, tid = threadIdx.x;
    for (int i = tid; i < TPn*TEn; i += 256) sTP[i] = tp[b*TPn*TEn + i];
    for (int i = tid; i < TEn*DKn; i += 256) sWt[i] = Wt[i];
    __syncthreads();
    for (int i = tid; i < TPn*DKn; i += 256) {
        int t = i >> 7, d = i & 127;
        float acc = bt[d];
        #pragma unroll 8
        for (int e = 0; e < TEn; e++) acc += sTP[t*TEn + e] * sWt[e*DKn + d];
        sE[i] = acc;
    }
    __syncthreads();
    float ss = 0.f;
    for (int i = tid; i < TPn*DKn; i += 256) ss += sE[i]*sE[i];
    red[tid] = ss; __syncthreads();
    for (int off = 128; off > 0; off >>= 1) {
        if (tid < off) red[tid] += red[tid+off];
        __syncthreads();
    }
    float tn = sqrtf((float)Sn * red[0]);
    float sc = (float)Sn / (tn + 1e-8f) * SCALE;
    for (int i = tid; i < DKn*DKn; i += 256) {
        int d = i >> 7, e2 = i & 127;
        float acc = 0.f;
        #pragma unroll
        for (int t = 0; t < TPn; t++) acc += sE[t*DKn + d] * sE[t*DKn + e2];
        float v = acc * sc;
        __half hh = __float2half_rn(v);
        __half hl = __float2half_rn(v - __half2float(hh));
        size_t base = (size_t)b*32768 + (size_t)d*256 + swz16((uint32_t)d, (uint32_t)(e2 >> 3)) + (size_t)(e2 & 7)*2;
        *(__half*)(g_Ts + base)            = hh;
        *(__half*)(g_Ts + TS_SPLIT + base) = hl;
    }
}

// ---------------- kernel 2: split x -> 2-split fp16 blobs ----------------
__global__ void split_x_kernel(const float* __restrict__ x) {
    int gidx = blockIdx.x*256 + threadIdx.x;
    int rt = gidx >> 7, gk = gidx & 127;
    int kc = gk >> 3, g = gk & 7;
    const float* src = x + (size_t)rt*Dn + kc*64 + g*8;
    float v[8];
    *(float4*)(v)   = *(const float4*)(src);
    *(float4*)(v+4) = *(const float4*)(src + 4);
    uint4 uh, ul;
    split2h8(v, uh, ul);
    int tile = rt >> 7, r = rt & 127;
    size_t off = (size_t)(tile*16 + kc)*16384 + (size_t)r*128 + swz8((uint32_t)r, (uint32_t)g);
    *(uint4*)(g_xs + off)            = uh;
    *(uint4*)(g_xs + XS_SPLIT + off) = ul;
}

// ---------------- kernel 3: split W^T -> 2-split fp16 blobs ----------------
__global__ void split_W_kernel(const float* __restrict__ Wq,
                               const float* __restrict__ Wk,
                               const float* __restrict__ Wv) {
    __shared__ float sW[64*128];
    int kc = blockIdx.x, mat = blockIdx.y, tid = threadIdx.x;
    const float* W = (mat == 0) ? Wq : ((mat == 1) ? Wk : Wv);
    for (int i = tid; i < 2048; i += 256)
        ((float4*)sW)[i] = ((const float4*)(W + (size_t)kc*64*128))[i];
    __syncthreads();
    for (int it = 0; it < 4; it++) {
        int gi = tid + it*256;
        int d = gi >> 3, g = gi & 7;
        float v[8];
        #pragma unroll
        for (int j = 0; j < 8; j++) v[j] = sW[(g*8 + j)*128 + d];
        uint4 uh, ul;
        split2h8(v, uh, ul);
        size_t off = (size_t)(mat*16 + kc)*16384 + (size_t)d*128 + swz8((uint32_t)d, (uint32_t)g);
        *(uint4*)(g_Ws + off)            = uh;
        *(uint4*)(g_Ws + WS_SPLIT + off) = ul;
    }
}

// ---------------- kernel 4: TC projection GEMM ----------------
#define PROJ_SMEM (2*65536)
template<int MODE>
__global__ void __launch_bounds__(256,1)
proj_tc(const unsigned char* __restrict__ Ab, size_t Asplit, int aStride,
        const unsigned char* __restrict__ Bb, size_t Bsplit, int bStride,
        const float* __restrict__ bias, unsigned char* __restrict__ Out,
        size_t OutSplit) {
    extern __shared__ unsigned char sm[];
    uint32_t sb = smem_u32(sm);
    int tid = threadIdx.x, w = tid >> 5, l = tid & 31;
    int tile = blockIdx.x;
    int aB0 = tile * aStride, bB0 = tile * bStride;
    const int pa[3] = {0,0,1};
    const int pb[3] = {0,1,0};

    float acc[16][4];
    #pragma unroll
    for (int nt = 0; nt < 16; nt++)
        #pragma unroll
        for (int c = 0; c < 4; c++) acc[nt][c] = 0.f;

    uint32_t stg[2] = {sb, sb + 65536};
    #pragma unroll
    for (int sp = 0; sp < 2; sp++) {
        const unsigned char* sa = Ab + (size_t)sp*Asplit + (size_t)(aB0 + 0)*16384;
        const unsigned char* sv = Bb + (size_t)sp*Bsplit + (size_t)(bB0 + 0)*16384;
        for (int i = tid; i < 1024; i += 256) {
            cp16(stg[0] + sp*16384 + i*16, sa + (size_t)i*16);
            cp16(stg[0] + 32768 + sp*16384 + i*16, sv + (size_t)i*16);
        }
    }
    CP_COMMIT();

    for (int kc = 0; kc < 16; kc++) {
        __syncthreads();
        if (kc + 1 < 16) {
            uint32_t dst = stg[(kc+1) & 1];
            #pragma unroll
            for (int sp = 0; sp < 2; sp++) {
                const unsigned char* sa = Ab + (size_t)sp*Asplit + (size_t)(aB0 + kc + 1)*16384;
                const unsigned char* sv = Bb + (size_t)sp*Bsplit + (size_t)(bB0 + kc + 1)*16384;
                for (int i = tid; i < 1024; i += 256) {
                    cp16(dst + sp*16384 + i*16, sa + (size_t)i*16);
                    cp16(dst + 32768 + sp*16384 + i*16, sv + (size_t)i*16);
                }
            }
            CP_COMMIT();
            CP_WAIT(1);
        } else {
            CP_WAIT(0);
        }
        __syncthreads();

        uint32_t a0 = stg[kc & 1], b0 = stg[kc & 1] + 32768;
        #pragma unroll
        for (int pr = 0; pr < 3; pr++) {
            uint32_t abase = a0 + (uint32_t)pa[pr]*16384;
            uint32_t bbase = b0 + (uint32_t)pb[pr]*16384;
            #pragma unroll
            for (int ks = 0; ks < 4; ks++) {
                uint32_t afr[4], bfr[32];
                {
                    uint32_t r = 16*w + (l & 7) + 8*((l >> 3) & 1);
                    uint32_t g = ks*2 + (l >> 4);
                    ldm_x4(afr, abase + r*128 + swz8(r, g));
                }
                #pragma unroll
                for (int p = 0; p < 8; p++) {
                    uint32_t n = 16*p + 8*((l >> 4) & 1) + (l & 7);
                    uint32_t g = ks*2 + ((l >> 3) & 1);
                    ldm_x4(bfr + 4*p, bbase + n*128 + swz8(n, g));
                }
                #pragma unroll
                for (int nt = 0; nt < 16; nt++)
                    mma16816(acc[nt], afr, &bfr[2*nt]);
            }
        }
    }

    __syncthreads();
    float* sOut = (float*)sm;
    #pragma unroll
    for (int nt = 0; nt < 16; nt++) {
        int colb = 8*nt + 2*(l & 3);
        int r0 = 16*w + (l >> 2);
        sOut[r0*132 + colb]       = acc[nt][0];
        sOut[r0*132 + colb + 1]   = acc[nt][1];
        sOut[(r0+8)*132 + colb]   = acc[nt][2];
        sOut[(r0+8)*132 + colb+1] = acc[nt][3];
    }
    __syncthreads();
    int tr = tid >> 4, tc = tid & 15;
    if (MODE == 1) {
        float bv[8];
        *(float4*)(bv)   = *(const float4*)(bias + 8*tc);
        *(float4*)(bv+4) = *(const float4*)(bias + 8*tc + 4);
        #pragma unroll
        for (int i = 0; i < 8; i++) {
            int row = 8*tr + i;
            float v[8];
            #pragma unroll
            for (int j = 0; j < 8; j++) v[j] = sOut[row*132 + 8*tc + j] + bv[j];
            uint4 uh, ul;
            split2h8(v, uh, ul);
            size_t base = (size_t)tile*32768 + (size_t)row*256 + swz16((uint32_t)row, (uint32_t)tc);
            *(uint4*)(Out + base)            = uh;
            *(uint4*)(Out + OutSplit + base) = ul;
        }
    } else {
        #pragma unroll
        for (int i = 0; i < 8; i++) {
            int d = 8*tr + i;
            float bd = bias[d];
            float v[8];
            #pragma unroll
            for (int j = 0; j < 8; j++) v[j] = sOut[d*132 + 8*tc + j] + bd;
            uint4 uh, ul;
            split2h8(v, uh, ul);
            size_t base = (size_t)tile*32768 + (size_t)d*256 + swz16((uint32_t)d, (uint32_t)tc);
            *(uint4*)(Out + base)            = uh;
            *(uint4*)(Out + OutSplit + base) = ul;
        }
    }
}

// ---------------- kernel 5: QT = Qs @ Ts (K=128, 3 products) ----------------
#define QT_SMEM (2*65536)
__global__ void __launch_bounds__(256,1) qt_tc() {
    extern __shared__ unsigned char sm[];
    uint32_t sb = smem_u32(sm);
    int tid = threadIdx.x, w = tid >> 5, l = tid & 31;
    int b = blockIdx.y, rb = blockIdx.x, tile = b*32 + rb;
    const int pa[3] = {0,0,1};
    const int pb[3] = {0,1,0};

    #pragma unroll
    for (int sp = 0; sp < 2; sp++) {
        const unsigned char* sa = g_Qs + (size_t)sp*SPLIT_SZ + (size_t)tile*32768;
        const unsigned char* st = g_Ts + (size_t)sp*TS_SPLIT + (size_t)b*32768;
        for (int i = tid; i < 2048; i += 256) {
            cp16(sb + sp*32768 + i*16, sa + (size_t)i*16);
            cp16(sb + 65536 + sp*32768 + i*16, st + (size_t)i*16);
        }
    }
    CP_COMMIT();
    CP_WAIT(0);
    __syncthreads();

    float acc[16][4];
    #pragma unroll
    for (int nt = 0; nt < 16; nt++)
        #pragma unroll
        for (int c = 0; c < 4; c++) acc[nt][c] = 0.f;

    #pragma unroll
    for (int pr = 0; pr < 3; pr++) {
        uint32_t abase = sb + (uint32_t)pa[pr]*32768;
        uint32_t bbase = sb + 65536 + (uint32_t)pb[pr]*32768;
        #pragma unroll
        for (int ks = 0; ks < 8; ks++) {
            uint32_t afr[4], bfr[32];
            {
                uint32_t r = 16*w + (l & 7) + 8*((l >> 3) & 1);
                uint32_t g = ks*2 + (l >> 4);
                ldm_x4(afr, abase + r*256 + swz16(r, g));
            }
            #pragma unroll
            for (int p = 0; p < 8; p++) {
                uint32_t n = 16*p + 8*((l >> 4) & 1) + (l & 7);
                uint32_t g = ks*2 + ((l >> 3) & 1);
                ldm_x4(bfr + 4*p, bbase + n*256 + swz16(n, g));
            }
            #pragma unroll
            for (int nt = 0; nt < 16; nt++)
                mma16816(acc[nt], afr, &bfr[2*nt]);
        }
    }

    __syncthreads();
    float* sOut = (float*)sm;
    #pragma unroll
    for (int nt = 0; nt < 16; nt++) {
        int colb = 8*nt + 2*(l & 3);
        int r0 = 16*w + (l >> 2);
        sOut[r0*132 + colb]       = acc[nt][0];
        sOut[r0*132 + colb + 1]   = acc[nt][1];
        sOut[(r0+8)*132 + colb]   = acc[nt][2];
        sOut[(r0+8)*132 + colb+1] = acc[nt][3];
    }
    __syncthreads();
    int tr = tid >> 4, tc = tid & 15;
    #pragma unroll
    for (int i = 0; i < 8; i++) {
        int row = 8*tr + i;
        float v[8];
        #pragma unroll
        for (int j = 0; j < 8; j++) v[j] = sOut[row*132 + 8*tc + j];
        uint4 uh, ul;
        split2h8(v, uh, ul);
        size_t base = (size_t)tile*32768 + (size_t)row*256 + swz16((uint32_t)row, (uint32_t)tc);
        *(uint4*)(g_QTs + base)            = uh;
        *(uint4*)(g_QTs + SPLIT_SZ + base) = ul;
    }
}

// ---------------- pass 1: 64-query CTAs, 2 CTAs/SM, deferred m/l merge ----------------
#define P1_SMEM (32768 + 65536 + 1024)
__global__ void __launch_bounds__(256,2) attn_pass1(float* __restrict__ d_out) {
    extern __shared__ unsigned char sm[];
    uint32_t sb = smem_u32(sm);
    uint32_t qt_s = sb, k_s = sb + 32768;
    float* sM = (float*)(sm + 98304);
    float* sL = sM + 128;

    int tid = threadIdx.x, w = tid >> 5, l = tid & 31;
    int b = blockIdx.y, bx = blockIdx.x;
    int wr = w >> 1, wc = w & 1;
    float* attn = d_out + (size_t)Bn*Sn*DKn;
    size_t rowbase = (size_t)b*Sn + (size_t)bx*64;

    // prologue: QT half-tile (64 rows) + K(0) half-tile
    size_t qoff = (size_t)(b*32 + (bx >> 1))*32768 + (size_t)(bx & 1)*16384;
    #pragma unroll
    for (int sp = 0; sp < 2; sp++) {
        const unsigned char* srcq = g_QTs + (size_t)sp*SPLIT_SZ + qoff;
        const unsigned char* srck = g_Ks + (size_t)sp*SPLIT_SZ + (size_t)(b*32)*32768;
        for (int i = tid; i < 1024; i += 256) {
            cp16(qt_s + sp*16384 + i*16, srcq + (size_t)i*16);
            cp16(k_s + sp*16384 + i*16, srck + (size_t)i*16);
        }
    }
    CP_COMMIT();

    const int pa[3] = {0,0,1};
    const int pb[3] = {0,1,0};
    int r0 = 16*wr + (l >> 2);
    float m0 = -1e30f, l0 = 0.f, m1 = -1e30f, l1 = 0.f;

    for (int jj = 0; jj < 64; jj++) {
        __syncthreads();
        if (jj + 1 < 64) {
            int jt = (jj+1) >> 1, hf = (jj+1) & 1;
            uint32_t dst = k_s + (uint32_t)(((jj+1) & 1) * 32768);
            #pragma unroll
            for (int sp = 0; sp < 2; sp++) {
                const unsigned char* src = g_Ks + (size_t)sp*SPLIT_SZ
                    + (size_t)(b*32 + jt)*32768 + (size_t)hf*16384;
                for (int i = tid; i < 1024; i += 256) cp16(dst + sp*16384 + i*16, src + (size_t)i*16);
            }
            CP_COMMIT();
            CP_WAIT(1);
        } else {
            CP_WAIT(0);
        }
        __syncthreads();

        uint32_t kb = k_s + (uint32_t)((jj & 1) * 32768);
        float acc[4][4];
        #pragma unroll
        for (int nt = 0; nt < 4; nt++)
            #pragma unroll
            for (int c = 0; c < 4; c++) acc[nt][c] = 0.f;

        #pragma unroll
        for (int pr = 0; pr < 3; pr++) {
            uint32_t abase = qt_s + (uint32_t)pa[pr]*16384;
            uint32_t bbase = kb + (uint32_t)pb[pr]*16384;
            #pragma unroll
            for (int kc = 0; kc < 8; kc++) {
                uint32_t afr[4], bfr[8];
                {
                    uint32_t r = 16*wr + (l & 7) + 8*((l >> 3) & 1);
                    uint32_t g = kc*2 + (l >> 4);
                    ldm_x4(afr, abase + r*256 + swz16(r, g));
                }
                #pragma unroll
                for (int p = 0; p < 2; p++) {
                    uint32_t n = 32*wc + 16*p + 8*((l >> 4) & 1) + (l & 7);
                    uint32_t g = kc*2 + ((l >> 3) & 1);
                    ldm_x4(bfr + 4*p, bbase + n*256 + swz16(n, g));
                }
                #pragma unroll
                for (int nt = 0; nt < 4; nt++)
                    mma16816(acc[nt], afr, &bfr[2*nt]);
            }
        }

        // warp-local (32-col slice) online stats
        float tm0 = -1e30f, tm1 = -1e30f;
        #pragma unroll
        for (int nt = 0; nt < 4; nt++) {
            tm0 = fmaxf(tm0, fmaxf(acc[nt][0], acc[nt][1]));
            tm1 = fmaxf(tm1, fmaxf(acc[nt][2], acc[nt][3]));
        }
        tm0 = fmaxf(tm0, __shfl_xor_sync(0xffffffffu, tm0, 1));
        tm0 = fmaxf(tm0, __shfl_xor_sync(0xffffffffu, tm0, 2));
        tm1 = fmaxf(tm1, __shfl_xor_sync(0xffffffffu, tm1, 1));
        tm1 = fmaxf(tm1, __shfl_xor_sync(0xffffffffu, tm1, 2));
        float mn0 = fmaxf(m0, tm0), mn1 = fmaxf(m1, tm1);
        float rs0 = 0.f, rs1 = 0.f;
        #pragma unroll
        for (int nt = 0; nt < 4; nt++) {
            rs0 += __expf(acc[nt][0] - mn0) + __expf(acc[nt][1] - mn0);
            rs1 += __expf(acc[nt][2] - mn1) + __expf(acc[nt][3] - mn1);
        }
        rs0 += __shfl_xor_sync(0xffffffffu, rs0, 1);
        rs0 += __shfl_xor_sync(0xffffffffu, rs0, 2);
        rs1 += __shfl_xor_sync(0xffffffffu, rs1, 1);
        rs1 += __shfl_xor_sync(0xffffffffu, rs1, 2);
        l0 = l0*__expf(m0 - mn0) + rs0; m0 = mn0;
        l1 = l1*__expf(m1 - mn1) + rs1; m1 = mn1;

        // dump raw scaled scores
        float* dst0 = attn + (rowbase + r0)*Sn + (size_t)jj*64 + 32*wc + 2*(l & 3);
        float* dst1 = attn + (rowbase + r0 + 8)*Sn + (size_t)jj*64 + 32*wc + 2*(l & 3);
        #pragma unroll
        for (int nt = 0; nt < 4; nt++) {
            *(float2*)(dst0 + 8*nt) = make_float2(acc[nt][0], acc[nt][1]);
            *(float2*)(dst1 + 8*nt) = make_float2(acc[nt][2], acc[nt][3]);
        }
    }

    // merge col-half stats
    if ((l & 3) == 0) {
        sM[wc*64 + r0]     = m0;  sL[wc*64 + r0]     = l0;
        sM[wc*64 + r0 + 8] = m1;  sL[wc*64 + r0 + 8] = l1;
    }
    __syncthreads();
    if (tid < 64) {
        float ma = sM[tid], mb = sM[64 + tid];
        float mn = fmaxf(ma, mb);
        float lt = sL[tid]*__expf(ma - mn) + sL[64 + tid]*__expf(mb - mn);
        g_m[rowbase + tid] = mn;
        g_l[rowbase + tid] = lt;
    }
}

// ---------------- pass 2: 64-query CTAs, 2 CTAs/SM ----------------
#define P2_SMEM (16384 + 65536)
__global__ void __launch_bounds__(256,2) attn_pass2(float* __restrict__ d_out) {
    extern __shared__ unsigned char sm[];
    uint32_t sb = smem_u32(sm);
    uint32_t p_s = sb, v_s = sb + 16384;

    int tid = threadIdx.x, w = tid >> 5, l = tid & 31;
    int b = blockIdx.y, bx = blockIdx.x;
    int wr = w >> 1, wc = w & 1;
    float* attn = d_out + (size_t)Bn*Sn*DKn;
    size_t rowbase = (size_t)b*Sn + (size_t)bx*64;

    // exp-phase row constants: thread owns row tid>>2, col groups (tid&3)*16 + {0,8}
    int erow = tid >> 2;
    int c0 = (tid & 3) * 16;
    float mv = g_m[rowbase + erow];
    float li = 1.0f / g_l[rowbase + erow];
    uint32_t pst0 = p_s + (uint32_t)erow*128 + swz8((uint32_t)erow, (uint32_t)(c0 >> 3));
    uint32_t pst1 = p_s + (uint32_t)erow*128 + swz8((uint32_t)erow, (uint32_t)(c0 >> 3) + 1);

    // prologue: V(0) half-tile (tokens 0..63), intra-row split copy
    #pragma unroll
    for (int sp = 0; sp < 2; sp++) {
        const unsigned char* src = g_Vt + (size_t)sp*SPLIT_SZ + (size_t)(b*32)*32768;
        for (int i = tid; i < 1024; i += 256) {
            int r = i >> 3, s8 = i & 7;
            cp16(v_s + sp*16384 + r*128 + s8*16, src + (size_t)r*256 + (size_t)s8*16);
        }
    }
    CP_COMMIT();

    float out[8][4];
    #pragma unroll
    for (int nt = 0; nt < 8; nt++)
        #pragma unroll
        for (int c = 0; c < 4; c++) out[nt][c] = 0.f;

    const int pa2[3] = {0,0,1};
    const int pb2[3] = {0,1,0};

    for (int jj = 0; jj < 64; jj++) {
        __syncthreads();                 // prev mma done: P + old V writable

        // exp: read raw scores, write final p, stage 2-split into P smem
        {
            float* srcp = attn + (rowbase + erow)*Sn + (size_t)jj*64 + c0;
            float p8[8];
            *(float4*)(p8)   = *(const float4*)(srcp);
            *(float4*)(p8+4) = *(const float4*)(srcp + 4);
            #pragma unroll
            for (int x = 0; x < 8; x++) p8[x] = __expf(p8[x] - mv) * li;
            *(float4*)(srcp)     = *(float4*)(p8);
            *(float4*)(srcp + 4) = *(float4*)(p8+4);
            uint4 uh, ul;
            split2h8(p8, uh, ul);
            STS16(pst0, uh);
            STS16(pst0 + 8192, ul);

            *(float4*)(p8)   = *(const float4*)(srcp + 8);
            *(float4*)(p8+4) = *(const float4*)(srcp + 12);
            #pragma unroll
            for (int x = 0; x < 8; x++) p8[x] = __expf(p8[x] - mv) * li;
            *(float4*)(srcp + 8)  = *(float4*)(p8);
            *(float4*)(srcp + 12) = *(float4*)(p8+4);
            split2h8(p8, uh, ul);
            STS16(pst1, uh);
            STS16(pst1 + 8192, ul);
        }

        if (jj + 1 < 64) {
            int jt = (jj+1) >> 1, hf = (jj+1) & 1;
            uint32_t dst = v_s + (uint32_t)(((jj+1) & 1) * 32768);
            #pragma unroll
            for (int sp = 0; sp < 2; sp++) {
                const unsigned char* src = g_Vt + (size_t)sp*SPLIT_SZ
                    + (size_t)(b*32 + jt)*32768 + (size_t)hf*128;
                for (int i = tid; i < 1024; i += 256) {
                    int r = i >> 3, s8 = i & 7;
                    cp16(dst + sp*16384 + r*128 + s8*16, src + (size_t)r*256 + (size_t)s8*16);
                }
            }
            CP_COMMIT();
            CP_WAIT(1);
        } else {
            CP_WAIT(0);
        }
        __syncthreads();

        uint32_t vb = v_s + (uint32_t)((jj & 1) * 32768);
        #pragma unroll
        for (int pr = 0; pr < 3; pr++) {
            uint32_t abase = p_s + (uint32_t)pa2[pr]*8192;
            uint32_t bbase = vb + (uint32_t)pb2[pr]*16384;
            #pragma unroll
            for (int kc = 0; kc < 4; kc++) {
                uint32_t afr[4], bfr[16];
                {
                    uint32_t r = 16*wr + (l & 7) + 8*((l >> 3) & 1);
                    uint32_t g = kc*2 + (l >> 4);
                    ldm_x4(afr, abase + r*128 + swz8(r, g));
                }
                #pragma unroll
                for (int p = 0; p < 4; p++) {
                    uint32_t n = 64*wc + 16*p + 8*((l >> 4) & 1) + (l & 7);
                    uint32_t g = kc*2 + ((l >> 3) & 1);
                    ldm_x4(bfr + 4*p, bbase + n*128 + swz8(n, g));
                }
                #pragma unroll
                for (int nt = 0; nt < 8; nt++)
                    mma16816(out[nt], afr, &bfr[2*nt]);
            }
        }
    }

    // epilogue
    #pragma unroll
    for (int nt = 0; nt < 8; nt++)
        #pragma unroll
        for (int dl = 0; dl < 2; dl++) {
            int row = 16*wr + (l >> 2) + 8*dl;
            float* o = d_out + (rowbase + row)*DKn + 64*wc + 8*nt + 2*(l & 3);
            *(float2*)(o) = make_float2(out[nt][2*dl], out[nt][2*dl+1]);
        }
}

// ---------------- launcher ----------------
extern "C" void kernel_launch(void* const* d_in, const int* in_sizes, int n_in,
                              void* d_out, int out_size) {
    const float* x  = (const float*)d_in[0];
    const float* tp = (const float*)d_in[1];
    const float* Wq = (const float*)d_in[2];
    const float* bq = (const float*)d_in[3];
    const float* Wk = (const float*)d_in[4];
    const float* bk = (const float*)d_in[5];
    const float* Wv = (const float*)d_in[6];
    const float* bv = (const float*)d_in[7];
    const float* Wt = (const float*)d_in[8];
    const float* bt = (const float*)d_in[9];
    float* out = (float*)d_out;

    unsigned char *pxs, *pWs, *pQs, *pKs, *pVt;
    cudaGetSymbolAddress((void**)&pxs,  g_xs);
    cudaGetSymbolAddress((void**)&pWs,  g_Ws);
    cudaGetSymbolAddress((void**)&pQs,  g_Qs);
    cudaGetSymbolAddress((void**)&pKs,  g_Ks);
    cudaGetSymbolAddress((void**)&pVt,  g_Vt);

    cudaFuncSetAttribute((const void*)proj_tc<1>, cudaFuncAttributeMaxDynamicSharedMemorySize, PROJ_SMEM);
    cudaFuncSetAttribute((const void*)proj_tc<2>, cudaFuncAttributeMaxDynamicSharedMemorySize, PROJ_SMEM);
    cudaFuncSetAttribute((const void*)qt_tc,      cudaFuncAttributeMaxDynamicSharedMemorySize, QT_SMEM);
    cudaFuncSetAttribute((const void*)attn_pass1, cudaFuncAttributeMaxDynamicSharedMemorySize, P1_SMEM);
    cudaFuncSetAttribute((const void*)attn_pass2, cudaFuncAttributeMaxDynamicSharedMemorySize, P2_SMEM);

    prep_T_kernel<<<Bn, 256>>>(tp, Wt, bt);
    split_x_kernel<<<8192, 256>>>(x);
    split_W_kernel<<<dim3(16, 3), 256>>>(Wq, Wk, Wv);

    proj_tc<1><<<128, 256, PROJ_SMEM>>>(pxs, XS_SPLIT, 16,
                                        pWs, WS_SPLIT, 0, bq, pQs, SPLIT_SZ);
    proj_tc<1><<<128, 256, PROJ_SMEM>>>(pxs, XS_SPLIT, 16,
                                        pWs + 16*16384, WS_SPLIT, 0, bk, pKs, SPLIT_SZ);
    proj_tc<2><<<128, 256, PROJ_SMEM>>>(pWs + 32*16384, WS_SPLIT, 0,
                                        pxs, XS_SPLIT, 16, bv, pVt, SPLIT_SZ);
    qt_tc<<<dim3(32, Bn), 256, QT_SMEM>>>();

    attn_pass1<<<dim3(64, Bn), 256, P1_SMEM>>>(out);
    attn_pass2<<<dim3(64, Bn), 256, P2_SMEM>>>(out);
}

// round 8
// speedup vs baseline: 3.3880x; 1.0654x over previous
#include <cuda_runtime.h>
#include <cuda_fp16.h>
#include <math.h>
#include <stdint.h>

#define Bn 4
#define Sn 4096
#define Dn 1024
#define TPn 16
#define TEn 64
#define DKn 128
#define NTILE 128
#define SPLIT_SZ (NTILE*32768ULL)
#define XS_SPLIT (NTILE*16*16384ULL)
#define WS_SPLIT (3*16*16384ULL)
#define TS_SPLIT (Bn*32768ULL)
#define SCALE 0.08838834764831845f

// ---------------- scratch (2-way fp16 splits; V keeps hi only) ----------------
__device__ __align__(16) unsigned char g_xs [2*XS_SPLIT];
__device__ __align__(16) unsigned char g_Ws [2*WS_SPLIT];
__device__ __align__(16) unsigned char g_Ts [2*TS_SPLIT];
__device__ __align__(16) unsigned char g_Qs [2*SPLIT_SZ];
__device__ __align__(16) unsigned char g_Ks [2*SPLIT_SZ];
__device__ __align__(16) unsigned char g_QTs[2*SPLIT_SZ];
__device__ __align__(16) unsigned char g_Vt [SPLIT_SZ];

// ---------------- helpers ----------------
__device__ __forceinline__ uint32_t smem_u32(const void* p){
    uint32_t a;
    asm("{ .reg .u64 t; cvta.to.shared.u64 t, %1; cvt.u32.u64 %0, t; }" : "=r"(a) : "l"(p));
    return a;
}
__device__ __forceinline__ uint32_t swz16(uint32_t r, uint32_t g){
    return ((g & 8u) | ((g ^ r) & 7u)) << 4;
}
__device__ __forceinline__ uint32_t swz8(uint32_t r, uint32_t g){
    return ((g ^ r) & 7u) << 4;
}
__device__ __forceinline__ void cp16(uint32_t dst, const void* src){
    asm volatile("cp.async.cg.shared.global [%0], [%1], 16;" :: "r"(dst), "l"(src) : "memory");
}
#define CP_COMMIT() asm volatile("cp.async.commit_group;" ::: "memory")
#define CP_WAIT(n)  asm volatile("cp.async.wait_group %0;" :: "n"(n) : "memory")
#define STS16(addr, v) asm volatile("st.shared.v4.b32 [%0], {%1,%2,%3,%4};" \
    :: "r"(addr), "r"((v).x), "r"((v).y), "r"((v).z), "r"((v).w) : "memory")

__device__ __forceinline__ void ldm_x4(uint32_t* r, uint32_t addr){
    asm volatile("ldmatrix.sync.aligned.m8n8.x4.shared.b16 {%0,%1,%2,%3}, [%4];"
        : "=r"(r[0]), "=r"(r[1]), "=r"(r[2]), "=r"(r[3]) : "r"(addr));
}
__device__ __forceinline__ void mma16816(float* d, const uint32_t* a, const uint32_t* b){
    asm volatile("mma.sync.aligned.m16n8k16.row.col.f32.f16.f16.f32 "
        "{%0,%1,%2,%3}, {%4,%5,%6,%7}, {%8,%9}, {%0,%1,%2,%3};"
        : "+f"(d[0]), "+f"(d[1]), "+f"(d[2]), "+f"(d[3])
        : "r"(a[0]), "r"(a[1]), "r"(a[2]), "r"(a[3]), "r"(b[0]), "r"(b[1]));
}
__device__ __forceinline__ uint32_t pk(unsigned short a, unsigned short b){
    return (uint32_t)a | ((uint32_t)b << 16);
}
__device__ __forceinline__ void split2h8(const float* v, uint4& uh, uint4& ul){
    unsigned short h[8], l[8];
    #pragma unroll
    for (int j = 0; j < 8; j++){
        __half hh = __float2half_rn(v[j]);
        __half hl = __float2half_rn(v[j] - __half2float(hh));
        h[j] = __half_as_ushort(hh); l[j] = __half_as_ushort(hl);
    }
    uh = make_uint4(pk(h[0],h[1]), pk(h[2],h[3]), pk(h[4],h[5]), pk(h[6],h[7]));
    ul = make_uint4(pk(l[0],l[1]), pk(l[2],l[3]), pk(l[4],l[5]), pk(l[6],l[7]));
}
__device__ __forceinline__ void packh8(const float* v, uint4& uh){
    unsigned short h[8];
    #pragma unroll
    for (int j = 0; j < 8; j++) h[j] = __half_as_ushort(__float2half_rn(v[j]));
    uh = make_uint4(pk(h[0],h[1]), pk(h[2],h[3]), pk(h[4],h[5]), pk(h[6],h[7]));
}

// ---------------- kernel 1: T_scaled (x SCALE) -> 2-split fp16 blobs ----------------
__global__ void prep_T_kernel(const float* __restrict__ tp,
                              const float* __restrict__ Wt,
                              const float* __restrict__ bt) {
    __shared__ float sTP[TPn*TEn];
    __shared__ float sWt[TEn*DKn];
    __shared__ float sE [TPn*DKn];
    __shared__ float red[256];
    int b = blockIdx.x, tid = threadIdx.x;
    for (int i = tid; i < TPn*TEn; i += 256) sTP[i] = tp[b*TPn*TEn + i];
    for (int i = tid; i < TEn*DKn; i += 256) sWt[i] = Wt[i];
    __syncthreads();
    for (int i = tid; i < TPn*DKn; i += 256) {
        int t = i >> 7, d = i & 127;
        float acc = bt[d];
        #pragma unroll 8
        for (int e = 0; e < TEn; e++) acc += sTP[t*TEn + e] * sWt[e*DKn + d];
        sE[i] = acc;
    }
    __syncthreads();
    float ss = 0.f;
    for (int i = tid; i < TPn*DKn; i += 256) ss += sE[i]*sE[i];
    red[tid] = ss; __syncthreads();
    for (int off = 128; off > 0; off >>= 1) {
        if (tid < off) red[tid] += red[tid+off];
        __syncthreads();
    }
    float tn = sqrtf((float)Sn * red[0]);
    float sc = (float)Sn / (tn + 1e-8f) * SCALE;
    for (int i = tid; i < DKn*DKn; i += 256) {
        int d = i >> 7, e2 = i & 127;
        float acc = 0.f;
        #pragma unroll
        for (int t = 0; t < TPn; t++) acc += sE[t*DKn + d] * sE[t*DKn + e2];
        float v = acc * sc;
        __half hh = __float2half_rn(v);
        __half hl = __float2half_rn(v - __half2float(hh));
        size_t base = (size_t)b*32768 + (size_t)d*256 + swz16((uint32_t)d, (uint32_t)(e2 >> 3)) + (size_t)(e2 & 7)*2;
        *(__half*)(g_Ts + base)            = hh;
        *(__half*)(g_Ts + TS_SPLIT + base) = hl;
    }
}

// ---------------- kernel 2: split x -> 2-split fp16 blobs ----------------
__global__ void split_x_kernel(const float* __restrict__ x) {
    int gidx = blockIdx.x*256 + threadIdx.x;
    int rt = gidx >> 7, gk = gidx & 127;
    int kc = gk >> 3, g = gk & 7;
    const float* src = x + (size_t)rt*Dn + kc*64 + g*8;
    float v[8];
    *(float4*)(v)   = *(const float4*)(src);
    *(float4*)(v+4) = *(const float4*)(src + 4);
    uint4 uh, ul;
    split2h8(v, uh, ul);
    int tile = rt >> 7, r = rt & 127;
    size_t off = (size_t)(tile*16 + kc)*16384 + (size_t)r*128 + swz8((uint32_t)r, (uint32_t)g);
    *(uint4*)(g_xs + off)            = uh;
    *(uint4*)(g_xs + XS_SPLIT + off) = ul;
}

// ---------------- kernel 3: split W^T -> 2-split fp16 blobs ----------------
__global__ void split_W_kernel(const float* __restrict__ Wq,
                               const float* __restrict__ Wk,
                               const float* __restrict__ Wv) {
    __shared__ float sW[64*128];
    int kc = blockIdx.x, mat = blockIdx.y, tid = threadIdx.x;
    const float* W = (mat == 0) ? Wq : ((mat == 1) ? Wk : Wv);
    for (int i = tid; i < 2048; i += 256)
        ((float4*)sW)[i] = ((const float4*)(W + (size_t)kc*64*128))[i];
    __syncthreads();
    for (int it = 0; it < 4; it++) {
        int gi = tid + it*256;
        int d = gi >> 3, g = gi & 7;
        float v[8];
        #pragma unroll
        for (int j = 0; j < 8; j++) v[j] = sW[(g*8 + j)*128 + d];
        uint4 uh, ul;
        split2h8(v, uh, ul);
        size_t off = (size_t)(mat*16 + kc)*16384 + (size_t)d*128 + swz8((uint32_t)d, (uint32_t)g);
        *(uint4*)(g_Ws + off)            = uh;
        *(uint4*)(g_Ws + WS_SPLIT + off) = ul;
    }
}

// ---------------- kernel 4: TC projection GEMM, 512 threads ----------------
// MODE 1: rows=tokens, 2-split blob + bias[col]. MODE 2: rows=dk, hi-only V^T + bias[row].
#define PROJ_SMEM (2*65536)
template<int MODE>
__global__ void __launch_bounds__(512,1)
proj_tc(const unsigned char* __restrict__ Ab, size_t Asplit, int aStride,
        const unsigned char* __restrict__ Bb, size_t Bsplit, int bStride,
        const float* __restrict__ bias, unsigned char* __restrict__ Out,
        size_t OutSplit) {
    extern __shared__ unsigned char sm[];
    uint32_t sb = smem_u32(sm);
    int tid = threadIdx.x, w = tid >> 5, l = tid & 31;
    int wrow = w >> 1, wcol = w & 1;
    int tile = blockIdx.x;
    int aB0 = tile * aStride, bB0 = tile * bStride;
    const int pa[3] = {0,0,1};
    const int pb[3] = {0,1,0};

    float acc[8][4];
    #pragma unroll
    for (int nt = 0; nt < 8; nt++)
        #pragma unroll
        for (int c = 0; c < 4; c++) acc[nt][c] = 0.f;

    uint32_t stg[2] = {sb, sb + 65536};
    #pragma unroll
    for (int sp = 0; sp < 2; sp++) {
        const unsigned char* sa = Ab + (size_t)sp*Asplit + (size_t)(aB0 + 0)*16384;
        const unsigned char* sv = Bb + (size_t)sp*Bsplit + (size_t)(bB0 + 0)*16384;
        for (int i = tid; i < 1024; i += 512) {
            cp16(stg[0] + sp*16384 + i*16, sa + (size_t)i*16);
            cp16(stg[0] + 32768 + sp*16384 + i*16, sv + (size_t)i*16);
        }
    }
    CP_COMMIT();

    for (int kc = 0; kc < 16; kc++) {
        __syncthreads();
        if (kc + 1 < 16) {
            uint32_t dst = stg[(kc+1) & 1];
            #pragma unroll
            for (int sp = 0; sp < 2; sp++) {
                const unsigned char* sa = Ab + (size_t)sp*Asplit + (size_t)(aB0 + kc + 1)*16384;
                const unsigned char* sv = Bb + (size_t)sp*Bsplit + (size_t)(bB0 + kc + 1)*16384;
                for (int i = tid; i < 1024; i += 512) {
                    cp16(dst + sp*16384 + i*16, sa + (size_t)i*16);
                    cp16(dst + 32768 + sp*16384 + i*16, sv + (size_t)i*16);
                }
            }
            CP_COMMIT();
            CP_WAIT(1);
        } else {
            CP_WAIT(0);
        }
        __syncthreads();

        uint32_t a0 = stg[kc & 1], b0 = stg[kc & 1] + 32768;
        #pragma unroll
        for (int pr = 0; pr < 3; pr++) {
            uint32_t abase = a0 + (uint32_t)pa[pr]*16384;
            uint32_t bbase = b0 + (uint32_t)pb[pr]*16384;
            #pragma unroll
            for (int ks = 0; ks < 4; ks++) {
                uint32_t afr[4], bfr[16];
                {
                    uint32_t r = 16*wrow + (l & 7) + 8*((l >> 3) & 1);
                    uint32_t g = ks*2 + (l >> 4);
                    ldm_x4(afr, abase + r*128 + swz8(r, g));
                }
                #pragma unroll
                for (int p = 0; p < 4; p++) {
                    uint32_t n = 64*wcol + 16*p + 8*((l >> 4) & 1) + (l & 7);
                    uint32_t g = ks*2 + ((l >> 3) & 1);
                    ldm_x4(bfr + 4*p, bbase + n*128 + swz8(n, g));
                }
                #pragma unroll
                for (int nt = 0; nt < 8; nt++)
                    mma16816(acc[nt], afr, &bfr[2*nt]);
            }
        }
    }

    __syncthreads();
    float* sOut = (float*)sm;
    #pragma unroll
    for (int nt = 0; nt < 8; nt++) {
        int colb = 64*wcol + 8*nt + 2*(l & 3);
        int r0 = 16*wrow + (l >> 2);
        sOut[r0*132 + colb]       = acc[nt][0];
        sOut[r0*132 + colb + 1]   = acc[nt][1];
        sOut[(r0+8)*132 + colb]   = acc[nt][2];
        sOut[(r0+8)*132 + colb+1] = acc[nt][3];
    }
    __syncthreads();
    int tr = tid >> 4, tc = tid & 15;     // 32 row-groups x 16 col-groups, 4 rows each
    if (MODE == 1) {
        float bv[8];
        *(float4*)(bv)   = *(const float4*)(bias + 8*tc);
        *(float4*)(bv+4) = *(const float4*)(bias + 8*tc + 4);
        #pragma unroll
        for (int i = 0; i < 4; i++) {
            int row = 4*tr + i;
            float v[8];
            #pragma unroll
            for (int j = 0; j < 8; j++) v[j] = sOut[row*132 + 8*tc + j] + bv[j];
            uint4 uh, ul;
            split2h8(v, uh, ul);
            size_t base = (size_t)tile*32768 + (size_t)row*256 + swz16((uint32_t)row, (uint32_t)tc);
            *(uint4*)(Out + base)            = uh;
            *(uint4*)(Out + OutSplit + base) = ul;
        }
    } else {
        #pragma unroll
        for (int i = 0; i < 4; i++) {
            int d = 4*tr + i;
            float bd = bias[d];
            float v[8];
            #pragma unroll
            for (int j = 0; j < 8; j++) v[j] = sOut[d*132 + 8*tc + j] + bd;
            uint4 uh;
            packh8(v, uh);
            size_t base = (size_t)tile*32768 + (size_t)d*256 + swz16((uint32_t)d, (uint32_t)tc);
            *(uint4*)(Out + base) = uh;
        }
    }
}

// ---------------- kernel 5: QT = Qs @ Ts (K=128, 3 products) ----------------
#define QT_SMEM (2*65536)
__global__ void __launch_bounds__(256,1) qt_tc() {
    extern __shared__ unsigned char sm[];
    uint32_t sb = smem_u32(sm);
    int tid = threadIdx.x, w = tid >> 5, l = tid & 31;
    int b = blockIdx.y, rb = blockIdx.x, tile = b*32 + rb;
    const int pa[3] = {0,0,1};
    const int pb[3] = {0,1,0};

    #pragma unroll
    for (int sp = 0; sp < 2; sp++) {
        const unsigned char* sa = g_Qs + (size_t)sp*SPLIT_SZ + (size_t)tile*32768;
        const unsigned char* st = g_Ts + (size_t)sp*TS_SPLIT + (size_t)b*32768;
        for (int i = tid; i < 2048; i += 256) {
            cp16(sb + sp*32768 + i*16, sa + (size_t)i*16);
            cp16(sb + 65536 + sp*32768 + i*16, st + (size_t)i*16);
        }
    }
    CP_COMMIT();
    CP_WAIT(0);
    __syncthreads();

    float acc[16][4];
    #pragma unroll
    for (int nt = 0; nt < 16; nt++)
        #pragma unroll
        for (int c = 0; c < 4; c++) acc[nt][c] = 0.f;

    #pragma unroll
    for (int pr = 0; pr < 3; pr++) {
        uint32_t abase = sb + (uint32_t)pa[pr]*32768;
        uint32_t bbase = sb + 65536 + (uint32_t)pb[pr]*32768;
        #pragma unroll
        for (int ks = 0; ks < 8; ks++) {
            uint32_t afr[4], bfr[32];
            {
                uint32_t r = 16*w + (l & 7) + 8*((l >> 3) & 1);
                uint32_t g = ks*2 + (l >> 4);
                ldm_x4(afr, abase + r*256 + swz16(r, g));
            }
            #pragma unroll
            for (int p = 0; p < 8; p++) {
                uint32_t n = 16*p + 8*((l >> 4) & 1) + (l & 7);
                uint32_t g = ks*2 + ((l >> 3) & 1);
                ldm_x4(bfr + 4*p, bbase + n*256 + swz16(n, g));
            }
            #pragma unroll
            for (int nt = 0; nt < 16; nt++)
                mma16816(acc[nt], afr, &bfr[2*nt]);
        }
    }

    __syncthreads();
    float* sOut = (float*)sm;
    #pragma unroll
    for (int nt = 0; nt < 16; nt++) {
        int colb = 8*nt + 2*(l & 3);
        int r0 = 16*w + (l >> 2);
        sOut[r0*132 + colb]       = acc[nt][0];
        sOut[r0*132 + colb + 1]   = acc[nt][1];
        sOut[(r0+8)*132 + colb]   = acc[nt][2];
        sOut[(r0+8)*132 + colb+1] = acc[nt][3];
    }
    __syncthreads();
    int tr = tid >> 4, tc = tid & 15;
    #pragma unroll
    for (int i = 0; i < 8; i++) {
        int row = 8*tr + i;
        float v[8];
        #pragma unroll
        for (int j = 0; j < 8; j++) v[j] = sOut[row*132 + 8*tc + j];
        uint4 uh, ul;
        split2h8(v, uh, ul);
        size_t base = (size_t)tile*32768 + (size_t)row*256 + swz16((uint32_t)row, (uint32_t)tc);
        *(uint4*)(g_QTs + base)            = uh;
        *(uint4*)(g_QTs + SPLIT_SZ + base) = ul;
    }
}

// ---------------- fused attention: phase1 scores+stats, phase2 exp + PV ----------------
#define ATT_SMEM (32768 + 65536 + 1024)
__global__ void __launch_bounds__(256,2) attn_fused(float* __restrict__ d_out) {
    extern __shared__ unsigned char sm[];
    uint32_t sb = smem_u32(sm);
    uint32_t qt_s = sb, k_s = sb + 32768;           // phase2: p_s = sb, v_s = sb + 32768
    float* sM = (float*)(sm + 98304);
    float* sL = sM + 128;

    int tid = threadIdx.x, w = tid >> 5, l = tid & 31;
    int b = blockIdx.y, bx = blockIdx.x;
    int wr = w >> 1, wc = w & 1;
    float* attn = d_out + (size_t)Bn*Sn*DKn;
    size_t rowbase = (size_t)b*Sn + (size_t)bx*64;

    // ---- phase 1 prologue: QT half-tile + K(0) half-tile ----
    size_t qoff = (size_t)(b*32 + (bx >> 1))*32768 + (size_t)(bx & 1)*16384;
    #pragma unroll
    for (int sp = 0; sp < 2; sp++) {
        const unsigned char* srcq = g_QTs + (size_t)sp*SPLIT_SZ + qoff;
        const unsigned char* srck = g_Ks + (size_t)sp*SPLIT_SZ + (size_t)(b*32)*32768;
        for (int i = tid; i < 1024; i += 256) {
            cp16(qt_s + sp*16384 + i*16, srcq + (size_t)i*16);
            cp16(k_s + sp*16384 + i*16, srck + (size_t)i*16);
        }
    }
    CP_COMMIT();

    const int pa[3] = {0,0,1};
    const int pb[3] = {0,1,0};
    int r0 = 16*wr + (l >> 2);
    float m0 = -1e30f, l0 = 0.f, m1 = -1e30f, l1 = 0.f;

    for (int jj = 0; jj < 64; jj++) {
        __syncthreads();
        if (jj + 1 < 64) {
            int jt = (jj+1) >> 1, hf = (jj+1) & 1;
            uint32_t dst = k_s + (uint32_t)(((jj+1) & 1) * 32768);
            #pragma unroll
            for (int sp = 0; sp < 2; sp++) {
                const unsigned char* src = g_Ks + (size_t)sp*SPLIT_SZ
                    + (size_t)(b*32 + jt)*32768 + (size_t)hf*16384;
                for (int i = tid; i < 1024; i += 256) cp16(dst + sp*16384 + i*16, src + (size_t)i*16);
            }
            CP_COMMIT();
            CP_WAIT(1);
        } else {
            CP_WAIT(0);
        }
        __syncthreads();

        uint32_t kb = k_s + (uint32_t)((jj & 1) * 32768);
        float acc[4][4];
        #pragma unroll
        for (int nt = 0; nt < 4; nt++)
            #pragma unroll
            for (int c = 0; c < 4; c++) acc[nt][c] = 0.f;

        #pragma unroll
        for (int pr = 0; pr < 3; pr++) {
            uint32_t abase = qt_s + (uint32_t)pa[pr]*16384;
            uint32_t bbase = kb + (uint32_t)pb[pr]*16384;
            #pragma unroll
            for (int kc = 0; kc < 8; kc++) {
                uint32_t afr[4], bfr[8];
                {
                    uint32_t r = 16*wr + (l & 7) + 8*((l >> 3) & 1);
                    uint32_t g = kc*2 + (l >> 4);
                    ldm_x4(afr, abase + r*256 + swz16(r, g));
                }
                #pragma unroll
                for (int p = 0; p < 2; p++) {
                    uint32_t n = 32*wc + 16*p + 8*((l >> 4) & 1) + (l & 7);
                    uint32_t g = kc*2 + ((l >> 3) & 1);
                    ldm_x4(bfr + 4*p, bbase + n*256 + swz16(n, g));
                }
                #pragma unroll
                for (int nt = 0; nt < 4; nt++)
                    mma16816(acc[nt], afr, &bfr[2*nt]);
            }
        }

        float tm0 = -1e30f, tm1 = -1e30f;
        #pragma unroll
        for (int nt = 0; nt < 4; nt++) {
            tm0 = fmaxf(tm0, fmaxf(acc[nt][0], acc[nt][1]));
            tm1 = fmaxf(tm1, fmaxf(acc[nt][2], acc[nt][3]));
        }
        tm0 = fmaxf(tm0, __shfl_xor_sync(0xffffffffu, tm0, 1));
        tm0 = fmaxf(tm0, __shfl_xor_sync(0xffffffffu, tm0, 2));
        tm1 = fmaxf(tm1, __shfl_xor_sync(0xffffffffu, tm1, 1));
        tm1 = fmaxf(tm1, __shfl_xor_sync(0xffffffffu, tm1, 2));
        float mn0 = fmaxf(m0, tm0), mn1 = fmaxf(m1, tm1);
        float rs0 = 0.f, rs1 = 0.f;
        #pragma unroll
        for (int nt = 0; nt < 4; nt++) {
            rs0 += __expf(acc[nt][0] - mn0) + __expf(acc[nt][1] - mn0);
            rs1 += __expf(acc[nt][2] - mn1) + __expf(acc[nt][3] - mn1);
        }
        rs0 += __shfl_xor_sync(0xffffffffu, rs0, 1);
        rs0 += __shfl_xor_sync(0xffffffffu, rs0, 2);
        rs1 += __shfl_xor_sync(0xffffffffu, rs1, 1);
        rs1 += __shfl_xor_sync(0xffffffffu, rs1, 2);
        l0 = l0*__expf(m0 - mn0) + rs0; m0 = mn0;
        l1 = l1*__expf(m1 - mn1) + rs1; m1 = mn1;

        float* dst0 = attn + (rowbase + r0)*Sn + (size_t)jj*64 + 32*wc + 2*(l & 3);
        float* dst1 = attn + (rowbase + r0 + 8)*Sn + (size_t)jj*64 + 32*wc + 2*(l & 3);
        #pragma unroll
        for (int nt = 0; nt < 4; nt++) {
            *(float2*)(dst0 + 8*nt) = make_float2(acc[nt][0], acc[nt][1]);
            *(float2*)(dst1 + 8*nt) = make_float2(acc[nt][2], acc[nt][3]);
        }
    }

    // ---- stats merge in smem ----
    if ((l & 3) == 0) {
        sM[wc*64 + r0]     = m0;  sL[wc*64 + r0]     = l0;
        sM[wc*64 + r0 + 8] = m1;  sL[wc*64 + r0 + 8] = l1;
    }
    __syncthreads();
    if (tid < 64) {
        float ma = sM[tid], mb = sM[64 + tid];
        float mn = fmaxf(ma, mb);
        float lt = sL[tid]*__expf(ma - mn) + sL[64 + tid]*__expf(mb - mn);
        sM[tid] = mn;
        sL[tid] = lt;
    }
    __syncthreads();

    // ---- phase 2: exp + PV (2 products: p_hi*v_hi + p_lo*v_hi) ----
    uint32_t p_s = sb, v_s = sb + 32768;
    int erow = tid >> 2;
    int c0 = (tid & 3) * 16;
    float mv = sM[erow];
    float li = 1.0f / sL[erow];
    __syncthreads();
    uint32_t pst0 = p_s + (uint32_t)erow*128 + swz8((uint32_t)erow, (uint32_t)(c0 >> 3));
    uint32_t pst1 = p_s + (uint32_t)erow*128 + swz8((uint32_t)erow, (uint32_t)(c0 >> 3) + 1);

    // prologue: V(0) half-tile hi split
    {
        const unsigned char* src = g_Vt + (size_t)(b*32)*32768;
        for (int i = tid; i < 1024; i += 256) {
            int r = i >> 3, s8 = i & 7;
            cp16(v_s + r*128 + s8*16, src + (size_t)r*256 + (size_t)s8*16);
        }
        CP_COMMIT();
    }

    float out[8][4];
    #pragma unroll
    for (int nt = 0; nt < 8; nt++)
        #pragma unroll
        for (int c = 0; c < 4; c++) out[nt][c] = 0.f;

    for (int jj = 0; jj < 64; jj++) {
        __syncthreads();

        {
            float* srcp = attn + (rowbase + erow)*Sn + (size_t)jj*64 + c0;
            float p8[8];
            *(float4*)(p8)   = *(const float4*)(srcp);
            *(float4*)(p8+4) = *(const float4*)(srcp + 4);
            #pragma unroll
            for (int x = 0; x < 8; x++) p8[x] = __expf(p8[x] - mv) * li;
            *(float4*)(srcp)     = *(float4*)(p8);
            *(float4*)(srcp + 4) = *(float4*)(p8+4);
            uint4 uh, ul;
            split2h8(p8, uh, ul);
            STS16(pst0, uh);
            STS16(pst0 + 8192, ul);

            *(float4*)(p8)   = *(const float4*)(srcp + 8);
            *(float4*)(p8+4) = *(const float4*)(srcp + 12);
            #pragma unroll
            for (int x = 0; x < 8; x++) p8[x] = __expf(p8[x] - mv) * li;
            *(float4*)(srcp + 8)  = *(float4*)(p8);
            *(float4*)(srcp + 12) = *(float4*)(p8+4);
            split2h8(p8, uh, ul);
            STS16(pst1, uh);
            STS16(pst1 + 8192, ul);
        }

        if (jj + 1 < 64) {
            int jt = (jj+1) >> 1, hf = (jj+1) & 1;
            uint32_t dst = v_s + (uint32_t)(((jj+1) & 1) * 16384);
            const unsigned char* src = g_Vt + (size_t)(b*32 + jt)*32768 + (size_t)hf*128;
            for (int i = tid; i < 1024; i += 256) {
                int r = i >> 3, s8 = i & 7;
                cp16(dst + r*128 + s8*16, src + (size_t)r*256 + (size_t)s8*16);
            }
            CP_COMMIT();
            CP_WAIT(1);
        } else {
            CP_WAIT(0);
        }
        __syncthreads();

        uint32_t vb = v_s + (uint32_t)((jj & 1) * 16384);
        #pragma unroll
        for (int pr = 0; pr < 2; pr++) {
            uint32_t abase = p_s + (uint32_t)pr*8192;
            #pragma unroll
            for (int kc = 0; kc < 4; kc++) {
                uint32_t afr[4], bfr[16];
                {
                    uint32_t r = 16*wr + (l & 7) + 8*((l >> 3) & 1);
                    uint32_t g = kc*2 + (l >> 4);
                    ldm_x4(afr, abase + r*128 + swz8(r, g));
                }
                #pragma unroll
                for (int p = 0; p < 4; p++) {
                    uint32_t n = 64*wc + 16*p + 8*((l >> 4) & 1) + (l & 7);
                    uint32_t g = kc*2 + ((l >> 3) & 1);
                    ldm_x4(bfr + 4*p, vb + n*128 + swz8(n, g));
                }
                #pragma unroll
                for (int nt = 0; nt < 8; nt++)
                    mma16816(out[nt], afr, &bfr[2*nt]);
            }
        }
    }

    // epilogue: out (warp covers 16 rows x 64 dk cols)
    #pragma unroll
    for (int nt = 0; nt < 8; nt++)
        #pragma unroll
        for (int dl = 0; dl < 2; dl++) {
            int row = 16*wr + (l >> 2) + 8*dl;
            float* o = d_out + (rowbase + row)*DKn + 64*wc + 8*nt + 2*(l & 3);
            *(float2*)(o) = make_float2(out[nt][2*dl], out[nt][2*dl+1]);
        }
}

// ---------------- launcher ----------------
extern "C" void kernel_launch(void* const* d_in, const int* in_sizes, int n_in,
                              void* d_out, int out_size) {
    const float* x  = (const float*)d_in[0];
    const float* tp = (const float*)d_in[1];
    const float* Wq = (const float*)d_in[2];
    const float* bq = (const float*)d_in[3];
    const float* Wk = (const float*)d_in[4];
    const float* bk = (const float*)d_in[5];
    const float* Wv = (const float*)d_in[6];
    const float* bv = (const float*)d_in[7];
    const float* Wt = (const float*)d_in[8];
    const float* bt = (const float*)d_in[9];
    float* out = (float*)d_out;

    unsigned char *pxs, *pWs, *pQs, *pKs, *pVt;
    cudaGetSymbolAddress((void**)&pxs,  g_xs);
    cudaGetSymbolAddress((void**)&pWs,  g_Ws);
    cudaGetSymbolAddress((void**)&pQs,  g_Qs);
    cudaGetSymbolAddress((void**)&pKs,  g_Ks);
    cudaGetSymbolAddress((void**)&pVt,  g_Vt);

    cudaFuncSetAttribute((const void*)proj_tc<1>, cudaFuncAttributeMaxDynamicSharedMemorySize, PROJ_SMEM);
    cudaFuncSetAttribute((const void*)proj_tc<2>, cudaFuncAttributeMaxDynamicSharedMemorySize, PROJ_SMEM);
    cudaFuncSetAttribute((const void*)qt_tc,      cudaFuncAttributeMaxDynamicSharedMemorySize, QT_SMEM);
    cudaFuncSetAttribute((const void*)attn_fused, cudaFuncAttributeMaxDynamicSharedMemorySize, ATT_SMEM);

    prep_T_kernel<<<Bn, 256>>>(tp, Wt, bt);
    split_x_kernel<<<8192, 256>>>(x);
    split_W_kernel<<<dim3(16, 3), 256>>>(Wq, Wk, Wv);

    proj_tc<1><<<128, 512, PROJ_SMEM>>>(pxs, XS_SPLIT, 16,
                                        pWs, WS_SPLIT, 0, bq, pQs, SPLIT_SZ);
    proj_tc<1><<<128, 512, PROJ_SMEM>>>(pxs, XS_SPLIT, 16,
                                        pWs + 16*16384, WS_SPLIT, 0, bk, pKs, SPLIT_SZ);
    proj_tc<2><<<128, 512, PROJ_SMEM>>>(pWs + 32*16384, WS_SPLIT, 0,
                                        pxs, XS_SPLIT, 16, bv, pVt, SPLIT_SZ);
    qt_tc<<<dim3(32, Bn), 256, QT_SMEM>>>();

    attn_fused<<<dim3(64, Bn), 256, ATT_SMEM>>>(out);
}

// round 9
// speedup vs baseline: 3.4739x; 1.0253x over previous
#include <cuda_runtime.h>
#include <cuda_fp16.h>
#include <math.h>
#include <stdint.h>

#define Bn 4
#define Sn 4096
#define Dn 1024
#define TPn 16
#define TEn 64
#define DKn 128
#define NTILE 128
#define SPLIT_SZ (NTILE*32768ULL)
#define XS_SPLIT (NTILE*16*16384ULL)
#define WS_SPLIT (3*16*16384ULL)
#define TS_SPLIT (Bn*32768ULL)
#define SCALE 0.08838834764831845f

// ---------------- scratch (2-way fp16 splits; V keeps hi only) ----------------
__device__ __align__(16) unsigned char g_xs [2*XS_SPLIT];
__device__ __align__(16) unsigned char g_Ws [2*WS_SPLIT];
__device__ __align__(16) unsigned char g_Ts [2*TS_SPLIT];
__device__ __align__(16) unsigned char g_Qs [2*SPLIT_SZ];
__device__ __align__(16) unsigned char g_Ks [2*SPLIT_SZ];
__device__ __align__(16) unsigned char g_QTs[2*SPLIT_SZ];
__device__ __align__(16) unsigned char g_Vt [SPLIT_SZ];

// ---------------- helpers ----------------
__device__ __forceinline__ uint32_t smem_u32(const void* p){
    uint32_t a;
    asm("{ .reg .u64 t; cvta.to.shared.u64 t, %1; cvt.u32.u64 %0, t; }" : "=r"(a) : "l"(p));
    return a;
}
__device__ __forceinline__ uint32_t swz16(uint32_t r, uint32_t g){
    return ((g & 8u) | ((g ^ r) & 7u)) << 4;
}
__device__ __forceinline__ uint32_t swz8(uint32_t r, uint32_t g){
    return ((g ^ r) & 7u) << 4;
}
__device__ __forceinline__ void cp16(uint32_t dst, const void* src){
    asm volatile("cp.async.cg.shared.global [%0], [%1], 16;" :: "r"(dst), "l"(src) : "memory");
}
#define CP_COMMIT() asm volatile("cp.async.commit_group;" ::: "memory")
#define CP_WAIT(n)  asm volatile("cp.async.wait_group %0;" :: "n"(n) : "memory")
#define STS16(addr, v) asm volatile("st.shared.v4.b32 [%0], {%1,%2,%3,%4};" \
    :: "r"(addr), "r"((v).x), "r"((v).y), "r"((v).z), "r"((v).w) : "memory")

__device__ __forceinline__ void ldm_x4(uint32_t* r, uint32_t addr){
    asm volatile("ldmatrix.sync.aligned.m8n8.x4.shared.b16 {%0,%1,%2,%3}, [%4];"
        : "=r"(r[0]), "=r"(r[1]), "=r"(r[2]), "=r"(r[3]) : "r"(addr));
}
__device__ __forceinline__ void mma16816(float* d, const uint32_t* a, const uint32_t* b){
    asm volatile("mma.sync.aligned.m16n8k16.row.col.f32.f16.f16.f32 "
        "{%0,%1,%2,%3}, {%4,%5,%6,%7}, {%8,%9}, {%0,%1,%2,%3};"
        : "+f"(d[0]), "+f"(d[1]), "+f"(d[2]), "+f"(d[3])
        : "r"(a[0]), "r"(a[1]), "r"(a[2]), "r"(a[3]), "r"(b[0]), "r"(b[1]));
}
__device__ __forceinline__ uint32_t pk(unsigned short a, unsigned short b){
    return (uint32_t)a | ((uint32_t)b << 16);
}
__device__ __forceinline__ void split2h8(const float* v, uint4& uh, uint4& ul){
    unsigned short h[8], l[8];
    #pragma unroll
    for (int j = 0; j < 8; j++){
        __half hh = __float2half_rn(v[j]);
        __half hl = __float2half_rn(v[j] - __half2float(hh));
        h[j] = __half_as_ushort(hh); l[j] = __half_as_ushort(hl);
    }
    uh = make_uint4(pk(h[0],h[1]), pk(h[2],h[3]), pk(h[4],h[5]), pk(h[6],h[7]));
    ul = make_uint4(pk(l[0],l[1]), pk(l[2],l[3]), pk(l[4],l[5]), pk(l[6],l[7]));
}
__device__ __forceinline__ void packh8(const float* v, uint4& uh){
    unsigned short h[8];
    #pragma unroll
    for (int j = 0; j < 8; j++) h[j] = __half_as_ushort(__float2half_rn(v[j]));
    uh = make_uint4(pk(h[0],h[1]), pk(h[2],h[3]), pk(h[4],h[5]), pk(h[6],h[7]));
}

// ---------------- kernel 1: T_scaled (x SCALE) -> 2-split fp16 blobs ----------------
__global__ void prep_T_kernel(const float* __restrict__ tp,
                              const float* __restrict__ Wt,
                              const float* __restrict__ bt) {
    __shared__ float sTP[TPn*TEn];
    __shared__ float sWt[TEn*DKn];
    __shared__ float sE [TPn*DKn];
    __shared__ float red[256];
    int b = blockIdx.x, tid = threadIdx.x;
    for (int i = tid; i < TPn*TEn; i += 256) sTP[i] = tp[b*TPn*TEn + i];
    for (int i = tid; i < TEn*DKn; i += 256) sWt[i] = Wt[i];
    __syncthreads();
    for (int i = tid; i < TPn*DKn; i += 256) {
        int t = i >> 7, d = i & 127;
        float acc = bt[d];
        #pragma unroll 8
        for (int e = 0; e < TEn; e++) acc += sTP[t*TEn + e] * sWt[e*DKn + d];
        sE[i] = acc;
    }
    __syncthreads();
    float ss = 0.f;
    for (int i = tid; i < TPn*DKn; i += 256) ss += sE[i]*sE[i];
    red[tid] = ss; __syncthreads();
    for (int off = 128; off > 0; off >>= 1) {
        if (tid < off) red[tid] += red[tid+off];
        __syncthreads();
    }
    float tn = sqrtf((float)Sn * red[0]);
    float sc = (float)Sn / (tn + 1e-8f) * SCALE;
    for (int i = tid; i < DKn*DKn; i += 256) {
        int d = i >> 7, e2 = i & 127;
        float acc = 0.f;
        #pragma unroll
        for (int t = 0; t < TPn; t++) acc += sE[t*DKn + d] * sE[t*DKn + e2];
        float v = acc * sc;
        __half hh = __float2half_rn(v);
        __half hl = __float2half_rn(v - __half2float(hh));
        size_t base = (size_t)b*32768 + (size_t)d*256 + swz16((uint32_t)d, (uint32_t)(e2 >> 3)) + (size_t)(e2 & 7)*2;
        *(__half*)(g_Ts + base)            = hh;
        *(__half*)(g_Ts + TS_SPLIT + base) = hl;
    }
}

// ---------------- kernel 2: split x -> 2-split fp16 blobs ----------------
__global__ void split_x_kernel(const float* __restrict__ x) {
    int gidx = blockIdx.x*256 + threadIdx.x;
    int rt = gidx >> 7, gk = gidx & 127;
    int kc = gk >> 3, g = gk & 7;
    const float* src = x + (size_t)rt*Dn + kc*64 + g*8;
    float v[8];
    *(float4*)(v)   = *(const float4*)(src);
    *(float4*)(v+4) = *(const float4*)(src + 4);
    uint4 uh, ul;
    split2h8(v, uh, ul);
    int tile = rt >> 7, r = rt & 127;
    size_t off = (size_t)(tile*16 + kc)*16384 + (size_t)r*128 + swz8((uint32_t)r, (uint32_t)g);
    *(uint4*)(g_xs + off)            = uh;
    *(uint4*)(g_xs + XS_SPLIT + off) = ul;
}

// ---------------- kernel 3: split W^T -> 2-split fp16 blobs ----------------
__global__ void split_W_kernel(const float* __restrict__ Wq,
                               const float* __restrict__ Wk,
                               const float* __restrict__ Wv) {
    __shared__ float sW[64*128];
    int kc = blockIdx.x, mat = blockIdx.y, tid = threadIdx.x;
    const float* W = (mat == 0) ? Wq : ((mat == 1) ? Wk : Wv);
    for (int i = tid; i < 2048; i += 256)
        ((float4*)sW)[i] = ((const float4*)(W + (size_t)kc*64*128))[i];
    __syncthreads();
    for (int it = 0; it < 4; it++) {
        int gi = tid + it*256;
        int d = gi >> 3, g = gi & 7;
        float v[8];
        #pragma unroll
        for (int j = 0; j < 8; j++) v[j] = sW[(g*8 + j)*128 + d];
        uint4 uh, ul;
        split2h8(v, uh, ul);
        size_t off = (size_t)(mat*16 + kc)*16384 + (size_t)d*128 + swz8((uint32_t)d, (uint32_t)g);
        *(uint4*)(g_Ws + off)            = uh;
        *(uint4*)(g_Ws + WS_SPLIT + off) = ul;
    }
}

// ---------------- kernel 4: fused QKV projection GEMM, grid (128, 3) ----------------
#define PROJ_SMEM (2*65536)
__global__ void __launch_bounds__(512,1)
proj_tc(const float* __restrict__ bq, const float* __restrict__ bk,
        const float* __restrict__ bv) {
    extern __shared__ unsigned char sm[];
    uint32_t sb = smem_u32(sm);
    int tid = threadIdx.x, w = tid >> 5, l = tid & 31;
    int wrow = w >> 1, wcol = w & 1;
    int tile = blockIdx.x, mat = blockIdx.y;

    // per-mat operand table
    const unsigned char* Ab;  size_t Asplit;  int aStride, aB0;
    const unsigned char* Bb;  size_t Bsplit;  int bStride, bB0;
    const float* bias;        unsigned char* Out;  int vmode;
    if (mat == 0) {
        Ab = g_xs; Asplit = XS_SPLIT; aStride = 16;
        Bb = g_Ws; Bsplit = WS_SPLIT; bStride = 0;
        bias = bq; Out = g_Qs; vmode = 0;
    } else if (mat == 1) {
        Ab = g_xs; Asplit = XS_SPLIT; aStride = 16;
        Bb = g_Ws + 16*16384; Bsplit = WS_SPLIT; bStride = 0;
        bias = bk; Out = g_Ks; vmode = 0;
    } else {
        Ab = g_Ws + 32*16384; Asplit = WS_SPLIT; aStride = 0;
        Bb = g_xs; Bsplit = XS_SPLIT; bStride = 16;
        bias = bv; Out = g_Vt; vmode = 1;
    }
    aB0 = tile * aStride; bB0 = tile * bStride;
    const int pa[3] = {0,0,1};
    const int pb[3] = {0,1,0};

    float acc[8][4];
    #pragma unroll
    for (int nt = 0; nt < 8; nt++)
        #pragma unroll
        for (int c = 0; c < 4; c++) acc[nt][c] = 0.f;

    uint32_t stg[2] = {sb, sb + 65536};
    #pragma unroll
    for (int sp = 0; sp < 2; sp++) {
        const unsigned char* sa = Ab + (size_t)sp*Asplit + (size_t)(aB0 + 0)*16384;
        const unsigned char* sv = Bb + (size_t)sp*Bsplit + (size_t)(bB0 + 0)*16384;
        for (int i = tid; i < 1024; i += 512) {
            cp16(stg[0] + sp*16384 + i*16, sa + (size_t)i*16);
            cp16(stg[0] + 32768 + sp*16384 + i*16, sv + (size_t)i*16);
        }
    }
    CP_COMMIT();

    for (int kc = 0; kc < 16; kc++) {
        __syncthreads();
        if (kc + 1 < 16) {
            uint32_t dst = stg[(kc+1) & 1];
            #pragma unroll
            for (int sp = 0; sp < 2; sp++) {
                const unsigned char* sa = Ab + (size_t)sp*Asplit + (size_t)(aB0 + kc + 1)*16384;
                const unsigned char* sv = Bb + (size_t)sp*Bsplit + (size_t)(bB0 + kc + 1)*16384;
                for (int i = tid; i < 1024; i += 512) {
                    cp16(dst + sp*16384 + i*16, sa + (size_t)i*16);
                    cp16(dst + 32768 + sp*16384 + i*16, sv + (size_t)i*16);
                }
            }
            CP_COMMIT();
            CP_WAIT(1);
        } else {
            CP_WAIT(0);
        }
        __syncthreads();

        uint32_t a0 = stg[kc & 1], b0 = stg[kc & 1] + 32768;
        #pragma unroll
        for (int pr = 0; pr < 3; pr++) {
            uint32_t abase = a0 + (uint32_t)pa[pr]*16384;
            uint32_t bbase = b0 + (uint32_t)pb[pr]*16384;
            #pragma unroll
            for (int ks = 0; ks < 4; ks++) {
                uint32_t afr[4], bfr[16];
                {
                    uint32_t r = 16*wrow + (l & 7) + 8*((l >> 3) & 1);
                    uint32_t g = ks*2 + (l >> 4);
                    ldm_x4(afr, abase + r*128 + swz8(r, g));
                }
                #pragma unroll
                for (int p = 0; p < 4; p++) {
                    uint32_t n = 64*wcol + 16*p + 8*((l >> 4) & 1) + (l & 7);
                    uint32_t g = ks*2 + ((l >> 3) & 1);
                    ldm_x4(bfr + 4*p, bbase + n*128 + swz8(n, g));
                }
                #pragma unroll
                for (int nt = 0; nt < 8; nt++)
                    mma16816(acc[nt], afr, &bfr[2*nt]);
            }
        }
    }

    __syncthreads();
    float* sOut = (float*)sm;
    #pragma unroll
    for (int nt = 0; nt < 8; nt++) {
        int colb = 64*wcol + 8*nt + 2*(l & 3);
        int r0 = 16*wrow + (l >> 2);
        sOut[r0*132 + colb]       = acc[nt][0];
        sOut[r0*132 + colb + 1]   = acc[nt][1];
        sOut[(r0+8)*132 + colb]   = acc[nt][2];
        sOut[(r0+8)*132 + colb+1] = acc[nt][3];
    }
    __syncthreads();
    int tr = tid >> 4, tc = tid & 15;
    if (!vmode) {
        float bvv[8];
        *(float4*)(bvv)   = *(const float4*)(bias + 8*tc);
        *(float4*)(bvv+4) = *(const float4*)(bias + 8*tc + 4);
        #pragma unroll
        for (int i = 0; i < 4; i++) {
            int row = 4*tr + i;
            float v[8];
            #pragma unroll
            for (int j = 0; j < 8; j++) v[j] = sOut[row*132 + 8*tc + j] + bvv[j];
            uint4 uh, ul;
            split2h8(v, uh, ul);
            size_t base = (size_t)tile*32768 + (size_t)row*256 + swz16((uint32_t)row, (uint32_t)tc);
            *(uint4*)(Out + base)            = uh;
            *(uint4*)(Out + SPLIT_SZ + base) = ul;
        }
    } else {
        #pragma unroll
        for (int i = 0; i < 4; i++) {
            int d = 4*tr + i;
            float bd = bias[d];
            float v[8];
            #pragma unroll
            for (int j = 0; j < 8; j++) v[j] = sOut[d*132 + 8*tc + j] + bd;
            uint4 uh;
            packh8(v, uh);
            size_t base = (size_t)tile*32768 + (size_t)d*256 + swz16((uint32_t)d, (uint32_t)tc);
            *(uint4*)(Out + base) = uh;
        }
    }
}

// ---------------- kernel 5: QT = Qs @ Ts (K=128, 3 products) ----------------
#define QT_SMEM (2*65536)
__global__ void __launch_bounds__(256,1) qt_tc() {
    extern __shared__ unsigned char sm[];
    uint32_t sb = smem_u32(sm);
    int tid = threadIdx.x, w = tid >> 5, l = tid & 31;
    int b = blockIdx.y, rb = blockIdx.x, tile = b*32 + rb;
    const int pa[3] = {0,0,1};
    const int pb[3] = {0,1,0};

    #pragma unroll
    for (int sp = 0; sp < 2; sp++) {
        const unsigned char* sa = g_Qs + (size_t)sp*SPLIT_SZ + (size_t)tile*32768;
        const unsigned char* st = g_Ts + (size_t)sp*TS_SPLIT + (size_t)b*32768;
        for (int i = tid; i < 2048; i += 256) {
            cp16(sb + sp*32768 + i*16, sa + (size_t)i*16);
            cp16(sb + 65536 + sp*32768 + i*16, st + (size_t)i*16);
        }
    }
    CP_COMMIT();
    CP_WAIT(0);
    __syncthreads();

    float acc[16][4];
    #pragma unroll
    for (int nt = 0; nt < 16; nt++)
        #pragma unroll
        for (int c = 0; c < 4; c++) acc[nt][c] = 0.f;

    #pragma unroll
    for (int pr = 0; pr < 3; pr++) {
        uint32_t abase = sb + (uint32_t)pa[pr]*32768;
        uint32_t bbase = sb + 65536 + (uint32_t)pb[pr]*32768;
        #pragma unroll
        for (int ks = 0; ks < 8; ks++) {
            uint32_t afr[4], bfr[32];
            {
                uint32_t r = 16*w + (l & 7) + 8*((l >> 3) & 1);
                uint32_t g = ks*2 + (l >> 4);
                ldm_x4(afr, abase + r*256 + swz16(r, g));
            }
            #pragma unroll
            for (int p = 0; p < 8; p++) {
                uint32_t n = 16*p + 8*((l >> 4) & 1) + (l & 7);
                uint32_t g = ks*2 + ((l >> 3) & 1);
                ldm_x4(bfr + 4*p, bbase + n*256 + swz16(n, g));
            }
            #pragma unroll
            for (int nt = 0; nt < 16; nt++)
                mma16816(acc[nt], afr, &bfr[2*nt]);
        }
    }

    __syncthreads();
    float* sOut = (float*)sm;
    #pragma unroll
    for (int nt = 0; nt < 16; nt++) {
        int colb = 8*nt + 2*(l & 3);
        int r0 = 16*w + (l >> 2);
        sOut[r0*132 + colb]       = acc[nt][0];
        sOut[r0*132 + colb + 1]   = acc[nt][1];
        sOut[(r0+8)*132 + colb]   = acc[nt][2];
        sOut[(r0+8)*132 + colb+1] = acc[nt][3];
    }
    __syncthreads();
    int tr = tid >> 4, tc = tid & 15;
    #pragma unroll
    for (int i = 0; i < 8; i++) {
        int row = 8*tr + i;
        float v[8];
        #pragma unroll
        for (int j = 0; j < 8; j++) v[j] = sOut[row*132 + 8*tc + j];
        uint4 uh, ul;
        split2h8(v, uh, ul);
        size_t base = (size_t)tile*32768 + (size_t)row*256 + swz16((uint32_t)row, (uint32_t)tc);
        *(uint4*)(g_QTs + base)            = uh;
        *(uint4*)(g_QTs + SPLIT_SZ + base) = ul;
    }
}

// ---------------- fused attention: phase1 scores+stats, phase2 exp + PV(1 product) ----------------
#define ATT_SMEM (32768 + 65536 + 1024)
__global__ void __launch_bounds__(256,2) attn_fused(float* __restrict__ d_out) {
    extern __shared__ unsigned char sm[];
    uint32_t sb = smem_u32(sm);
    uint32_t qt_s = sb, k_s = sb + 32768;
    float* sM = (float*)(sm + 98304);
    float* sL = sM + 128;

    int tid = threadIdx.x, w = tid >> 5, l = tid & 31;
    int b = blockIdx.y, bx = blockIdx.x;
    int wr = w >> 1, wc = w & 1;
    float* attn = d_out + (size_t)Bn*Sn*DKn;
    size_t rowbase = (size_t)b*Sn + (size_t)bx*64;

    // ---- phase 1 prologue ----
    size_t qoff = (size_t)(b*32 + (bx >> 1))*32768 + (size_t)(bx & 1)*16384;
    #pragma unroll
    for (int sp = 0; sp < 2; sp++) {
        const unsigned char* srcq = g_QTs + (size_t)sp*SPLIT_SZ + qoff;
        const unsigned char* srck = g_Ks + (size_t)sp*SPLIT_SZ + (size_t)(b*32)*32768;
        for (int i = tid; i < 1024; i += 256) {
            cp16(qt_s + sp*16384 + i*16, srcq + (size_t)i*16);
            cp16(k_s + sp*16384 + i*16, srck + (size_t)i*16);
        }
    }
    CP_COMMIT();

    const int pa[3] = {0,0,1};
    const int pb[3] = {0,1,0};
    int r0 = 16*wr + (l >> 2);
    float m0 = -1e30f, l0 = 0.f, m1 = -1e30f, l1 = 0.f;

    for (int jj = 0; jj < 64; jj++) {
        __syncthreads();
        if (jj + 1 < 64) {
            int jt = (jj+1) >> 1, hf = (jj+1) & 1;
            uint32_t dst = k_s + (uint32_t)(((jj+1) & 1) * 32768);
            #pragma unroll
            for (int sp = 0; sp < 2; sp++) {
                const unsigned char* src = g_Ks + (size_t)sp*SPLIT_SZ
                    + (size_t)(b*32 + jt)*32768 + (size_t)hf*16384;
                for (int i = tid; i < 1024; i += 256) cp16(dst + sp*16384 + i*16, src + (size_t)i*16);
            }
            CP_COMMIT();
            CP_WAIT(1);
        } else {
            CP_WAIT(0);
        }
        __syncthreads();

        uint32_t kb = k_s + (uint32_t)((jj & 1) * 32768);
        float acc[4][4];
        #pragma unroll
        for (int nt = 0; nt < 4; nt++)
            #pragma unroll
            for (int c = 0; c < 4; c++) acc[nt][c] = 0.f;

        #pragma unroll
        for (int pr = 0; pr < 3; pr++) {
            uint32_t abase = qt_s + (uint32_t)pa[pr]*16384;
            uint32_t bbase = kb + (uint32_t)pb[pr]*16384;
            #pragma unroll
            for (int kc = 0; kc < 8; kc++) {
                uint32_t afr[4], bfr[8];
                {
                    uint32_t r = 16*wr + (l & 7) + 8*((l >> 3) & 1);
                    uint32_t g = kc*2 + (l >> 4);
                    ldm_x4(afr, abase + r*256 + swz16(r, g));
                }
                #pragma unroll
                for (int p = 0; p < 2; p++) {
                    uint32_t n = 32*wc + 16*p + 8*((l >> 4) & 1) + (l & 7);
                    uint32_t g = kc*2 + ((l >> 3) & 1);
                    ldm_x4(bfr + 4*p, bbase + n*256 + swz16(n, g));
                }
                #pragma unroll
                for (int nt = 0; nt < 4; nt++)
                    mma16816(acc[nt], afr, &bfr[2*nt]);
            }
        }

        float tm0 = -1e30f, tm1 = -1e30f;
        #pragma unroll
        for (int nt = 0; nt < 4; nt++) {
            tm0 = fmaxf(tm0, fmaxf(acc[nt][0], acc[nt][1]));
            tm1 = fmaxf(tm1, fmaxf(acc[nt][2], acc[nt][3]));
        }
        tm0 = fmaxf(tm0, __shfl_xor_sync(0xffffffffu, tm0, 1));
        tm0 = fmaxf(tm0, __shfl_xor_sync(0xffffffffu, tm0, 2));
        tm1 = fmaxf(tm1, __shfl_xor_sync(0xffffffffu, tm1, 1));
        tm1 = fmaxf(tm1, __shfl_xor_sync(0xffffffffu, tm1, 2));
        float mn0 = fmaxf(m0, tm0), mn1 = fmaxf(m1, tm1);
        float rs0 = 0.f, rs1 = 0.f;
        #pragma unroll
        for (int nt = 0; nt < 4; nt++) {
            rs0 += __expf(acc[nt][0] - mn0) + __expf(acc[nt][1] - mn0);
            rs1 += __expf(acc[nt][2] - mn1) + __expf(acc[nt][3] - mn1);
        }
        rs0 += __shfl_xor_sync(0xffffffffu, rs0, 1);
        rs0 += __shfl_xor_sync(0xffffffffu, rs0, 2);
        rs1 += __shfl_xor_sync(0xffffffffu, rs1, 1);
        rs1 += __shfl_xor_sync(0xffffffffu, rs1, 2);
        l0 = l0*__expf(m0 - mn0) + rs0; m0 = mn0;
        l1 = l1*__expf(m1 - mn1) + rs1; m1 = mn1;

        float* dst0 = attn + (rowbase + r0)*Sn + (size_t)jj*64 + 32*wc + 2*(l & 3);
        float* dst1 = attn + (rowbase + r0 + 8)*Sn + (size_t)jj*64 + 32*wc + 2*(l & 3);
        #pragma unroll
        for (int nt = 0; nt < 4; nt++) {
            *(float2*)(dst0 + 8*nt) = make_float2(acc[nt][0], acc[nt][1]);
            *(float2*)(dst1 + 8*nt) = make_float2(acc[nt][2], acc[nt][3]);
        }
    }

    // ---- stats merge in smem ----
    if ((l & 3) == 0) {
        sM[wc*64 + r0]     = m0;  sL[wc*64 + r0]     = l0;
        sM[wc*64 + r0 + 8] = m1;  sL[wc*64 + r0 + 8] = l1;
    }
    __syncthreads();
    if (tid < 64) {
        float ma = sM[tid], mb = sM[64 + tid];
        float mn = fmaxf(ma, mb);
        float lt = sL[tid]*__expf(ma - mn) + sL[64 + tid]*__expf(mb - mn);
        sM[tid] = mn;
        sL[tid] = lt;
    }
    __syncthreads();

    // ---- phase 2: exp + PV, single product p_hi * v_hi ----
    uint32_t p_s = sb, v_s = sb + 32768;
    int erow = tid >> 2;
    int c0 = (tid & 3) * 16;
    float mv = sM[erow];
    float li = 1.0f / sL[erow];
    __syncthreads();
    uint32_t pst0 = p_s + (uint32_t)erow*128 + swz8((uint32_t)erow, (uint32_t)(c0 >> 3));
    uint32_t pst1 = p_s + (uint32_t)erow*128 + swz8((uint32_t)erow, (uint32_t)(c0 >> 3) + 1);

    {
        const unsigned char* src = g_Vt + (size_t)(b*32)*32768;
        for (int i = tid; i < 1024; i += 256) {
            int r = i >> 3, s8 = i & 7;
            cp16(v_s + r*128 + s8*16, src + (size_t)r*256 + (size_t)s8*16);
        }
        CP_COMMIT();
    }

    float out[8][4];
    #pragma unroll
    for (int nt = 0; nt < 8; nt++)
        #pragma unroll
        for (int c = 0; c < 4; c++) out[nt][c] = 0.f;

    for (int jj = 0; jj < 64; jj++) {
        __syncthreads();

        {
            float* srcp = attn + (rowbase + erow)*Sn + (size_t)jj*64 + c0;
            float p8[8];
            *(float4*)(p8)   = *(const float4*)(srcp);
            *(float4*)(p8+4) = *(const float4*)(srcp + 4);
            #pragma unroll
            for (int x = 0; x < 8; x++) p8[x] = __expf(p8[x] - mv) * li;
            *(float4*)(srcp)     = *(float4*)(p8);
            *(float4*)(srcp + 4) = *(float4*)(p8+4);
            uint4 uh;
            packh8(p8, uh);
            STS16(pst0, uh);

            *(float4*)(p8)   = *(const float4*)(srcp + 8);
            *(float4*)(p8+4) = *(const float4*)(srcp + 12);
            #pragma unroll
            for (int x = 0; x < 8; x++) p8[x] = __expf(p8[x] - mv) * li;
            *(float4*)(srcp + 8)  = *(float4*)(p8);
            *(float4*)(srcp + 12) = *(float4*)(p8+4);
            packh8(p8, uh);
            STS16(pst1, uh);
        }

        if (jj + 1 < 64) {
            int jt = (jj+1) >> 1, hf = (jj+1) & 1;
            uint32_t dst = v_s + (uint32_t)(((jj+1) & 1) * 16384);
            const unsigned char* src = g_Vt + (size_t)(b*32 + jt)*32768 + (size_t)hf*128;
            for (int i = tid; i < 1024; i += 256) {
                int r = i >> 3, s8 = i & 7;
                cp16(dst + r*128 + s8*16, src + (size_t)r*256 + (size_t)s8*16);
            }
            CP_COMMIT();
            CP_WAIT(1);
        } else {
            CP_WAIT(0);
        }
        __syncthreads();

        uint32_t vb = v_s + (uint32_t)((jj & 1) * 16384);
        #pragma unroll
        for (int kc = 0; kc < 4; kc++) {
            uint32_t afr[4], bfr[16];
            {
                uint32_t r = 16*wr + (l & 7) + 8*((l >> 3) & 1);
                uint32_t g = kc*2 + (l >> 4);
                ldm_x4(afr, p_s + r*128 + swz8(r, g));
            }
            #pragma unroll
            for (int p = 0; p < 4; p++) {
                uint32_t n = 64*wc + 16*p + 8*((l >> 4) & 1) + (l & 7);
                uint32_t g = kc*2 + ((l >> 3) & 1);
                ldm_x4(bfr + 4*p, vb + n*128 + swz8(n, g));
            }
            #pragma unroll
            for (int nt = 0; nt < 8; nt++)
                mma16816(out[nt], afr, &bfr[2*nt]);
        }
    }

    // epilogue
    #pragma unroll
    for (int nt = 0; nt < 8; nt++)
        #pragma unroll
        for (int dl = 0; dl < 2; dl++) {
            int row = 16*wr + (l >> 2) + 8*dl;
            float* o = d_out + (rowbase + row)*DKn + 64*wc + 8*nt + 2*(l & 3);
            *(float2*)(o) = make_float2(out[nt][2*dl], out[nt][2*dl+1]);
        }
}

// ---------------- launcher ----------------
extern "C" void kernel_launch(void* const* d_in, const int* in_sizes, int n_in,
                              void* d_out, int out_size) {
    const float* x  = (const float*)d_in[0];
    const float* tp = (const float*)d_in[1];
    const float* bq = (const float*)d_in[3];
    const float* bk = (const float*)d_in[5];
    const float* bv = (const float*)d_in[7];
    const float* Wq = (const float*)d_in[2];
    const float* Wk = (const float*)d_in[4];
    const float* Wv = (const float*)d_in[6];
    const float* Wt = (const float*)d_in[8];
    const float* bt = (const float*)d_in[9];
    float* out = (float*)d_out;

    cudaFuncSetAttribute((const void*)proj_tc,    cudaFuncAttributeMaxDynamicSharedMemorySize, PROJ_SMEM);
    cudaFuncSetAttribute((const void*)qt_tc,      cudaFuncAttributeMaxDynamicSharedMemorySize, QT_SMEM);
    cudaFuncSetAttribute((const void*)attn_fused, cudaFuncAttributeMaxDynamicSharedMemorySize, ATT_SMEM);

    prep_T_kernel<<<Bn, 256>>>(tp, Wt, bt);
    split_x_kernel<<<8192, 256>>>(x);
    split_W_kernel<<<dim3(16, 3), 256>>>(Wq, Wk, Wv);

    proj_tc<<<dim3(128, 3), 512, PROJ_SMEM>>>(bq, bk, bv);
    qt_tc<<<dim3(32, Bn), 256, QT_SMEM>>>();

    attn_fused<<<dim3(64, Bn), 256, ATT_SMEM>>>(out);
}

// round 10
// speedup vs baseline: 3.7950x; 1.0925x over previous
#include <cuda_runtime.h>
#include <cuda_fp16.h>
#include <math.h>
#include <stdint.h>

#define Bn 4
#define Sn 4096
#define Dn 1024
#define TPn 16
#define TEn 64
#define DKn 128
#define NTILE 128
#define SPLIT_SZ (NTILE*32768ULL)
#define XS_SPLIT (NTILE*16*16384ULL)
#define WS_SPLIT (3*16*16384ULL)
#define TS_SPLIT (Bn*32768ULL)
#define SCALE 0.08838834764831845f

// ---------------- scratch (2-way fp16 splits; V keeps hi only) ----------------
__device__ __align__(16) unsigned char g_xs [2*XS_SPLIT];
__device__ __align__(16) unsigned char g_Ws [2*WS_SPLIT];
__device__ __align__(16) unsigned char g_Ts [2*TS_SPLIT];
__device__ __align__(16) unsigned char g_Qs [2*SPLIT_SZ];
__device__ __align__(16) unsigned char g_Ks [2*SPLIT_SZ];
__device__ __align__(16) unsigned char g_QTs[2*SPLIT_SZ];
__device__ __align__(16) unsigned char g_Vt [SPLIT_SZ];

// ---------------- helpers ----------------
__device__ __forceinline__ uint32_t smem_u32(const void* p){
    uint32_t a;
    asm("{ .reg .u64 t; cvta.to.shared.u64 t, %1; cvt.u32.u64 %0, t; }" : "=r"(a) : "l"(p));
    return a;
}
__device__ __forceinline__ uint32_t swz16(uint32_t r, uint32_t g){
    return ((g & 8u) | ((g ^ r) & 7u)) << 4;
}
__device__ __forceinline__ uint32_t swz8(uint32_t r, uint32_t g){
    return ((g ^ r) & 7u) << 4;
}
__device__ __forceinline__ void cp16(uint32_t dst, const void* src){
    asm volatile("cp.async.cg.shared.global [%0], [%1], 16;" :: "r"(dst), "l"(src) : "memory");
}
#define CP_COMMIT() asm volatile("cp.async.commit_group;" ::: "memory")
#define CP_WAIT(n)  asm volatile("cp.async.wait_group %0;" :: "n"(n) : "memory")
#define STS16(addr, v) asm volatile("st.shared.v4.b32 [%0], {%1,%2,%3,%4};" \
    :: "r"(addr), "r"((v).x), "r"((v).y), "r"((v).z), "r"((v).w) : "memory")

__device__ __forceinline__ void ldm_x4(uint32_t* r, uint32_t addr){
    asm volatile("ldmatrix.sync.aligned.m8n8.x4.shared.b16 {%0,%1,%2,%3}, [%4];"
        : "=r"(r[0]), "=r"(r[1]), "=r"(r[2]), "=r"(r[3]) : "r"(addr));
}
__device__ __forceinline__ void mma16816(float* d, const uint32_t* a, const uint32_t* b){
    asm volatile("mma.sync.aligned.m16n8k16.row.col.f32.f16.f16.f32 "
        "{%0,%1,%2,%3}, {%4,%5,%6,%7}, {%8,%9}, {%0,%1,%2,%3};"
        : "+f"(d[0]), "+f"(d[1]), "+f"(d[2]), "+f"(d[3])
        : "r"(a[0]), "r"(a[1]), "r"(a[2]), "r"(a[3]), "r"(b[0]), "r"(b[1]));
}
__device__ __forceinline__ uint32_t pk(unsigned short a, unsigned short b){
    return (uint32_t)a | ((uint32_t)b << 16);
}
__device__ __forceinline__ void split2h8(const float* v, uint4& uh, uint4& ul){
    unsigned short h[8], l[8];
    #pragma unroll
    for (int j = 0; j < 8; j++){
        __half hh = __float2half_rn(v[j]);
        __half hl = __float2half_rn(v[j] - __half2float(hh));
        h[j] = __half_as_ushort(hh); l[j] = __half_as_ushort(hl);
    }
    uh = make_uint4(pk(h[0],h[1]), pk(h[2],h[3]), pk(h[4],h[5]), pk(h[6],h[7]));
    ul = make_uint4(pk(l[0],l[1]), pk(l[2],l[3]), pk(l[4],l[5]), pk(l[6],l[7]));
}
__device__ __forceinline__ void packh8(const float* v, uint4& uh){
    unsigned short h[8];
    #pragma unroll
    for (int j = 0; j < 8; j++) h[j] = __half_as_ushort(__float2half_rn(v[j]));
    uh = make_uint4(pk(h[0],h[1]), pk(h[2],h[3]), pk(h[4],h[5]), pk(h[6],h[7]));
}

// ---------------- kernel 1: T_scaled (x SCALE) -> 2-split fp16 blobs ----------------
__global__ void prep_T_kernel(const float* __restrict__ tp,
                              const float* __restrict__ Wt,
                              const float* __restrict__ bt) {
    __shared__ float sTP[TPn*TEn];
    __shared__ float sWt[TEn*DKn];
    __shared__ float sE [TPn*DKn];
    __shared__ float red[256];
    int b = blockIdx.x, tid = threadIdx.x;
    for (int i = tid; i < TPn*TEn; i += 256) sTP[i] = tp[b*TPn*TEn + i];
    for (int i = tid; i < TEn*DKn; i += 256) sWt[i] = Wt[i];
    __syncthreads();
    for (int i = tid; i < TPn*DKn; i += 256) {
        int t = i >> 7, d = i & 127;
        float acc = bt[d];
        #pragma unroll 8
        for (int e = 0; e < TEn; e++) acc += sTP[t*TEn + e] * sWt[e*DKn + d];
        sE[i] = acc;
    }
    __syncthreads();
    float ss = 0.f;
    for (int i = tid; i < TPn*DKn; i += 256) ss += sE[i]*sE[i];
    red[tid] = ss; __syncthreads();
    for (int off = 128; off > 0; off >>= 1) {
        if (tid < off) red[tid] += red[tid+off];
        __syncthreads();
    }
    float tn = sqrtf((float)Sn * red[0]);
    float sc = (float)Sn / (tn + 1e-8f) * SCALE;
    for (int i = tid; i < DKn*DKn; i += 256) {
        int d = i >> 7, e2 = i & 127;
        float acc = 0.f;
        #pragma unroll
        for (int t = 0; t < TPn; t++) acc += sE[t*DKn + d] * sE[t*DKn + e2];
        float v = acc * sc;
        __half hh = __float2half_rn(v);
        __half hl = __float2half_rn(v - __half2float(hh));
        size_t base = (size_t)b*32768 + (size_t)d*256 + swz16((uint32_t)d, (uint32_t)(e2 >> 3)) + (size_t)(e2 & 7)*2;
        *(__half*)(g_Ts + base)            = hh;
        *(__half*)(g_Ts + TS_SPLIT + base) = hl;
    }
}

// ---------------- kernel 2: split x -> 2-split fp16 blobs ----------------
__global__ void split_x_kernel(const float* __restrict__ x) {
    int gidx = blockIdx.x*256 + threadIdx.x;
    int rt = gidx >> 7, gk = gidx & 127;
    int kc = gk >> 3, g = gk & 7;
    const float* src = x + (size_t)rt*Dn + kc*64 + g*8;
    float v[8];
    *(float4*)(v)   = *(const float4*)(src);
    *(float4*)(v+4) = *(const float4*)(src + 4);
    uint4 uh, ul;
    split2h8(v, uh, ul);
    int tile = rt >> 7, r = rt & 127;
    size_t off = (size_t)(tile*16 + kc)*16384 + (size_t)r*128 + swz8((uint32_t)r, (uint32_t)g);
    *(uint4*)(g_xs + off)            = uh;
    *(uint4*)(g_xs + XS_SPLIT + off) = ul;
}

// ---------------- kernel 3: split W^T -> 2-split fp16 blobs ----------------
__global__ void split_W_kernel(const float* __restrict__ Wq,
                               const float* __restrict__ Wk,
                               const float* __restrict__ Wv) {
    __shared__ float sW[64*128];
    int kc = blockIdx.x, mat = blockIdx.y, tid = threadIdx.x;
    const float* W = (mat == 0) ? Wq : ((mat == 1) ? Wk : Wv);
    for (int i = tid; i < 2048; i += 256)
        ((float4*)sW)[i] = ((const float4*)(W + (size_t)kc*64*128))[i];
    __syncthreads();
    for (int it = 0; it < 4; it++) {
        int gi = tid + it*256;
        int d = gi >> 3, g = gi & 7;
        float v[8];
        #pragma unroll
        for (int j = 0; j < 8; j++) v[j] = sW[(g*8 + j)*128 + d];
        uint4 uh, ul;
        split2h8(v, uh, ul);
        size_t off = (size_t)(mat*16 + kc)*16384 + (size_t)d*128 + swz8((uint32_t)d, (uint32_t)g);
        *(uint4*)(g_Ws + off)            = uh;
        *(uint4*)(g_Ws + WS_SPLIT + off) = ul;
    }
}

// ---------------- kernel 4: fused QKV projection GEMM, shared fragment loads ----------------
#define PROJ_SMEM (2*65536)
__global__ void __launch_bounds__(512,1)
proj_tc(const float* __restrict__ bq, const float* __restrict__ bk,
        const float* __restrict__ bv) {
    extern __shared__ unsigned char sm[];
    uint32_t sb = smem_u32(sm);
    int tid = threadIdx.x, w = tid >> 5, l = tid & 31;
    int wrow = w >> 1, wcol = w & 1;
    int tile = blockIdx.x, mat = blockIdx.y;

    const unsigned char* Ab;  size_t Asplit;  int aStride, aB0;
    const unsigned char* Bb;  size_t Bsplit;  int bStride, bB0;
    const float* bias;        unsigned char* Out;  int vmode;
    if (mat == 0) {
        Ab = g_xs; Asplit = XS_SPLIT; aStride = 16;
        Bb = g_Ws; Bsplit = WS_SPLIT; bStride = 0;
        bias = bq; Out = g_Qs; vmode = 0;
    } else if (mat == 1) {
        Ab = g_xs; Asplit = XS_SPLIT; aStride = 16;
        Bb = g_Ws + 16*16384; Bsplit = WS_SPLIT; bStride = 0;
        bias = bk; Out = g_Ks; vmode = 0;
    } else {
        Ab = g_Ws + 32*16384; Asplit = WS_SPLIT; aStride = 0;
        Bb = g_xs; Bsplit = XS_SPLIT; bStride = 16;
        bias = bv; Out = g_Vt; vmode = 1;
    }
    aB0 = tile * aStride; bB0 = tile * bStride;

    float acc[8][4];
    #pragma unroll
    for (int nt = 0; nt < 8; nt++)
        #pragma unroll
        for (int c = 0; c < 4; c++) acc[nt][c] = 0.f;

    uint32_t stg[2] = {sb, sb + 65536};
    #pragma unroll
    for (int sp = 0; sp < 2; sp++) {
        const unsigned char* sa = Ab + (size_t)sp*Asplit + (size_t)(aB0 + 0)*16384;
        const unsigned char* sv = Bb + (size_t)sp*Bsplit + (size_t)(bB0 + 0)*16384;
        for (int i = tid; i < 1024; i += 512) {
            cp16(stg[0] + sp*16384 + i*16, sa + (size_t)i*16);
            cp16(stg[0] + 32768 + sp*16384 + i*16, sv + (size_t)i*16);
        }
    }
    CP_COMMIT();

    for (int kc = 0; kc < 16; kc++) {
        __syncthreads();
        if (kc + 1 < 16) {
            uint32_t dst = stg[(kc+1) & 1];
            #pragma unroll
            for (int sp = 0; sp < 2; sp++) {
                const unsigned char* sa = Ab + (size_t)sp*Asplit + (size_t)(aB0 + kc + 1)*16384;
                const unsigned char* sv = Bb + (size_t)sp*Bsplit + (size_t)(bB0 + kc + 1)*16384;
                for (int i = tid; i < 1024; i += 512) {
                    cp16(dst + sp*16384 + i*16, sa + (size_t)i*16);
                    cp16(dst + 32768 + sp*16384 + i*16, sv + (size_t)i*16);
                }
            }
            CP_COMMIT();
            CP_WAIT(1);
        } else {
            CP_WAIT(0);
        }
        __syncthreads();

        uint32_t a0 = stg[kc & 1], b0 = stg[kc & 1] + 32768;
        #pragma unroll
        for (int ks = 0; ks < 4; ks++) {
            uint32_t aH[4], aL[4], bH[16], bL[16];
            {
                uint32_t r = 16*wrow + (l & 7) + 8*((l >> 3) & 1);
                uint32_t g = ks*2 + (l >> 4);
                ldm_x4(aH, a0 + r*128 + swz8(r, g));
                ldm_x4(aL, a0 + 16384 + r*128 + swz8(r, g));
            }
            #pragma unroll
            for (int p = 0; p < 4; p++) {
                uint32_t n = 64*wcol + 16*p + 8*((l >> 4) & 1) + (l & 7);
                uint32_t g = ks*2 + ((l >> 3) & 1);
                ldm_x4(bH + 4*p, b0 + n*128 + swz8(n, g));
                ldm_x4(bL + 4*p, b0 + 16384 + n*128 + swz8(n, g));
            }
            #pragma unroll
            for (int nt = 0; nt < 8; nt++) mma16816(acc[nt], aH, &bH[2*nt]);
            #pragma unroll
            for (int nt = 0; nt < 8; nt++) mma16816(acc[nt], aH, &bL[2*nt]);
            #pragma unroll
            for (int nt = 0; nt < 8; nt++) mma16816(acc[nt], aL, &bH[2*nt]);
        }
    }

    __syncthreads();
    float* sOut = (float*)sm;
    #pragma unroll
    for (int nt = 0; nt < 8; nt++) {
        int colb = 64*wcol + 8*nt + 2*(l & 3);
        int r0 = 16*wrow + (l >> 2);
        sOut[r0*132 + colb]       = acc[nt][0];
        sOut[r0*132 + colb + 1]   = acc[nt][1];
        sOut[(r0+8)*132 + colb]   = acc[nt][2];
        sOut[(r0+8)*132 + colb+1] = acc[nt][3];
    }
    __syncthreads();
    int tr = tid >> 4, tc = tid & 15;
    if (!vmode) {
        float bvv[8];
        *(float4*)(bvv)   = *(const float4*)(bias + 8*tc);
        *(float4*)(bvv+4) = *(const float4*)(bias + 8*tc + 4);
        #pragma unroll
        for (int i = 0; i < 4; i++) {
            int row = 4*tr + i;
            float v[8];
            #pragma unroll
            for (int j = 0; j < 8; j++) v[j] = sOut[row*132 + 8*tc + j] + bvv[j];
            uint4 uh, ul;
            split2h8(v, uh, ul);
            size_t base = (size_t)tile*32768 + (size_t)row*256 + swz16((uint32_t)row, (uint32_t)tc);
            *(uint4*)(Out + base)            = uh;
            *(uint4*)(Out + SPLIT_SZ + base) = ul;
        }
    } else {
        #pragma unroll
        for (int i = 0; i < 4; i++) {
            int d = 4*tr + i;
            float bd = bias[d];
            float v[8];
            #pragma unroll
            for (int j = 0; j < 8; j++) v[j] = sOut[d*132 + 8*tc + j] + bd;
            uint4 uh;
            packh8(v, uh);
            size_t base = (size_t)tile*32768 + (size_t)d*256 + swz16((uint32_t)d, (uint32_t)tc);
            *(uint4*)(Out + base) = uh;
        }
    }
}

// ---------------- kernel 5: QT = Qs @ Ts (K=128, 3 products, shared loads) ----------------
#define QT_SMEM (2*65536)
__global__ void __launch_bounds__(256,1) qt_tc() {
    extern __shared__ unsigned char sm[];
    uint32_t sb = smem_u32(sm);
    int tid = threadIdx.x, w = tid >> 5, l = tid & 31;
    int b = blockIdx.y, rb = blockIdx.x, tile = b*32 + rb;

    #pragma unroll
    for (int sp = 0; sp < 2; sp++) {
        const unsigned char* sa = g_Qs + (size_t)sp*SPLIT_SZ + (size_t)tile*32768;
        const unsigned char* st = g_Ts + (size_t)sp*TS_SPLIT + (size_t)b*32768;
        for (int i = tid; i < 2048; i += 256) {
            cp16(sb + sp*32768 + i*16, sa + (size_t)i*16);
            cp16(sb + 65536 + sp*32768 + i*16, st + (size_t)i*16);
        }
    }
    CP_COMMIT();
    CP_WAIT(0);
    __syncthreads();

    float acc[16][4];
    #pragma unroll
    for (int nt = 0; nt < 16; nt++)
        #pragma unroll
        for (int c = 0; c < 4; c++) acc[nt][c] = 0.f;

    #pragma unroll
    for (int ks = 0; ks < 8; ks++) {
        uint32_t aH[4], aL[4], bH[16], bL[16];
        {
            uint32_t r = 16*w + (l & 7) + 8*((l >> 3) & 1);
            uint32_t g = ks*2 + (l >> 4);
            ldm_x4(aH, sb + r*256 + swz16(r, g));
            ldm_x4(aL, sb + 32768 + r*256 + swz16(r, g));
        }
        // first half of N (cols 0..63)
        #pragma unroll
        for (int p = 0; p < 4; p++) {
            uint32_t n = 16*p + 8*((l >> 4) & 1) + (l & 7);
            uint32_t g = ks*2 + ((l >> 3) & 1);
            ldm_x4(bH + 4*p, sb + 65536 + n*256 + swz16(n, g));
            ldm_x4(bL + 4*p, sb + 98304 + n*256 + swz16(n, g));
        }
        #pragma unroll
        for (int nt = 0; nt < 8; nt++) mma16816(acc[nt], aH, &bH[2*nt]);
        #pragma unroll
        for (int nt = 0; nt < 8; nt++) mma16816(acc[nt], aH, &bL[2*nt]);
        #pragma unroll
        for (int nt = 0; nt < 8; nt++) mma16816(acc[nt], aL, &bH[2*nt]);
        // second half of N (cols 64..127)
        #pragma unroll
        for (int p = 0; p < 4; p++) {
            uint32_t n = 64 + 16*p + 8*((l >> 4) & 1) + (l & 7);
            uint32_t g = ks*2 + ((l >> 3) & 1);
            ldm_x4(bH + 4*p, sb + 65536 + n*256 + swz16(n, g));
            ldm_x4(bL + 4*p, sb + 98304 + n*256 + swz16(n, g));
        }
        #pragma unroll
        for (int nt = 0; nt < 8; nt++) mma16816(acc[8+nt], aH, &bH[2*nt]);
        #pragma unroll
        for (int nt = 0; nt < 8; nt++) mma16816(acc[8+nt], aH, &bL[2*nt]);
        #pragma unroll
        for (int nt = 0; nt < 8; nt++) mma16816(acc[8+nt], aL, &bH[2*nt]);
    }

    __syncthreads();
    float* sOut = (float*)sm;
    #pragma unroll
    for (int nt = 0; nt < 16; nt++) {
        int colb = 8*nt + 2*(l & 3);
        int r0 = 16*w + (l >> 2);
        sOut[r0*132 + colb]       = acc[nt][0];
        sOut[r0*132 + colb + 1]   = acc[nt][1];
        sOut[(r0+8)*132 + colb]   = acc[nt][2];
        sOut[(r0+8)*132 + colb+1] = acc[nt][3];
    }
    __syncthreads();
    int tr = tid >> 4, tc = tid & 15;
    #pragma unroll
    for (int i = 0; i < 8; i++) {
        int row = 8*tr + i;
        float v[8];
        #pragma unroll
        for (int j = 0; j < 8; j++) v[j] = sOut[row*132 + 8*tc + j];
        uint4 uh, ul;
        split2h8(v, uh, ul);
        size_t base = (size_t)tile*32768 + (size_t)row*256 + swz16((uint32_t)row, (uint32_t)tc);
        *(uint4*)(g_QTs + base)            = uh;
        *(uint4*)(g_QTs + SPLIT_SZ + base) = ul;
    }
}

// ---------------- fused attention, shared fragment loads ----------------
#define ATT_SMEM (32768 + 65536 + 1024)
__global__ void __launch_bounds__(256,2) attn_fused(float* __restrict__ d_out) {
    extern __shared__ unsigned char sm[];
    uint32_t sb = smem_u32(sm);
    uint32_t qt_s = sb, k_s = sb + 32768;
    float* sM = (float*)(sm + 98304);
    float* sL = sM + 128;

    int tid = threadIdx.x, w = tid >> 5, l = tid & 31;
    int b = blockIdx.y, bx = blockIdx.x;
    int wr = w >> 1, wc = w & 1;
    float* attn = d_out + (size_t)Bn*Sn*DKn;
    size_t rowbase = (size_t)b*Sn + (size_t)bx*64;

    size_t qoff = (size_t)(b*32 + (bx >> 1))*32768 + (size_t)(bx & 1)*16384;
    #pragma unroll
    for (int sp = 0; sp < 2; sp++) {
        const unsigned char* srcq = g_QTs + (size_t)sp*SPLIT_SZ + qoff;
        const unsigned char* srck = g_Ks + (size_t)sp*SPLIT_SZ + (size_t)(b*32)*32768;
        for (int i = tid; i < 1024; i += 256) {
            cp16(qt_s + sp*16384 + i*16, srcq + (size_t)i*16);
            cp16(k_s + sp*16384 + i*16, srck + (size_t)i*16);
        }
    }
    CP_COMMIT();

    int r0 = 16*wr + (l >> 2);
    float m0 = -1e30f, l0 = 0.f, m1 = -1e30f, l1 = 0.f;

    for (int jj = 0; jj < 64; jj++) {
        __syncthreads();
        if (jj + 1 < 64) {
            int jt = (jj+1) >> 1, hf = (jj+1) & 1;
            uint32_t dst = k_s + (uint32_t)(((jj+1) & 1) * 32768);
            #pragma unroll
            for (int sp = 0; sp < 2; sp++) {
                const unsigned char* src = g_Ks + (size_t)sp*SPLIT_SZ
                    + (size_t)(b*32 + jt)*32768 + (size_t)hf*16384;
                for (int i = tid; i < 1024; i += 256) cp16(dst + sp*16384 + i*16, src + (size_t)i*16);
            }
            CP_COMMIT();
            CP_WAIT(1);
        } else {
            CP_WAIT(0);
        }
        __syncthreads();

        uint32_t kb = k_s + (uint32_t)((jj & 1) * 32768);
        float acc[4][4];
        #pragma unroll
        for (int nt = 0; nt < 4; nt++)
            #pragma unroll
            for (int c = 0; c < 4; c++) acc[nt][c] = 0.f;

        #pragma unroll
        for (int kc = 0; kc < 8; kc++) {
            uint32_t aH[4], aL[4], bH[8], bL[8];
            {
                uint32_t r = 16*wr + (l & 7) + 8*((l >> 3) & 1);
                uint32_t g = kc*2 + (l >> 4);
                ldm_x4(aH, qt_s + r*256 + swz16(r, g));
                ldm_x4(aL, qt_s + 16384 + r*256 + swz16(r, g));
            }
            #pragma unroll
            for (int p = 0; p < 2; p++) {
                uint32_t n = 32*wc + 16*p + 8*((l >> 4) & 1) + (l & 7);
                uint32_t g = kc*2 + ((l >> 3) & 1);
                ldm_x4(bH + 4*p, kb + n*256 + swz16(n, g));
                ldm_x4(bL + 4*p, kb + 16384 + n*256 + swz16(n, g));
            }
            #pragma unroll
            for (int nt = 0; nt < 4; nt++) mma16816(acc[nt], aH, &bH[2*nt]);
            #pragma unroll
            for (int nt = 0; nt < 4; nt++) mma16816(acc[nt], aH, &bL[2*nt]);
            #pragma unroll
            for (int nt = 0; nt < 4; nt++) mma16816(acc[nt], aL, &bH[2*nt]);
        }

        float tm0 = -1e30f, tm1 = -1e30f;
        #pragma unroll
        for (int nt = 0; nt < 4; nt++) {
            tm0 = fmaxf(tm0, fmaxf(acc[nt][0], acc[nt][1]));
            tm1 = fmaxf(tm1, fmaxf(acc[nt][2], acc[nt][3]));
        }
        tm0 = fmaxf(tm0, __shfl_xor_sync(0xffffffffu, tm0, 1));
        tm0 = fmaxf(tm0, __shfl_xor_sync(0xffffffffu, tm0, 2));
        tm1 = fmaxf(tm1, __shfl_xor_sync(0xffffffffu, tm1, 1));
        tm1 = fmaxf(tm1, __shfl_xor_sync(0xffffffffu, tm1, 2));
        float mn0 = fmaxf(m0, tm0), mn1 = fmaxf(m1, tm1);
        float rs0 = 0.f, rs1 = 0.f;
        #pragma unroll
        for (int nt = 0; nt < 4; nt++) {
            rs0 += __expf(acc[nt][0] - mn0) + __expf(acc[nt][1] - mn0);
            rs1 += __expf(acc[nt][2] - mn1) + __expf(acc[nt][3] - mn1);
        }
        rs0 += __shfl_xor_sync(0xffffffffu, rs0, 1);
        rs0 += __shfl_xor_sync(0xffffffffu, rs0, 2);
        rs1 += __shfl_xor_sync(0xffffffffu, rs1, 1);
        rs1 += __shfl_xor_sync(0xffffffffu, rs1, 2);
        l0 = l0*__expf(m0 - mn0) + rs0; m0 = mn0;
        l1 = l1*__expf(m1 - mn1) + rs1; m1 = mn1;

        float* dst0 = attn + (rowbase + r0)*Sn + (size_t)jj*64 + 32*wc + 2*(l & 3);
        float* dst1 = attn + (rowbase + r0 + 8)*Sn + (size_t)jj*64 + 32*wc + 2*(l & 3);
        #pragma unroll
        for (int nt = 0; nt < 4; nt++) {
            *(float2*)(dst0 + 8*nt) = make_float2(acc[nt][0], acc[nt][1]);
            *(float2*)(dst1 + 8*nt) = make_float2(acc[nt][2], acc[nt][3]);
        }
    }

    if ((l & 3) == 0) {
        sM[wc*64 + r0]     = m0;  sL[wc*64 + r0]     = l0;
        sM[wc*64 + r0 + 8] = m1;  sL[wc*64 + r0 + 8] = l1;
    }
    __syncthreads();
    if (tid < 64) {
        float ma = sM[tid], mb = sM[64 + tid];
        float mn = fmaxf(ma, mb);
        float lt = sL[tid]*__expf(ma - mn) + sL[64 + tid]*__expf(mb - mn);
        sM[tid] = mn;
        sL[tid] = lt;
    }
    __syncthreads();

    // ---- phase 2: exp + PV, single product ----
    uint32_t p_s = sb, v_s = sb + 32768;
    int erow = tid >> 2;
    int c0 = (tid & 3) * 16;
    float mv = sM[erow];
    float li = 1.0f / sL[erow];
    __syncthreads();
    uint32_t pst0 = p_s + (uint32_t)erow*128 + swz8((uint32_t)erow, (uint32_t)(c0 >> 3));
    uint32_t pst1 = p_s + (uint32_t)erow*128 + swz8((uint32_t)erow, (uint32_t)(c0 >> 3) + 1);

    {
        const unsigned char* src = g_Vt + (size_t)(b*32)*32768;
        for (int i = tid; i < 1024; i += 256) {
            int r = i >> 3, s8 = i & 7;
            cp16(v_s + r*128 + s8*16, src + (size_t)r*256 + (size_t)s8*16);
        }
        CP_COMMIT();
    }

    float out[8][4];
    #pragma unroll
    for (int nt = 0; nt < 8; nt++)
        #pragma unroll
        for (int c = 0; c < 4; c++) out[nt][c] = 0.f;

    for (int jj = 0; jj < 64; jj++) {
        __syncthreads();

        {
            float* srcp = attn + (rowbase + erow)*Sn + (size_t)jj*64 + c0;
            float p8[8];
            *(float4*)(p8)   = *(const float4*)(srcp);
            *(float4*)(p8+4) = *(const float4*)(srcp + 4);
            #pragma unroll
            for (int x = 0; x < 8; x++) p8[x] = __expf(p8[x] - mv) * li;
            *(float4*)(srcp)     = *(float4*)(p8);
            *(float4*)(srcp + 4) = *(float4*)(p8+4);
            uint4 uh;
            packh8(p8, uh);
            STS16(pst0, uh);

            *(float4*)(p8)   = *(const float4*)(srcp + 8);
            *(float4*)(p8+4) = *(const float4*)(srcp + 12);
            #pragma unroll
            for (int x = 0; x < 8; x++) p8[x] = __expf(p8[x] - mv) * li;
            *(float4*)(srcp + 8)  = *(float4*)(p8);
            *(float4*)(srcp + 12) = *(float4*)(p8+4);
            packh8(p8, uh);
            STS16(pst1, uh);
        }

        if (jj + 1 < 64) {
            int jt = (jj+1) >> 1, hf = (jj+1) & 1;
            uint32_t dst = v_s + (uint32_t)(((jj+1) & 1) * 16384);
            const unsigned char* src = g_Vt + (size_t)(b*32 + jt)*32768 + (size_t)hf*128;
            for (int i = tid; i < 1024; i += 256) {
                int r = i >> 3, s8 = i & 7;
                cp16(dst + r*128 + s8*16, src + (size_t)r*256 + (size_t)s8*16);
            }
            CP_COMMIT();
            CP_WAIT(1);
        } else {
            CP_WAIT(0);
        }
        __syncthreads();

        uint32_t vb = v_s + (uint32_t)((jj & 1) * 16384);
        #pragma unroll
        for (int kc = 0; kc < 4; kc++) {
            uint32_t afr[4], bfr[16];
            {
                uint32_t r = 16*wr + (l & 7) + 8*((l >> 3) & 1);
                uint32_t g = kc*2 + (l >> 4);
                ldm_x4(afr, p_s + r*128 + swz8(r, g));
            }
            #pragma unroll
            for (int p = 0; p < 4; p++) {
                uint32_t n = 64*wc + 16*p + 8*((l >> 4) & 1) + (l & 7);
                uint32_t g = kc*2 + ((l >> 3) & 1);
                ldm_x4(bfr + 4*p, vb + n*128 + swz8(n, g));
            }
            #pragma unroll
            for (int nt = 0; nt < 8; nt++)
                mma16816(out[nt], afr, &bfr[2*nt]);
        }
    }

    #pragma unroll
    for (int nt = 0; nt < 8; nt++)
        #pragma unroll
        for (int dl = 0; dl < 2; dl++) {
            int row = 16*wr + (l >> 2) + 8*dl;
            float* o = d_out + (rowbase + row)*DKn + 64*wc + 8*nt + 2*(l & 3);
            *(float2*)(o) = make_float2(out[nt][2*dl], out[nt][2*dl+1]);
        }
}

// ---------------- launcher ----------------
extern "C" void kernel_launch(void* const* d_in, const int* in_sizes, int n_in,
                              void* d_out, int out_size) {
    const float* x  = (const float*)d_in[0];
    const float* tp = (const float*)d_in[1];
    const float* Wq = (const float*)d_in[2];
    const float* bq = (const float*)d_in[3];
    const float* Wk = (const float*)d_in[4];
    const float* bk = (const float*)d_in[5];
    const float* Wv = (const float*)d_in[6];
    const float* bv = (const float*)d_in[7];
    const float* Wt = (const float*)d_in[8];
    const float* bt = (const float*)d_in[9];
    float* out = (float*)d_out;

    cudaFuncSetAttribute((const void*)proj_tc,    cudaFuncAttributeMaxDynamicSharedMemorySize, PROJ_SMEM);
    cudaFuncSetAttribute((const void*)qt_tc,      cudaFuncAttributeMaxDynamicSharedMemorySize, QT_SMEM);
    cudaFuncSetAttribute((const void*)attn_fused, cudaFuncAttributeMaxDynamicSharedMemorySize, ATT_SMEM);

    prep_T_kernel<<<Bn, 256>>>(tp, Wt, bt);
    split_x_kernel<<<8192, 256>>>(x);
    split_W_kernel<<<dim3(16, 3), 256>>>(Wq, Wk, Wv);

    proj_tc<<<dim3(128, 3), 512, PROJ_SMEM>>>(bq, bk, bv);
    qt_tc<<<dim3(32, Bn), 256, QT_SMEM>>>();

    attn_fused<<<dim3(64, Bn), 256, ATT_SMEM>>>(out);
}

// round 11
// speedup vs baseline: 4.0335x; 1.0628x over previous
#include <cuda_runtime.h>
#include <cuda_fp16.h>
#include <math.h>
#include <stdint.h>

#define Bn 4
#define Sn 4096
#define Dn 1024
#define TPn 16
#define TEn 64
#define DKn 128
#define NTILE 128
#define SPLIT_SZ (NTILE*32768ULL)
#define XS_SPLIT (NTILE*16*16384ULL)
#define WS_SPLIT (3*16*16384ULL)
#define TS_SPLIT (Bn*32768ULL)
#define SCALE 0.08838834764831845f

// ---------------- scratch ----------------
__device__ __align__(16) unsigned char g_xs [2*XS_SPLIT];
__device__ __align__(16) unsigned char g_Ws [2*WS_SPLIT];
__device__ __align__(16) unsigned char g_Ts [2*TS_SPLIT];
__device__ __align__(16) unsigned char g_Qs [2*SPLIT_SZ];
__device__ __align__(16) unsigned char g_Ks [2*SPLIT_SZ];
__device__ __align__(16) unsigned char g_QTs[2*SPLIT_SZ];
__device__ __align__(16) unsigned char g_Vt [SPLIT_SZ];
__device__ __align__(16) unsigned char g_U  [256ULL*64*8192];   // fp16 u blobs, 128MB
__device__ float g_mj[256*64*64];                                // per-tile running max, 4MB

// ---------------- helpers ----------------
__device__ __forceinline__ uint32_t smem_u32(const void* p){
    uint32_t a;
    asm("{ .reg .u64 t; cvta.to.shared.u64 t, %1; cvt.u32.u64 %0, t; }" : "=r"(a) : "l"(p));
    return a;
}
__device__ __forceinline__ uint32_t swz16(uint32_t r, uint32_t g){
    return ((g & 8u) | ((g ^ r) & 7u)) << 4;
}
__device__ __forceinline__ uint32_t swz8(uint32_t r, uint32_t g){
    return ((g ^ r) & 7u) << 4;
}
__device__ __forceinline__ void cp16(uint32_t dst, const void* src){
    asm volatile("cp.async.cg.shared.global [%0], [%1], 16;" :: "r"(dst), "l"(src) : "memory");
}
#define CP_COMMIT() asm volatile("cp.async.commit_group;" ::: "memory")
#define CP_WAIT(n)  asm volatile("cp.async.wait_group %0;" :: "n"(n) : "memory")
#define LDS16(r, addr) asm volatile("ld.shared.v4.b32 {%0,%1,%2,%3}, [%4];" \
    : "=r"((r)[0]), "=r"((r)[1]), "=r"((r)[2]), "=r"((r)[3]) : "r"(addr))

__device__ __forceinline__ void ldm_x4(uint32_t* r, uint32_t addr){
    asm volatile("ldmatrix.sync.aligned.m8n8.x4.shared.b16 {%0,%1,%2,%3}, [%4];"
        : "=r"(r[0]), "=r"(r[1]), "=r"(r[2]), "=r"(r[3]) : "r"(addr));
}
__device__ __forceinline__ void mma16816(float* d, const uint32_t* a, const uint32_t* b){
    asm volatile("mma.sync.aligned.m16n8k16.row.col.f32.f16.f16.f32 "
        "{%0,%1,%2,%3}, {%4,%5,%6,%7}, {%8,%9}, {%0,%1,%2,%3};"
        : "+f"(d[0]), "+f"(d[1]), "+f"(d[2]), "+f"(d[3])
        : "r"(a[0]), "r"(a[1]), "r"(a[2]), "r"(a[3]), "r"(b[0]), "r"(b[1]));
}
__device__ __forceinline__ uint32_t pk(unsigned short a, unsigned short b){
    return (uint32_t)a | ((uint32_t)b << 16);
}
__device__ __forceinline__ uint32_t pkh(float a, float b){
    return pk(__half_as_ushort(__float2half_rn(a)), __half_as_ushort(__float2half_rn(b)));
}
__device__ __forceinline__ void split2h8(const float* v, uint4& uh, uint4& ul){
    unsigned short h[8], l[8];
    #pragma unroll
    for (int j = 0; j < 8; j++){
        __half hh = __float2half_rn(v[j]);
        __half hl = __float2half_rn(v[j] - __half2float(hh));
        h[j] = __half_as_ushort(hh); l[j] = __half_as_ushort(hl);
    }
    uh = make_uint4(pk(h[0],h[1]), pk(h[2],h[3]), pk(h[4],h[5]), pk(h[6],h[7]));
    ul = make_uint4(pk(l[0],l[1]), pk(l[2],l[3]), pk(l[4],l[5]), pk(l[6],l[7]));
}
__device__ __forceinline__ void packh8(const float* v, uint4& uh){
    unsigned short h[8];
    #pragma unroll
    for (int j = 0; j < 8; j++) h[j] = __half_as_ushort(__float2half_rn(v[j]));
    uh = make_uint4(pk(h[0],h[1]), pk(h[2],h[3]), pk(h[4],h[5]), pk(h[6],h[7]));
}

// ---------------- kernel 1: T_scaled (x SCALE) -> 2-split fp16 blobs ----------------
__global__ void prep_T_kernel(const float* __restrict__ tp,
                              const float* __restrict__ Wt,
                              const float* __restrict__ bt) {
    __shared__ float sTP[TPn*TEn];
    __shared__ float sWt[TEn*DKn];
    __shared__ float sE [TPn*DKn];
    __shared__ float red[256];
    int b = blockIdx.x, tid = threadIdx.x;
    for (int i = tid; i < TPn*TEn; i += 256) sTP[i] = tp[b*TPn*TEn + i];
    for (int i = tid; i < TEn*DKn; i += 256) sWt[i] = Wt[i];
    __syncthreads();
    for (int i = tid; i < TPn*DKn; i += 256) {
        int t = i >> 7, d = i & 127;
        float acc = bt[d];
        #pragma unroll 8
        for (int e = 0; e < TEn; e++) acc += sTP[t*TEn + e] * sWt[e*DKn + d];
        sE[i] = acc;
    }
    __syncthreads();
    float ss = 0.f;
    for (int i = tid; i < TPn*DKn; i += 256) ss += sE[i]*sE[i];
    red[tid] = ss; __syncthreads();
    for (int off = 128; off > 0; off >>= 1) {
        if (tid < off) red[tid] += red[tid+off];
        __syncthreads();
    }
    float tn = sqrtf((float)Sn * red[0]);
    float sc = (float)Sn / (tn + 1e-8f) * SCALE;
    for (int i = tid; i < DKn*DKn; i += 256) {
        int d = i >> 7, e2 = i & 127;
        float acc = 0.f;
        #pragma unroll
        for (int t = 0; t < TPn; t++) acc += sE[t*DKn + d] * sE[t*DKn + e2];
        float v = acc * sc;
        __half hh = __float2half_rn(v);
        __half hl = __float2half_rn(v - __half2float(hh));
        size_t base = (size_t)b*32768 + (size_t)d*256 + swz16((uint32_t)d, (uint32_t)(e2 >> 3)) + (size_t)(e2 & 7)*2;
        *(__half*)(g_Ts + base)            = hh;
        *(__half*)(g_Ts + TS_SPLIT + base) = hl;
    }
}

// ---------------- kernel 2: split x -> 2-split fp16 blobs ----------------
__global__ void split_x_kernel(const float* __restrict__ x) {
    int gidx = blockIdx.x*256 + threadIdx.x;
    int rt = gidx >> 7, gk = gidx & 127;
    int kc = gk >> 3, g = gk & 7;
    const float* src = x + (size_t)rt*Dn + kc*64 + g*8;
    float v[8];
    *(float4*)(v)   = *(const float4*)(src);
    *(float4*)(v+4) = *(const float4*)(src + 4);
    uint4 uh, ul;
    split2h8(v, uh, ul);
    int tile = rt >> 7, r = rt & 127;
    size_t off = (size_t)(tile*16 + kc)*16384 + (size_t)r*128 + swz8((uint32_t)r, (uint32_t)g);
    *(uint4*)(g_xs + off)            = uh;
    *(uint4*)(g_xs + XS_SPLIT + off) = ul;
}

// ---------------- kernel 3: split W^T -> 2-split fp16 blobs ----------------
__global__ void split_W_kernel(const float* __restrict__ Wq,
                               const float* __restrict__ Wk,
                               const float* __restrict__ Wv) {
    __shared__ float sW[64*128];
    int kc = blockIdx.x, mat = blockIdx.y, tid = threadIdx.x;
    const float* W = (mat == 0) ? Wq : ((mat == 1) ? Wk : Wv);
    for (int i = tid; i < 2048; i += 256)
        ((float4*)sW)[i] = ((const float4*)(W + (size_t)kc*64*128))[i];
    __syncthreads();
    for (int it = 0; it < 4; it++) {
        int gi = tid + it*256;
        int d = gi >> 3, g = gi & 7;
        float v[8];
        #pragma unroll
        for (int j = 0; j < 8; j++) v[j] = sW[(g*8 + j)*128 + d];
        uint4 uh, ul;
        split2h8(v, uh, ul);
        size_t off = (size_t)(mat*16 + kc)*16384 + (size_t)d*128 + swz8((uint32_t)d, (uint32_t)g);
        *(uint4*)(g_Ws + off)            = uh;
        *(uint4*)(g_Ws + WS_SPLIT + off) = ul;
    }
}

// ---------------- kernel 4: fused QKV projection GEMM ----------------
#define PROJ_SMEM (2*65536)
__global__ void __launch_bounds__(512,1)
proj_tc(const float* __restrict__ bq, const float* __restrict__ bk,
        const float* __restrict__ bv) {
    extern __shared__ unsigned char sm[];
    uint32_t sb = smem_u32(sm);
    int tid = threadIdx.x, w = tid >> 5, l = tid & 31;
    int wrow = w >> 1, wcol = w & 1;
    int tile = blockIdx.x, mat = blockIdx.y;

    const unsigned char* Ab;  size_t Asplit;  int aStride, aB0;
    const unsigned char* Bb;  size_t Bsplit;  int bStride, bB0;
    const float* bias;        unsigned char* Out;  int vmode;
    if (mat == 0) {
        Ab = g_xs; Asplit = XS_SPLIT; aStride = 16;
        Bb = g_Ws; Bsplit = WS_SPLIT; bStride = 0;
        bias = bq; Out = g_Qs; vmode = 0;
    } else if (mat == 1) {
        Ab = g_xs; Asplit = XS_SPLIT; aStride = 16;
        Bb = g_Ws + 16*16384; Bsplit = WS_SPLIT; bStride = 0;
        bias = bk; Out = g_Ks; vmode = 0;
    } else {
        Ab = g_Ws + 32*16384; Asplit = WS_SPLIT; aStride = 0;
        Bb = g_xs; Bsplit = XS_SPLIT; bStride = 16;
        bias = bv; Out = g_Vt; vmode = 1;
    }
    aB0 = tile * aStride; bB0 = tile * bStride;

    float acc[8][4];
    #pragma unroll
    for (int nt = 0; nt < 8; nt++)
        #pragma unroll
        for (int c = 0; c < 4; c++) acc[nt][c] = 0.f;

    uint32_t stg[2] = {sb, sb + 65536};
    #pragma unroll
    for (int sp = 0; sp < 2; sp++) {
        const unsigned char* sa = Ab + (size_t)sp*Asplit + (size_t)(aB0 + 0)*16384;
        const unsigned char* sv = Bb + (size_t)sp*Bsplit + (size_t)(bB0 + 0)*16384;
        for (int i = tid; i < 1024; i += 512) {
            cp16(stg[0] + sp*16384 + i*16, sa + (size_t)i*16);
            cp16(stg[0] + 32768 + sp*16384 + i*16, sv + (size_t)i*16);
        }
    }
    CP_COMMIT();

    for (int kc = 0; kc < 16; kc++) {
        __syncthreads();
        if (kc + 1 < 16) {
            uint32_t dst = stg[(kc+1) & 1];
            #pragma unroll
            for (int sp = 0; sp < 2; sp++) {
                const unsigned char* sa = Ab + (size_t)sp*Asplit + (size_t)(aB0 + kc + 1)*16384;
                const unsigned char* sv = Bb + (size_t)sp*Bsplit + (size_t)(bB0 + kc + 1)*16384;
                for (int i = tid; i < 1024; i += 512) {
                    cp16(dst + sp*16384 + i*16, sa + (size_t)i*16);
                    cp16(dst + 32768 + sp*16384 + i*16, sv + (size_t)i*16);
                }
            }
            CP_COMMIT();
            CP_WAIT(1);
        } else {
            CP_WAIT(0);
        }
        __syncthreads();

        uint32_t a0 = stg[kc & 1], b0 = stg[kc & 1] + 32768;
        #pragma unroll
        for (int ks = 0; ks < 4; ks++) {
            uint32_t aH[4], aL[4], bH[16], bL[16];
            {
                uint32_t r = 16*wrow + (l & 7) + 8*((l >> 3) & 1);
                uint32_t g = ks*2 + (l >> 4);
                ldm_x4(aH, a0 + r*128 + swz8(r, g));
                ldm_x4(aL, a0 + 16384 + r*128 + swz8(r, g));
            }
            #pragma unroll
            for (int p = 0; p < 4; p++) {
                uint32_t n = 64*wcol + 16*p + 8*((l >> 4) & 1) + (l & 7);
                uint32_t g = ks*2 + ((l >> 3) & 1);
                ldm_x4(bH + 4*p, b0 + n*128 + swz8(n, g));
                ldm_x4(bL + 4*p, b0 + 16384 + n*128 + swz8(n, g));
            }
            #pragma unroll
            for (int nt = 0; nt < 8; nt++) mma16816(acc[nt], aH, &bH[2*nt]);
            #pragma unroll
            for (int nt = 0; nt < 8; nt++) mma16816(acc[nt], aH, &bL[2*nt]);
            #pragma unroll
            for (int nt = 0; nt < 8; nt++) mma16816(acc[nt], aL, &bH[2*nt]);
        }
    }

    __syncthreads();
    float* sOut = (float*)sm;
    #pragma unroll
    for (int nt = 0; nt < 8; nt++) {
        int colb = 64*wcol + 8*nt + 2*(l & 3);
        int r0 = 16*wrow + (l >> 2);
        sOut[r0*132 + colb]       = acc[nt][0];
        sOut[r0*132 + colb + 1]   = acc[nt][1];
        sOut[(r0+8)*132 + colb]   = acc[nt][2];
        sOut[(r0+8)*132 + colb+1] = acc[nt][3];
    }
    __syncthreads();
    int tr = tid >> 4, tc = tid & 15;
    if (!vmode) {
        float bvv[8];
        *(float4*)(bvv)   = *(const float4*)(bias + 8*tc);
        *(float4*)(bvv+4) = *(const float4*)(bias + 8*tc + 4);
        #pragma unroll
        for (int i = 0; i < 4; i++) {
            int row = 4*tr + i;
            float v[8];
            #pragma unroll
            for (int j = 0; j < 8; j++) v[j] = sOut[row*132 + 8*tc + j] + bvv[j];
            uint4 uh, ul;
            split2h8(v, uh, ul);
            size_t base = (size_t)tile*32768 + (size_t)row*256 + swz16((uint32_t)row, (uint32_t)tc);
            *(uint4*)(Out + base)            = uh;
            *(uint4*)(Out + SPLIT_SZ + base) = ul;
        }
    } else {
        #pragma unroll
        for (int i = 0; i < 4; i++) {
            int d = 4*tr + i;
            float bd = bias[d];
            float v[8];
            #pragma unroll
            for (int j = 0; j < 8; j++) v[j] = sOut[d*132 + 8*tc + j] + bd;
            uint4 uh;
            packh8(v, uh);
            size_t base = (size_t)tile*32768 + (size_t)d*256 + swz16((uint32_t)d, (uint32_t)tc);
            *(uint4*)(Out + base) = uh;
        }
    }
}

// ---------------- kernel 5: QT = Qs @ Ts ----------------
#define QT_SMEM (2*65536)
__global__ void __launch_bounds__(256,1) qt_tc() {
    extern __shared__ unsigned char sm[];
    uint32_t sb = smem_u32(sm);
    int tid = threadIdx.x, w = tid >> 5, l = tid & 31;
    int b = blockIdx.y, rb = blockIdx.x, tile = b*32 + rb;

    #pragma unroll
    for (int sp = 0; sp < 2; sp++) {
        const unsigned char* sa = g_Qs + (size_t)sp*SPLIT_SZ + (size_t)tile*32768;
        const unsigned char* st = g_Ts + (size_t)sp*TS_SPLIT + (size_t)b*32768;
        for (int i = tid; i < 2048; i += 256) {
            cp16(sb + sp*32768 + i*16, sa + (size_t)i*16);
            cp16(sb + 65536 + sp*32768 + i*16, st + (size_t)i*16);
        }
    }
    CP_COMMIT();
    CP_WAIT(0);
    __syncthreads();

    float acc[16][4];
    #pragma unroll
    for (int nt = 0; nt < 16; nt++)
        #pragma unroll
        for (int c = 0; c < 4; c++) acc[nt][c] = 0.f;

    #pragma unroll
    for (int ks = 0; ks < 8; ks++) {
        uint32_t aH[4], aL[4], bH[16], bL[16];
        {
            uint32_t r = 16*w + (l & 7) + 8*((l >> 3) & 1);
            uint32_t g = ks*2 + (l >> 4);
            ldm_x4(aH, sb + r*256 + swz16(r, g));
            ldm_x4(aL, sb + 32768 + r*256 + swz16(r, g));
        }
        #pragma unroll
        for (int p = 0; p < 4; p++) {
            uint32_t n = 16*p + 8*((l >> 4) & 1) + (l & 7);
            uint32_t g = ks*2 + ((l >> 3) & 1);
            ldm_x4(bH + 4*p, sb + 65536 + n*256 + swz16(n, g));
            ldm_x4(bL + 4*p, sb + 98304 + n*256 + swz16(n, g));
        }
        #pragma unroll
        for (int nt = 0; nt < 8; nt++) mma16816(acc[nt], aH, &bH[2*nt]);
        #pragma unroll
        for (int nt = 0; nt < 8; nt++) mma16816(acc[nt], aH, &bL[2*nt]);
        #pragma unroll
        for (int nt = 0; nt < 8; nt++) mma16816(acc[nt], aL, &bH[2*nt]);
        #pragma unroll
        for (int p = 0; p < 4; p++) {
            uint32_t n = 64 + 16*p + 8*((l >> 4) & 1) + (l & 7);
            uint32_t g = ks*2 + ((l >> 3) & 1);
            ldm_x4(bH + 4*p, sb + 65536 + n*256 + swz16(n, g));
            ldm_x4(bL + 4*p, sb + 98304 + n*256 + swz16(n, g));
        }
        #pragma unroll
        for (int nt = 0; nt < 8; nt++) mma16816(acc[8+nt], aH, &bH[2*nt]);
        #pragma unroll
        for (int nt = 0; nt < 8; nt++) mma16816(acc[8+nt], aH, &bL[2*nt]);
        #pragma unroll
        for (int nt = 0; nt < 8; nt++) mma16816(acc[8+nt], aL, &bH[2*nt]);
    }

    __syncthreads();
    float* sOut = (float*)sm;
    #pragma unroll
    for (int nt = 0; nt < 16; nt++) {
        int colb = 8*nt + 2*(l & 3);
        int r0 = 16*w + (l >> 2);
        sOut[r0*132 + colb]       = acc[nt][0];
        sOut[r0*132 + colb + 1]   = acc[nt][1];
        sOut[(r0+8)*132 + colb]   = acc[nt][2];
        sOut[(r0+8)*132 + colb+1] = acc[nt][3];
    }
    __syncthreads();
    int tr = tid >> 4, tc = tid & 15;
    #pragma unroll
    for (int i = 0; i < 8; i++) {
        int row = 8*tr + i;
        float v[8];
        #pragma unroll
        for (int j = 0; j < 8; j++) v[j] = sOut[row*132 + 8*tc + j];
        uint4 uh, ul;
        split2h8(v, uh, ul);
        size_t base = (size_t)tile*32768 + (size_t)row*256 + swz16((uint32_t)row, (uint32_t)tc);
        *(uint4*)(g_QTs + base)            = uh;
        *(uint4*)(g_QTs + SPLIT_SZ + base) = ul;
    }
}

// ---------------- fused flash attention with u-blob intermediate ----------------
#define ATT_SMEM (98304 + 2048)
__global__ void __launch_bounds__(256,2) attn_fused(float* __restrict__ d_out) {
    extern __shared__ unsigned char sm[];
    uint32_t sb = smem_u32(sm);
    uint32_t qt_s = sb, k_s = sb + 32768;
    float* sTM = (float*)(sm + 98304);       // [2][64]
    float* sRS = sTM + 128;                  // [2][64]
    float* sM  = sRS + 128;                  // [64]
    float* sL  = sM + 64;                    // [64]

    int tid = threadIdx.x, w = tid >> 5, l = tid & 31;
    int b = blockIdx.y, bx = blockIdx.x;
    int wr = w >> 1, wc = w & 1;
    float* attn = d_out + (size_t)Bn*Sn*DKn;
    size_t rowbase = (size_t)b*Sn + (size_t)bx*64;
    int ci = b*64 + bx;

    // ---- phase 1 prologue ----
    size_t qoff = (size_t)(b*32 + (bx >> 1))*32768 + (size_t)(bx & 1)*16384;
    #pragma unroll
    for (int sp = 0; sp < 2; sp++) {
        const unsigned char* srcq = g_QTs + (size_t)sp*SPLIT_SZ + qoff;
        const unsigned char* srck = g_Ks + (size_t)sp*SPLIT_SZ + (size_t)(b*32)*32768;
        for (int i = tid; i < 1024; i += 256) {
            cp16(qt_s + sp*16384 + i*16, srcq + (size_t)i*16);
            cp16(k_s + sp*16384 + i*16, srck + (size_t)i*16);
        }
    }
    CP_COMMIT();

    int r0 = 16*wr + (l >> 2);
    float m0 = -1e30f, l0 = 0.f, m1 = -1e30f, l1 = 0.f;

    for (int jj = 0; jj < 64; jj++) {
        __syncthreads();
        if (jj + 1 < 64) {
            int jt = (jj+1) >> 1, hf = (jj+1) & 1;
            uint32_t dst = k_s + (uint32_t)(((jj+1) & 1) * 32768);
            #pragma unroll
            for (int sp = 0; sp < 2; sp++) {
                const unsigned char* src = g_Ks + (size_t)sp*SPLIT_SZ
                    + (size_t)(b*32 + jt)*32768 + (size_t)hf*16384;
                for (int i = tid; i < 1024; i += 256) cp16(dst + sp*16384 + i*16, src + (size_t)i*16);
            }
            CP_COMMIT();
            CP_WAIT(1);
        } else {
            CP_WAIT(0);
        }
        __syncthreads();

        uint32_t kb = k_s + (uint32_t)((jj & 1) * 32768);
        float acc[4][4];
        #pragma unroll
        for (int nt = 0; nt < 4; nt++)
            #pragma unroll
            for (int c = 0; c < 4; c++) acc[nt][c] = 0.f;

        #pragma unroll
        for (int kc = 0; kc < 8; kc++) {
            uint32_t aH[4], aL[4], bH[8], bL[8];
            {
                uint32_t r = 16*wr + (l & 7) + 8*((l >> 3) & 1);
                uint32_t g = kc*2 + (l >> 4);
                ldm_x4(aH, qt_s + r*256 + swz16(r, g));
                ldm_x4(aL, qt_s + 16384 + r*256 + swz16(r, g));
            }
            #pragma unroll
            for (int p = 0; p < 2; p++) {
                uint32_t n = 32*wc + 16*p + 8*((l >> 4) & 1) + (l & 7);
                uint32_t g = kc*2 + ((l >> 3) & 1);
                ldm_x4(bH + 4*p, kb + n*256 + swz16(n, g));
                ldm_x4(bL + 4*p, kb + 16384 + n*256 + swz16(n, g));
            }
            #pragma unroll
            for (int nt = 0; nt < 4; nt++) mma16816(acc[nt], aH, &bH[2*nt]);
            #pragma unroll
            for (int nt = 0; nt < 4; nt++) mma16816(acc[nt], aH, &bL[2*nt]);
            #pragma unroll
            for (int nt = 0; nt < 4; nt++) mma16816(acc[nt], aL, &bH[2*nt]);
        }

        // half-local tile max -> smem exchange -> unified row max
        float tm0 = -1e30f, tm1 = -1e30f;
        #pragma unroll
        for (int nt = 0; nt < 4; nt++) {
            tm0 = fmaxf(tm0, fmaxf(acc[nt][0], acc[nt][1]));
            tm1 = fmaxf(tm1, fmaxf(acc[nt][2], acc[nt][3]));
        }
        tm0 = fmaxf(tm0, __shfl_xor_sync(0xffffffffu, tm0, 1));
        tm0 = fmaxf(tm0, __shfl_xor_sync(0xffffffffu, tm0, 2));
        tm1 = fmaxf(tm1, __shfl_xor_sync(0xffffffffu, tm1, 1));
        tm1 = fmaxf(tm1, __shfl_xor_sync(0xffffffffu, tm1, 2));
        if ((l & 3) == 0) {
            sTM[wc*64 + r0]     = tm0;
            sTM[wc*64 + r0 + 8] = tm1;
        }
        __syncthreads();
        float mn0 = fmaxf(m0, fmaxf(sTM[r0],     sTM[64 + r0]));
        float mn1 = fmaxf(m1, fmaxf(sTM[r0 + 8], sTM[64 + r0 + 8]));

        // u = exp(s - mn), half-local sums -> smem -> unified l update
        float rs0 = 0.f, rs1 = 0.f;
        #pragma unroll
        for (int nt = 0; nt < 4; nt++) {
            acc[nt][0] = __expf(acc[nt][0] - mn0);
            acc[nt][1] = __expf(acc[nt][1] - mn0);
            acc[nt][2] = __expf(acc[nt][2] - mn1);
            acc[nt][3] = __expf(acc[nt][3] - mn1);
            rs0 += acc[nt][0] + acc[nt][1];
            rs1 += acc[nt][2] + acc[nt][3];
        }
        rs0 += __shfl_xor_sync(0xffffffffu, rs0, 1);
        rs0 += __shfl_xor_sync(0xffffffffu, rs0, 2);
        rs1 += __shfl_xor_sync(0xffffffffu, rs1, 1);
        rs1 += __shfl_xor_sync(0xffffffffu, rs1, 2);
        if ((l & 3) == 0) {
            sRS[wc*64 + r0]     = rs0;
            sRS[wc*64 + r0 + 8] = rs1;
        }
        __syncthreads();
        l0 = l0*__expf(m0 - mn0) + sRS[r0]     + sRS[64 + r0];
        l1 = l1*__expf(m1 - mn1) + sRS[r0 + 8] + sRS[64 + r0 + 8];
        m0 = mn0; m1 = mn1;

        // dump u (fp16, swizzled blob) + running max
        unsigned char* ub = g_U + ((size_t)ci*64 + jj)*8192;
        #pragma unroll
        for (int nt = 0; nt < 4; nt++) {
            uint32_t gq = 4*wc + nt;
            *(uint32_t*)(ub + (uint32_t)r0*128     + swz8((uint32_t)r0, gq)   + 4*(l & 3)) = pkh(acc[nt][0], acc[nt][1]);
            *(uint32_t*)(ub + (uint32_t)(r0+8)*128 + swz8((uint32_t)(r0+8), gq) + 4*(l & 3)) = pkh(acc[nt][2], acc[nt][3]);
        }
        if (wc == 0 && (l & 3) == 0) {
            g_mj[((size_t)ci*64 + jj)*64 + r0]     = mn0;
            g_mj[((size_t)ci*64 + jj)*64 + r0 + 8] = mn1;
        }
    }

    // final stats into smem
    if (wc == 0 && (l & 3) == 0) {
        sM[r0] = m0;     sL[r0] = l0;
        sM[r0 + 8] = m1; sL[r0 + 8] = l1;
    }
    __syncthreads();

    // ---- phase 2: flash PV from u blobs + attn write ----
    uint32_t u_s = sb, v_s = sb + 16384;   // u db 2x8KB, V db 2x16KB
    int erow = tid >> 2;
    int c0 = (tid & 3) * 16;
    float mfin_e = sM[erow];
    float linv_e = 1.0f / sL[erow];
    int rr = 16*wr + (l >> 2);
    float linv0 = 1.0f / sL[rr], linv1 = 1.0f / sL[rr + 8];
    __syncthreads();

    // prologue: u(0) + V(0)
    {
        const unsigned char* su = g_U + (size_t)ci*64*8192;
        for (int i = tid; i < 512; i += 256) cp16(u_s + i*16, su + (size_t)i*16);
        const unsigned char* sv = g_Vt + (size_t)(b*32)*32768;
        for (int i = tid; i < 1024; i += 256) {
            int r = i >> 3, s8 = i & 7;
            cp16(v_s + r*128 + s8*16, sv + (size_t)r*256 + (size_t)s8*16);
        }
        CP_COMMIT();
    }

    float out[8][4];
    #pragma unroll
    for (int nt = 0; nt < 8; nt++)
        #pragma unroll
        for (int c = 0; c < 4; c++) out[nt][c] = 0.f;
    float mp0 = -1e30f, mp1 = -1e30f;

    for (int jj = 0; jj < 64; jj++) {
        __syncthreads();
        if (jj + 1 < 64) {
            const unsigned char* su = g_U + ((size_t)ci*64 + jj + 1)*8192;
            uint32_t ud = u_s + (uint32_t)(((jj+1) & 1) * 8192);
            for (int i = tid; i < 512; i += 256) cp16(ud + i*16, su + (size_t)i*16);
            int jt = (jj+1) >> 1, hf = (jj+1) & 1;
            uint32_t vd = v_s + (uint32_t)(((jj+1) & 1) * 16384);
            const unsigned char* sv = g_Vt + (size_t)(b*32 + jt)*32768 + (size_t)hf*128;
            for (int i = tid; i < 1024; i += 256) {
                int r = i >> 3, s8 = i & 7;
                cp16(vd + r*128 + s8*16, sv + (size_t)r*256 + (size_t)s8*16);
            }
            CP_COMMIT();
            CP_WAIT(1);
        } else {
            CP_WAIT(0);
        }
        __syncthreads();

        uint32_t ub = u_s + (uint32_t)((jj & 1) * 8192);
        uint32_t vb = v_s + (uint32_t)((jj & 1) * 16384);

        // accumulator rescale
        const float* mrow = g_mj + ((size_t)ci*64 + jj)*64;
        float mc0 = mrow[rr], mc1 = mrow[rr + 8];
        float rsc0 = __expf(mp0 - mc0), rsc1 = __expf(mp1 - mc1);
        mp0 = mc0; mp1 = mc1;
        #pragma unroll
        for (int nt = 0; nt < 8; nt++) {
            out[nt][0] *= rsc0; out[nt][1] *= rsc0;
            out[nt][2] *= rsc1; out[nt][3] *= rsc1;
        }

        // PV MMA
        #pragma unroll
        for (int kc = 0; kc < 4; kc++) {
            uint32_t afr[4], bfr[16];
            {
                uint32_t r = 16*wr + (l & 7) + 8*((l >> 3) & 1);
                uint32_t g = kc*2 + (l >> 4);
                ldm_x4(afr, ub + r*128 + swz8(r, g));
            }
            #pragma unroll
            for (int p = 0; p < 4; p++) {
                uint32_t n = 64*wc + 16*p + 8*((l >> 4) & 1) + (l & 7);
                uint32_t g = kc*2 + ((l >> 3) & 1);
                ldm_x4(bfr + 4*p, vb + n*128 + swz8(n, g));
            }
            #pragma unroll
            for (int nt = 0; nt < 8; nt++)
                mma16816(out[nt], afr, &bfr[2*nt]);
        }

        // attn write: p = u * exp(m_j - m_fin) / l
        {
            float corr = __expf(mrow[erow] - mfin_e) * linv_e;
            uint32_t g0 = (uint32_t)((tid & 3) * 2);
            uint32_t q0[4], q1[4];
            LDS16(q0, ub + (uint32_t)erow*128 + swz8((uint32_t)erow, g0));
            LDS16(q1, ub + (uint32_t)erow*128 + swz8((uint32_t)erow, g0 + 1));
            float* dst = attn + (rowbase + erow)*Sn + (size_t)jj*64 + c0;
            float p8[8];
            #pragma unroll
            for (int i2 = 0; i2 < 4; i2++) {
                float2 f = __half22float2(*(__half2*)&q0[i2]);
                p8[2*i2]   = f.x * corr;
                p8[2*i2+1] = f.y * corr;
            }
            *(float4*)(dst)     = *(float4*)(p8);
            *(float4*)(dst + 4) = *(float4*)(p8 + 4);
            #pragma unroll
            for (int i2 = 0; i2 < 4; i2++) {
                float2 f = __half22float2(*(__half2*)&q1[i2]);
                p8[2*i2]   = f.x * corr;
                p8[2*i2+1] = f.y * corr;
            }
            *(float4*)(dst + 8)  = *(float4*)(p8);
            *(float4*)(dst + 12) = *(float4*)(p8 + 4);
        }
    }

    // epilogue: out /= l
    #pragma unroll
    for (int nt = 0; nt < 8; nt++) {
        out[nt][0] *= linv0; out[nt][1] *= linv0;
        out[nt][2] *= linv1; out[nt][3] *= linv1;
    }
    #pragma unroll
    for (int nt = 0; nt < 8; nt++)
        #pragma unroll
        for (int dl = 0; dl < 2; dl++) {
            int row = 16*wr + (l >> 2) + 8*dl;
            float* o = d_out + (rowbase + row)*DKn + 64*wc + 8*nt + 2*(l & 3);
            *(float2*)(o) = make_float2(out[nt][2*dl], out[nt][2*dl+1]);
        }
}

// ---------------- launcher ----------------
extern "C" void kernel_launch(void* const* d_in, const int* in_sizes, int n_in,
                              void* d_out, int out_size) {
    const float* x  = (const float*)d_in[0];
    const float* tp = (const float*)d_in[1];
    const float* Wq = (const float*)d_in[2];
    const float* bq = (const float*)d_in[3];
    const float* Wk = (const float*)d_in[4];
    const float* bk = (const float*)d_in[5];
    const float* Wv = (const float*)d_in[6];
    const float* bv = (const float*)d_in[7];
    const float* Wt = (const float*)d_in[8];
    const float* bt = (const float*)d_in[9];
    float* out = (float*)d_out;

    cudaFuncSetAttribute((const void*)proj_tc,    cudaFuncAttributeMaxDynamicSharedMemorySize, PROJ_SMEM);
    cudaFuncSetAttribute((const void*)qt_tc,      cudaFuncAttributeMaxDynamicSharedMemorySize, QT_SMEM);
    cudaFuncSetAttribute((const void*)attn_fused, cudaFuncAttributeMaxDynamicSharedMemorySize, ATT_SMEM);

    prep_T_kernel<<<Bn, 256>>>(tp, Wt, bt);
    split_x_kernel<<<8192, 256>>>(x);
    split_W_kernel<<<dim3(16, 3), 256>>>(Wq, Wk, Wv);

    proj_tc<<<dim3(128, 3), 512, PROJ_SMEM>>>(bq, bk, bv);
    qt_tc<<<dim3(32, Bn), 256, QT_SMEM>>>();

    attn_fused<<<dim3(64, Bn), 256, ATT_SMEM>>>(out);
}